// round 8
// baseline (speedup 1.0000x reference)
#include <cuda_runtime.h>
#include <cuda_bf16.h>
#include <math.h>
#include <stdint.h>

#define NB 4
#define BATCH 2
#define HW 4096
#define F 64
#define LOG2E 1.4426950408889634f

// ---------------- scratch (device globals; no allocation allowed) ----------
__device__ float    g_fused[BATCH * HW * 256];
__device__ uint32_t g_q[BATCH * NB * HW * 8];
__device__ uint32_t g_k[BATCH * NB * HW * 8];
__device__ uint32_t g_vp[BATCH * NB * 32 * 4096];
__device__ float    g_pool[NB * BATCH * HW * 16];

// ---------------- helpers ---------------------------------------------------
__device__ __forceinline__ uint32_t f2tf32(float f) {
    uint32_t r; asm("cvt.rna.tf32.f32 %0, %1;" : "=r"(r) : "f"(f)); return r;
}
__device__ __forceinline__ uint32_t packbf(float hi, float lo) {
    uint32_t r; asm("cvt.rn.bf16x2.f32 %0, %1, %2;" : "=r"(r) : "f"(hi), "f"(lo)); return r;
}
__device__ __forceinline__ float ex2(float x) {
    float y; asm("ex2.approx.f32 %0, %1;" : "=f"(y) : "f"(x)); return y;
}
__device__ __forceinline__ void mma_tf32(float c[4], uint32_t a0, uint32_t a1,
                                         uint32_t a2, uint32_t a3,
                                         uint32_t b0, uint32_t b1) {
    asm volatile(
        "mma.sync.aligned.m16n8k8.row.col.f32.tf32.tf32.f32 "
        "{%0,%1,%2,%3},{%4,%5,%6,%7},{%8,%9},{%0,%1,%2,%3};"
        : "+f"(c[0]), "+f"(c[1]), "+f"(c[2]), "+f"(c[3])
        : "r"(a0), "r"(a1), "r"(a2), "r"(a3), "r"(b0), "r"(b1));
}
__device__ __forceinline__ void mma_bf16(float c[4], uint32_t a0, uint32_t a1,
                                         uint32_t a2, uint32_t a3,
                                         uint32_t b0, uint32_t b1) {
    asm volatile(
        "mma.sync.aligned.m16n8k16.row.col.f32.bf16.bf16.f32 "
        "{%0,%1,%2,%3},{%4,%5,%6,%7},{%8,%9},{%0,%1,%2,%3};"
        : "+f"(c[0]), "+f"(c[1]), "+f"(c[2]), "+f"(c[3])
        : "r"(a0), "r"(a1), "r"(a2), "r"(a3), "r"(b0), "r"(b1));
}
__device__ __forceinline__ void ldsm_x4(uint32_t& r0, uint32_t& r1,
                                        uint32_t& r2, uint32_t& r3, uint32_t addr) {
    asm volatile("ldmatrix.sync.aligned.m8n8.x4.shared.b16 {%0,%1,%2,%3}, [%4];"
        : "=r"(r0), "=r"(r1), "=r"(r2), "=r"(r3) : "r"(addr));
}
__device__ __forceinline__ void cpa16(uint32_t s, const void* g) {
    asm volatile("cp.async.cg.shared.global [%0], [%1], 16;" :: "r"(s), "l"(g));
}
__device__ __forceinline__ void cpa16z(uint32_t s, const void* g, int sz) {
    asm volatile("cp.async.cg.shared.global [%0], [%1], 16, %2;" :: "r"(s), "l"(g), "r"(sz));
}

// ---------------- K1: dilated conv, double-buffered cp.async + fused QKV ---
// dyn layout (uint32): A0 @0 (8704), A1 @8704, W0 @17408 (4608), W1 @22016,
//   Vt @26624 (4224), QW @30848 (544), KW @31392 (544),
//   scs @31936, shs @32000, vbs @32064, qkb @32128..32144
__global__ void __launch_bounds__(256) k_conv(
        const float* __restrict__ x, const float* __restrict__ wg,
        const float* __restrict__ cb, const float* __restrict__ bg,
        const float* __restrict__ bbe, const float* __restrict__ bm,
        const float* __restrict__ bv,
        const float* __restrict__ qw, const float* __restrict__ qb,
        const float* __restrict__ kw, const float* __restrict__ kb_,
        const float* __restrict__ vw, const float* __restrict__ vb) {
    extern __shared__ uint32_t dyn[];
    uint32_t* Vt = dyn + 26624;
    uint32_t* QW = dyn + 30848;
    uint32_t* KW = dyn + 31392;
    float* scs = (float*)(dyn + 31936);
    float* shs = (float*)(dyn + 32000);
    float* vbs = (float*)(dyn + 32064);
    float* qkb = (float*)(dyn + 32128);

    int tid = threadIdx.x;
    int bb = blockIdx.y, b = bb >> 2, br = bb & 3;
    int d = 1 << br;
    int pix0 = blockIdx.x * 128;
    int y0 = blockIdx.x * 2;

    if (tid < 64) {
        int idx = br * 64 + tid;
        float sc = bg[idx] * rsqrtf(bv[idx] + 1e-3f);
        scs[tid] = sc;
        shs[tid] = bbe[idx] - bm[idx] * sc + cb[idx] * sc;
    }

    int w = tid >> 5, lane = tid & 31;
    int g = lane >> 2, t = lane & 3;
    int m0 = w * 16;

    float c[8][4];
#pragma unroll
    for (int nb = 0; nb < 8; ++nb) c[nb][0] = c[nb][1] = c[nb][2] = c[nb][3] = 0.f;

    int p = tid >> 1, ch = (tid & 1) * 32;
    int prow = p >> 6, pcol = p & 63;
    int wrow = tid >> 2, wseg4 = (tid & 3) * 4;   // W copy: 4 chunks/thread

    uint32_t sh0 = (uint32_t)__cvta_generic_to_shared(dyn);
    uint32_t a_dst0 = sh0 + (uint32_t)((p * 68 + ch) * 4);
    const float* xb = x + (size_t)b * 64 * 64 * 64;
    const float* wbase = wg + (size_t)br * 9 * 4096;

    // prefetch macro-ish: tap -> buffer bi
#define PREFETCH(tap, bi) do {                                               \
        int ky_ = (tap) / 3, kx_ = (tap) - ky_ * 3;                          \
        int iy_ = y0 + prow + d * (ky_ - 1);                                 \
        int ix_ = pcol + d * (kx_ - 1);                                      \
        int val_ = (((unsigned)iy_ < 64u) & ((unsigned)ix_ < 64u)) ? 16 : 0; \
        int iyc_ = min(max(iy_, 0), 63), ixc_ = min(max(ix_, 0), 63);        \
        const float* asrc_ = xb + (((size_t)iyc_ * 64 + ixc_) * 64 + ch);    \
        uint32_t ad_ = a_dst0 + (uint32_t)(bi) * 34816u;                     \
        _Pragma("unroll")                                                    \
        for (int i_ = 0; i_ < 8; ++i_) cpa16z(ad_ + i_ * 16, asrc_ + i_ * 4, val_); \
        const float* wsrc_ = wbase + (size_t)(tap) * 4096 + wrow * 64 + wseg4 * 4; \
        uint32_t wd_ = sh0 + 69632u + (uint32_t)(bi) * 18432u                \
                     + (uint32_t)((wrow * 72 + wseg4 * 4) * 4);              \
        _Pragma("unroll")                                                    \
        for (int i_ = 0; i_ < 4; ++i_) cpa16(wd_ + i_ * 16, wsrc_ + i_ * 4); \
        asm volatile("cp.async.commit_group;");                              \
    } while (0)

    PREFETCH(0, 0);
    PREFETCH(1, 1);
    asm volatile("cp.async.wait_group 1;");
    __syncthreads();

#pragma unroll 1
    for (int tap = 0; tap < 9; ++tap) {
        const uint32_t* Ab = dyn + (tap & 1) * 8704;
        const uint32_t* Wb = dyn + 17408 + (tap & 1) * 4608;
        const uint32_t* Ar0 = Ab + (m0 + g) * 68 + t;
        const uint32_t* Ar1 = Ab + (m0 + g + 8) * 68 + t;
        const uint32_t* Wr = Wb + g;   // W[k][n] raw, stride 72
#pragma unroll
        for (int k0 = 0; k0 < 64; k0 += 8) {
            uint32_t a0 = Ar0[k0], a1 = Ar1[k0];
            uint32_t a2 = Ar0[k0 + 4], a3 = Ar1[k0 + 4];
            const uint32_t* wk0 = Wr + (k0 + t) * 72;
            const uint32_t* wk1 = Wr + (k0 + t + 4) * 72;
#pragma unroll
            for (int nb = 0; nb < 8; ++nb)
                mma_tf32(c[nb], a0, a1, a2, a3, wk0[nb * 8], wk1[nb * 8]);
        }
        __syncthreads();
        if (tap + 2 < 9) {
            PREFETCH(tap + 2, (tap & 1));
            asm volatile("cp.async.wait_group 1;");
            __syncthreads();
        } else if (tap + 1 < 9) {
            asm volatile("cp.async.wait_group 0;");
            __syncthreads();
        }
    }
#undef PREFETCH

    // ---- epilogue: BN + ReLU -> g_fused + registers ----
    float rv[8][4];
    float* f0 = g_fused + ((size_t)b * HW + pix0 + m0 + g) * 256 + br * 64;
    float* f1 = f0 + 8 * 256;
#pragma unroll
    for (int nb = 0; nb < 8; ++nb) {
        int col = nb * 8 + 2 * t;
        rv[nb][0] = fmaxf(c[nb][0] * scs[col] + shs[col], 0.f);
        rv[nb][1] = fmaxf(c[nb][1] * scs[col + 1] + shs[col + 1], 0.f);
        rv[nb][2] = fmaxf(c[nb][2] * scs[col] + shs[col], 0.f);
        rv[nb][3] = fmaxf(c[nb][3] * scs[col + 1] + shs[col + 1], 0.f);
        *(float2*)(f0 + col) = make_float2(rv[nb][0], rv[nb][1]);
        *(float2*)(f1 + col) = make_float2(rv[nb][2], rv[nb][3]);
    }
    __syncthreads();
    // ---- Bt (tf32 branch tile) into A0 region ----
    uint32_t* As = dyn;
#pragma unroll
    for (int nb = 0; nb < 8; ++nb) {
        int col = nb * 8 + 2 * t;
        *(uint2*)&As[(m0 + g) * 68 + col] =
            make_uint2(f2tf32(rv[nb][0]), f2tf32(rv[nb][1]));
        *(uint2*)&As[(m0 + g + 8) * 68 + col] =
            make_uint2(f2tf32(rv[nb][2]), f2tf32(rv[nb][3]));
    }
    // ---- stage Wv ([co][ci], stride 68) into W0 region; Wq/Wk ----
    uint32_t* Wv = dyn + 17408;
#pragma unroll
    for (int i = 0; i < 4; ++i) {
        int id = tid + i * 256;
        int ci = id >> 4, co4 = (id & 15) * 4;
        float4 v = *(const float4*)(vw + br * 4096 + ci * 64 + co4);
        Wv[(co4 + 0) * 68 + ci] = f2tf32(v.x);
        Wv[(co4 + 1) * 68 + ci] = f2tf32(v.y);
        Wv[(co4 + 2) * 68 + ci] = f2tf32(v.z);
        Wv[(co4 + 3) * 68 + ci] = f2tf32(v.w);
    }
    if (tid < 128) {
        int ci = tid >> 1, d4 = (tid & 1) * 4;
        float4 v = *(const float4*)(qw + br * 512 + ci * 8 + d4);
        QW[(d4 + 0) * 68 + ci] = f2tf32(v.x * LOG2E);
        QW[(d4 + 1) * 68 + ci] = f2tf32(v.y * LOG2E);
        QW[(d4 + 2) * 68 + ci] = f2tf32(v.z * LOG2E);
        QW[(d4 + 3) * 68 + ci] = f2tf32(v.w * LOG2E);
    } else {
        int id = tid - 128;
        int ci = id >> 1, d4 = (id & 1) * 4;
        float4 v = *(const float4*)(kw + br * 512 + ci * 8 + d4);
        KW[(d4 + 0) * 68 + ci] = f2tf32(v.x);
        KW[(d4 + 1) * 68 + ci] = f2tf32(v.y);
        KW[(d4 + 2) * 68 + ci] = f2tf32(v.z);
        KW[(d4 + 3) * 68 + ci] = f2tf32(v.w);
    }
    if (tid < 64) vbs[tid] = vb[br * 64 + tid];
    if (tid >= 64 && tid < 72) qkb[tid - 64] = qb[br * 8 + tid - 64] * LOG2E;
    if (tid >= 72 && tid < 80) qkb[8 + tid - 72] = kb_[br * 8 + tid - 72];
    __syncthreads();
    const uint32_t* Ar0 = As + (m0 + g) * 68 + t;
    const uint32_t* Ar1 = As + (m0 + g + 8) * 68 + t;
    const uint32_t* Wg_ = Wv + g * 68 + t;
    // ---- V = Bt * Wv^T ----
    float vac[8][4];
#pragma unroll
    for (int nb = 0; nb < 8; ++nb) vac[nb][0] = vac[nb][1] = vac[nb][2] = vac[nb][3] = 0.f;
#pragma unroll
    for (int k0 = 0; k0 < 64; k0 += 8) {
        uint32_t a0 = Ar0[k0], a1 = Ar1[k0];
        uint32_t a2 = Ar0[k0 + 4], a3 = Ar1[k0 + 4];
#pragma unroll
        for (int nb = 0; nb < 8; ++nb)
            mma_tf32(vac[nb], a0, a1, a2, a3, Wg_[nb * 8 * 68 + k0], Wg_[nb * 8 * 68 + k0 + 4]);
    }
    // ---- Q, K ----
    float qa_[4] = {0.f, 0.f, 0.f, 0.f}, ka_[4] = {0.f, 0.f, 0.f, 0.f};
    const uint32_t* Qg_ = QW + g * 68 + t;
    const uint32_t* Kg_ = KW + g * 68 + t;
#pragma unroll
    for (int k0 = 0; k0 < 64; k0 += 8) {
        uint32_t a0 = Ar0[k0], a1 = Ar1[k0];
        uint32_t a2 = Ar0[k0 + 4], a3 = Ar1[k0 + 4];
        mma_tf32(qa_, a0, a1, a2, a3, Qg_[k0], Qg_[k0 + 4]);
        mma_tf32(ka_, a0, a1, a2, a3, Kg_[k0], Kg_[k0 + 4]);
    }
    {
        float b0f = qkb[2 * t], b1f = qkb[2 * t + 1];
        uint32_t* qd = g_q + ((size_t)bb * HW + pix0 + m0 + g) * 8 + 2 * t;
        *(uint2*)qd = make_uint2(f2tf32(qa_[0] + b0f), f2tf32(qa_[1] + b1f));
        *(uint2*)(qd + 64) = make_uint2(f2tf32(qa_[2] + b0f), f2tf32(qa_[3] + b1f));
        float c0f = qkb[8 + 2 * t], c1f = qkb[8 + 2 * t + 1];
        uint32_t* kd = g_k + ((size_t)bb * HW + pix0 + m0 + g) * 8 + 2 * t;
        *(uint2*)kd = make_uint2(f2tf32(ka_[0] + c0f), f2tf32(ka_[1] + c1f));
        *(uint2*)(kd + 64) = make_uint2(f2tf32(ka_[2] + c0f), f2tf32(ka_[3] + c1f));
    }
    // ---- V pack into Vt[px][33] ----
#pragma unroll
    for (int nb = 0; nb < 8; ++nb) {
        int col = nb * 8 + 2 * t;
        Vt[(m0 + g) * 33 + nb * 4 + t] =
            packbf(vac[nb][1] + vbs[col + 1], vac[nb][0] + vbs[col]);
        Vt[(m0 + g + 8) * 33 + nb * 4 + t] =
            packbf(vac[nb][3] + vbs[col + 1], vac[nb][2] + vbs[col]);
    }
    __syncthreads();
    // ---- scatter Vt -> g_vp (tile-major ldmatrix order) ----
    uint32_t* vout = g_vp + ((size_t)bb * 32 + blockIdx.x) * 4096;
#pragma unroll
    for (int i = 0; i < 16; ++i) {
        int o = tid + i * 256;
        int col = o & 3, row = (o >> 2) & 7, mat = o >> 5;
        int kpt = ((mat >> 3) << 2) | col;
        int cch = ((mat & 7) << 3) | row;
        uint32_t lo = Vt[(2 * kpt) * 33 + (cch >> 1)];
        uint32_t hi = Vt[(2 * kpt + 1) * 33 + (cch >> 1)];
        vout[o] = (cch & 1) ? ((lo >> 16) | (hi & 0xFFFF0000u))
                            : ((lo & 0xFFFFu) | (hi << 16));
    }
}

// ---------------- K3: flash attention (no-max softmax), 2 CTA/SM -----------
__global__ void __launch_bounds__(256, 2) k_attn(const float* __restrict__ gamma) {
    __shared__ __align__(16) uint32_t Qs[1024];
    __shared__ __align__(16) uint32_t Ks[2][1024];
    __shared__ __align__(16) uint32_t Vs[2][4096];
    int tid = threadIdx.x;
    int br = blockIdx.y, b = blockIdx.z;
    int bb = b * NB + br;
    int n0 = blockIdx.x * 128;
    int w = tid >> 5, lane = tid & 31;
    int g = lane >> 2, t = lane & 3;

    const uint32_t* kgm = g_k + (size_t)bb * HW * 8;
    const uint32_t* vgm = g_vp + (size_t)bb * 32 * 4096;

    uint32_t ksa[2], vsa[2];
    ksa[0] = (uint32_t)__cvta_generic_to_shared(Ks[0]);
    ksa[1] = (uint32_t)__cvta_generic_to_shared(Ks[1]);
    vsa[0] = (uint32_t)__cvta_generic_to_shared(Vs[0]);
    vsa[1] = (uint32_t)__cvta_generic_to_shared(Vs[1]);

    cpa16(ksa[0] + tid * 16, kgm + tid * 4);
#pragma unroll
    for (int j = 0; j < 4; ++j)
        cpa16(vsa[0] + (tid + j * 256) * 16, vgm + (tid + j * 256) * 4);
    asm volatile("cp.async.commit_group;");
    ((uint4*)Qs)[tid] = ((const uint4*)(g_q + ((size_t)bb * HW + n0) * 8))[tid];
    cpa16(ksa[1] + tid * 16, kgm + 1024 + tid * 4);
#pragma unroll
    for (int j = 0; j < 4; ++j)
        cpa16(vsa[1] + (tid + j * 256) * 16, vgm + 4096 + (tid + j * 256) * 4);
    asm volatile("cp.async.commit_group;");
    asm volatile("cp.async.wait_group 1;");
    __syncthreads();

    int r0i = w * 16 + g;
    uint32_t qa0 = Qs[r0i * 8 + t];
    uint32_t qa1 = Qs[(r0i + 8) * 8 + t];
    uint32_t qa2 = Qs[r0i * 8 + t + 4];
    uint32_t qa3 = Qs[(r0i + 8) * 8 + t + 4];

    int midx = lane >> 3;
    int lane_const = (midx & 1) * 8 + (midx >> 1);
    uint32_t lboff = (uint32_t)((lane_const * 32 + (lane & 7) * 4) * 4);

    float o[8][4];
#pragma unroll
    for (int nb = 0; nb < 8; ++nb) { o[nb][0] = o[nb][1] = o[nb][2] = o[nb][3] = 0.f; }
    float Z0 = 0.f, Z1 = 0.f;

#pragma unroll 1
    for (int it = 0; it < 32; ++it) {
        int cur = it & 1;
        const uint32_t* Kc = Ks[cur];
        uint32_t lb = vsa[cur] + lboff;

        uint32_t pa[16][2];
#pragma unroll
        for (int half = 0; half < 2; ++half) {
            float s[8][4];
#pragma unroll
            for (int n2 = 0; n2 < 8; ++n2) {
                int nb = half * 8 + n2;
                uint32_t b0 = Kc[(nb * 8 + g) * 8 + t];
                uint32_t b1 = Kc[(nb * 8 + g) * 8 + t + 4];
                s[n2][0] = s[n2][1] = s[n2][2] = s[n2][3] = 0.f;
                mma_tf32(s[n2], qa0, qa1, qa2, qa3, b0, b1);
            }
#pragma unroll
            for (int n2 = 0; n2 < 8; ++n2) {
                int j = half * 8 + n2;
                float p0 = ex2(s[n2][0]), p1 = ex2(s[n2][1]);
                float p2 = ex2(s[n2][2]), p3 = ex2(s[n2][3]);
                Z0 += p0 + p1; Z1 += p2 + p3;
                pa[j][0] = packbf(p1, p0);
                pa[j][1] = packbf(p3, p2);
            }
        }
#pragma unroll
        for (int ks = 0; ks < 8; ++ks) {
#pragma unroll
            for (int nbp = 0; nbp < 4; ++nbp) {
                uint32_t b00, b10, b01, b11;
                ldsm_x4(b00, b10, b01, b11, lb + (uint32_t)((16 * ks + 2 * nbp) * 128));
                mma_bf16(o[2 * nbp], pa[2 * ks][0], pa[2 * ks][1],
                         pa[2 * ks + 1][0], pa[2 * ks + 1][1], b00, b10);
                mma_bf16(o[2 * nbp + 1], pa[2 * ks][0], pa[2 * ks][1],
                         pa[2 * ks + 1][0], pa[2 * ks + 1][1], b01, b11);
            }
        }
        __syncthreads();
        if (it + 2 < 32) {
            int t2 = it + 2;
            cpa16(ksa[cur] + tid * 16, kgm + (size_t)t2 * 1024 + tid * 4);
#pragma unroll
            for (int j = 0; j < 4; ++j)
                cpa16(vsa[cur] + (tid + j * 256) * 16,
                      vgm + (size_t)t2 * 4096 + (tid + j * 256) * 4);
            asm volatile("cp.async.commit_group;");
            asm volatile("cp.async.wait_group 1;");
            __syncthreads();
        } else if (it + 1 < 32) {
            asm volatile("cp.async.wait_group 0;");
            __syncthreads();
        }
    }
    Z0 += __shfl_xor_sync(0xffffffffu, Z0, 1);
    Z0 += __shfl_xor_sync(0xffffffffu, Z0, 2);
    Z1 += __shfl_xor_sync(0xffffffffu, Z1, 1);
    Z1 += __shfl_xor_sync(0xffffffffu, Z1, 2);
    float ga = gamma[br];
    float i0 = ga / Z0, i1 = ga / Z1;
    float* base0 = g_fused + ((size_t)b * HW + n0 + w * 16 + g) * 256 + br * 64 + 2 * t;
    float* base1 = base0 + 8 * 256;
#pragma unroll
    for (int nb = 0; nb < 8; ++nb) {
        float2 v0 = *(float2*)(base0 + nb * 8);
        v0.x += o[nb][0] * i0; v0.y += o[nb][1] * i0;
        *(float2*)(base0 + nb * 8) = v0;
        float2 v1 = *(float2*)(base1 + nb * 8);
        v1.x += o[nb][2] * i1; v1.y += o[nb][3] * i1;
        *(float2*)(base1 + nb * 8) = v1;
    }
}

// ---------------- K4: ps>=2 avg-pool(SAME) + 1x1 conv + BN ----------------
__global__ void k_pool(const float* __restrict__ pw, const float* __restrict__ pb,
                       const float* __restrict__ pg, const float* __restrict__ pbe,
                       const float* __restrict__ pm, const float* __restrict__ pv) {
    const int HP[4] = {64, 32, 22, 11};
    const int PS[4] = {1, 2, 3, 6};
    const int PLO[4] = {0, 0, 1, 1};
    int b = blockIdx.y;
    int lin = blockIdx.x;
    int j, r;
    if (lin < 1024)      { j = 1; r = lin; }
    else if (lin < 1508) { j = 2; r = lin - 1024; }
    else                 { j = 3; r = lin - 1508; }
    int hp = HP[j], ps = PS[j], plo = PLO[j];
    int oy = r / hp, ox = r % hp;
    __shared__ float avg[256];
    __shared__ float part[256];
    int tt = threadIdx.x;
    int ys = oy * ps - plo, xs = ox * ps - plo;
    int ye = min(ys + ps, 64), xe = min(xs + ps, 64);
    ys = max(ys, 0); xs = max(xs, 0);
    float s = 0.f;
    for (int yy = ys; yy < ye; ++yy)
        for (int xx = xs; xx < xe; ++xx)
            s += g_fused[((size_t)(b * HW) + yy * 64 + xx) * 256 + tt];
    avg[tt] = s * (1.f / (float)((ye - ys) * (xe - xs)));
    __syncthreads();
    int o = tt & 15, ck = tt >> 4;
    const float* wp = pw + j * 256 * 16 + o;
    float a = 0.f;
#pragma unroll
    for (int q = 0; q < 16; ++q) {
        int ci = ck * 16 + q;
        a += avg[ci] * wp[ci * 16];
    }
    part[ck * 16 + o] = a;
    __syncthreads();
    if (tt < 16) {
        float acc = pb[j * 16 + tt];
#pragma unroll
        for (int k2 = 0; k2 < 16; ++k2) acc += part[k2 * 16 + tt];
        int idx = j * 16 + tt;
        float sc = pg[idx] * rsqrtf(pv[idx] + 1e-3f);
        float sh = pbe[idx] - pm[idx] * sc;
        g_pool[((size_t)((j * 2 + b) * HW) + oy * hp + ox) * 16 + tt] = acc * sc + sh;
    }
}

// ---------------- K5: fused ps=1 conv + upsample + proj (8 tokens/CTA) -----
__global__ void __launch_bounds__(256) k_proj(
        const float* __restrict__ w, const float* __restrict__ pb,
        const float* __restrict__ g, const float* __restrict__ be,
        const float* __restrict__ m, const float* __restrict__ v,
        const float* __restrict__ pplw, const float* __restrict__ pplb,
        const float* __restrict__ ppg, const float* __restrict__ ppbe,
        const float* __restrict__ ppm, const float* __restrict__ ppv,
        float* __restrict__ out) {
    __shared__ float fv[8][324];
    __shared__ float ws[256 * 16];
    int tid = threadIdx.x;
    int tok0 = blockIdx.x * 8;
    int b2 = tok0 >> 12;
    int pos0 = tok0 & 4095;
    int yy = pos0 >> 6, xx0 = pos0 & 63;
#pragma unroll
    for (int i = 0; i < 2; ++i) {
        int fid = tid + i * 256;
        int px = fid >> 6, c4 = (fid & 63) * 4;
        *(float4*)&fv[px][c4] = *(const float4*)(g_fused + (size_t)(tok0 + px) * 256 + c4);
    }
#pragma unroll
    for (int i = 0; i < 4; ++i) {
        int fid = tid + i * 256;
        *(float4*)&ws[fid * 4] = *(const float4*)(pplw + fid * 4);
    }
    __syncthreads();
    if (tid < 128) {
        // ps=1 pyramid: 1x1 conv 256->16 + BN, channels 256..272
        int o = tid & 15, px = tid >> 4;
        float acc = pplb[o];
#pragma unroll 8
        for (int ci = 0; ci < 256; ci += 4) {
            float4 xv = *(const float4*)&fv[px][ci];
            acc += xv.x * ws[ci * 16 + o] + xv.y * ws[(ci + 1) * 16 + o]
                 + xv.z * ws[(ci + 2) * 16 + o] + xv.w * ws[(ci + 3) * 16 + o];
        }
        float sc = ppg[o] * rsqrtf(ppv[o] + 1e-3f);
        float sh = ppbe[o] - ppm[o] * sc;
        fv[px][256 + o] = acc * sc + sh;
    } else {
        // bilinear upsample of ps>=2 levels, channels 272..320
        const int HP[3] = {32, 22, 11};
        int id2 = tid - 128;
#pragma unroll
        for (int k = 0; k < 3; ++k) {
            int e = id2 + k * 128;
            int j = e >> 7;
            int rem = e & 127;
            int c = rem & 15, px = rem >> 4;
            int hp = HP[j];
            float scale = hp * (1.f / 64.f);
            float fy = (yy + 0.5f) * scale - 0.5f;
            float fx = (xx0 + px + 0.5f) * scale - 0.5f;
            float y0f = floorf(fy), x0f = floorf(fx);
            float ty = fy - y0f, tx = fx - x0f;
            int yA = min(max((int)y0f, 0), hp - 1);
            int yB = min(max((int)y0f + 1, 0), hp - 1);
            int xA = min(max((int)x0f, 0), hp - 1);
            int xB = min(max((int)x0f + 1, 0), hp - 1);
            const float* P = g_pool + (size_t)(((j + 1) * 2 + b2) * HW) * 16 + c;
            float v00 = P[(yA * hp + xA) * 16], v01 = P[(yA * hp + xB) * 16];
            float v10 = P[(yB * hp + xA) * 16], v11 = P[(yB * hp + xB) * 16];
            fv[px][272 + j * 16 + c] =
                (1.f - ty) * ((1.f - tx) * v00 + tx * v01)
                + ty * ((1.f - tx) * v10 + tx * v11);
        }
    }
    __syncthreads();
    int co = tid & 63, tg = tid >> 6;
    int r0 = tg * 2;
    float a0 = pb[co], a1 = a0;
    const float* wp = w + co;
#pragma unroll 8
    for (int ci = 0; ci < 320; ci += 4) {
        float w0 = wp[ci * 64], w1 = wp[(ci + 1) * 64];
        float w2 = wp[(ci + 2) * 64], w3 = wp[(ci + 3) * 64];
        float4 x0 = *(const float4*)&fv[r0][ci];
        float4 x1 = *(const float4*)&fv[r0 + 1][ci];
        a0 += x0.x * w0 + x0.y * w1 + x0.z * w2 + x0.w * w3;
        a1 += x1.x * w0 + x1.y * w1 + x1.z * w2 + x1.w * w3;
    }
    float sc = g[co] * rsqrtf(v[co] + 1e-3f);
    float sh = be[co] - m[co] * sc;
    float* op = out + (size_t)(tok0 + r0) * 64 + co;
    op[0]  = fmaxf(a0 * sc + sh, 0.f);
    op[64] = fmaxf(a1 * sc + sh, 0.f);
}

// ---------------- launch ---------------------------------------------------
extern "C" void kernel_launch(void* const* d_in, const int* in_sizes, int n_in,
                              void* d_out, int out_size) {
    const float* x       = (const float*)d_in[0];
    const float* conv_w  = (const float*)d_in[1];
    const float* conv_b  = (const float*)d_in[2];
    const float* bn_g    = (const float*)d_in[3];
    const float* bn_b    = (const float*)d_in[4];
    const float* bn_m    = (const float*)d_in[5];
    const float* bn_v    = (const float*)d_in[6];
    const float* q_w     = (const float*)d_in[7];
    const float* q_b     = (const float*)d_in[8];
    const float* k_w     = (const float*)d_in[9];
    const float* k_b     = (const float*)d_in[10];
    const float* v_w     = (const float*)d_in[11];
    const float* v_b     = (const float*)d_in[12];
    const float* attn_g  = (const float*)d_in[13];
    const float* ppl_w   = (const float*)d_in[14];
    const float* ppl_b   = (const float*)d_in[15];
    const float* ppl_bng = (const float*)d_in[16];
    const float* ppl_bnb = (const float*)d_in[17];
    const float* ppl_bnm = (const float*)d_in[18];
    const float* ppl_bnv = (const float*)d_in[19];
    const float* proj_w  = (const float*)d_in[20];
    const float* proj_b  = (const float*)d_in[21];
    const float* pbn_g   = (const float*)d_in[22];
    const float* pbn_b   = (const float*)d_in[23];
    const float* pbn_m   = (const float*)d_in[24];
    const float* pbn_v   = (const float*)d_in[25];
    float* out = (float*)d_out;

    const int CONV_SMEM = 32144 * 4;  // 128,576 B
    cudaFuncSetAttribute(k_conv, cudaFuncAttributeMaxDynamicSharedMemorySize, CONV_SMEM);

    k_conv<<<dim3(32, 8), 256, CONV_SMEM>>>(x, conv_w, conv_b, bn_g, bn_b, bn_m, bn_v,
                                            q_w, q_b, k_w, k_b, v_w, v_b);
    k_attn<<<dim3(32, 4, 2), 256>>>(attn_g);
    k_pool<<<dim3(1629, 2), 256>>>(ppl_w, ppl_b, ppl_bng, ppl_bnb, ppl_bnm, ppl_bnv);
    k_proj<<<1024, 256>>>(proj_w, proj_b, pbn_g, pbn_b, pbn_m, pbn_v,
                          ppl_w, ppl_b, ppl_bng, ppl_bnb, ppl_bnm, ppl_bnv, out);
}

// round 9
// speedup vs baseline: 1.0111x; 1.0111x over previous
#include <cuda_runtime.h>
#include <cuda_bf16.h>
#include <math.h>
#include <stdint.h>

#define NB 4
#define BATCH 2
#define HW 4096
#define F 64
#define LOG2E 1.4426950408889634f

// ---------------- scratch (device globals; no allocation allowed) ----------
__device__ float    g_fused[BATCH * HW * 256];
__device__ uint32_t g_q[BATCH * NB * HW * 8];
__device__ uint32_t g_k[BATCH * NB * HW * 8];
__device__ uint32_t g_vp[BATCH * NB * 32 * 4096];
__device__ float    g_pool[NB * BATCH * HW * 16];

// ---------------- helpers ---------------------------------------------------
__device__ __forceinline__ uint32_t f2tf32(float f) {
    uint32_t r; asm("cvt.rna.tf32.f32 %0, %1;" : "=r"(r) : "f"(f)); return r;
}
__device__ __forceinline__ uint32_t packbf(float hi, float lo) {
    uint32_t r; asm("cvt.rn.bf16x2.f32 %0, %1, %2;" : "=r"(r) : "f"(hi), "f"(lo)); return r;
}
__device__ __forceinline__ float ex2(float x) {
    float y; asm("ex2.approx.f32 %0, %1;" : "=f"(y) : "f"(x)); return y;
}
__device__ __forceinline__ void mma_tf32(float c[4], uint32_t a0, uint32_t a1,
                                         uint32_t a2, uint32_t a3,
                                         uint32_t b0, uint32_t b1) {
    asm volatile(
        "mma.sync.aligned.m16n8k8.row.col.f32.tf32.tf32.f32 "
        "{%0,%1,%2,%3},{%4,%5,%6,%7},{%8,%9},{%0,%1,%2,%3};"
        : "+f"(c[0]), "+f"(c[1]), "+f"(c[2]), "+f"(c[3])
        : "r"(a0), "r"(a1), "r"(a2), "r"(a3), "r"(b0), "r"(b1));
}
__device__ __forceinline__ void mma_bf16(float c[4], uint32_t a0, uint32_t a1,
                                         uint32_t a2, uint32_t a3,
                                         uint32_t b0, uint32_t b1) {
    asm volatile(
        "mma.sync.aligned.m16n8k16.row.col.f32.bf16.bf16.f32 "
        "{%0,%1,%2,%3},{%4,%5,%6,%7},{%8,%9},{%0,%1,%2,%3};"
        : "+f"(c[0]), "+f"(c[1]), "+f"(c[2]), "+f"(c[3])
        : "r"(a0), "r"(a1), "r"(a2), "r"(a3), "r"(b0), "r"(b1));
}
__device__ __forceinline__ void ldsm_x4(uint32_t& r0, uint32_t& r1,
                                        uint32_t& r2, uint32_t& r3, uint32_t addr) {
    asm volatile("ldmatrix.sync.aligned.m8n8.x4.shared.b16 {%0,%1,%2,%3}, [%4];"
        : "=r"(r0), "=r"(r1), "=r"(r2), "=r"(r3) : "r"(addr));
}
__device__ __forceinline__ void cpa16(uint32_t s, const void* g) {
    asm volatile("cp.async.cg.shared.global [%0], [%1], 16;" :: "r"(s), "l"(g));
}
__device__ __forceinline__ void cpa16z(uint32_t s, const void* g, int sz) {
    asm volatile("cp.async.cg.shared.global [%0], [%1], 16, %2;" :: "r"(s), "l"(g), "r"(sz));
}

// ---------------- K1: dilated conv, A double-buffered, W reg-pipelined -----
// dyn layout (uint32): A0 @0 (8704), A1 @8704, W0 @17408 (4352), W1 @21760,
//   Vt @26112 (4224), QW @30336 (544), KW @30880 (544),
//   scs @31424, shs @31488, vbs @31552, qkb @31616..31632
__global__ void __launch_bounds__(256) k_conv(
        const float* __restrict__ x, const float* __restrict__ wg,
        const float* __restrict__ cb, const float* __restrict__ bg,
        const float* __restrict__ bbe, const float* __restrict__ bm,
        const float* __restrict__ bv,
        const float* __restrict__ qw, const float* __restrict__ qb,
        const float* __restrict__ kw, const float* __restrict__ kb_,
        const float* __restrict__ vw, const float* __restrict__ vb) {
    extern __shared__ uint32_t dyn[];
    uint32_t* Vt = dyn + 26112;
    uint32_t* QW = dyn + 30336;
    uint32_t* KW = dyn + 30880;
    float* scs = (float*)(dyn + 31424);
    float* shs = (float*)(dyn + 31488);
    float* vbs = (float*)(dyn + 31552);
    float* qkb = (float*)(dyn + 31616);

    int tid = threadIdx.x;
    int bb = blockIdx.y, b = bb >> 2, br = bb & 3;
    int d = 1 << br;
    int pix0 = blockIdx.x * 128;
    int y0 = blockIdx.x * 2;

    if (tid < 64) {
        int idx = br * 64 + tid;
        float sc = bg[idx] * rsqrtf(bv[idx] + 1e-3f);
        scs[tid] = sc;
        shs[tid] = bbe[idx] - bm[idx] * sc + cb[idx] * sc;
    }

    int w = tid >> 5, lane = tid & 31;
    int g = lane >> 2, t = lane & 3;
    int m0 = w * 16;

    float c[8][4];
#pragma unroll
    for (int nb = 0; nb < 8; ++nb) c[nb][0] = c[nb][1] = c[nb][2] = c[nb][3] = 0.f;

    int p = tid >> 1, ch = (tid & 1) * 32;
    int prow = p >> 6, pcol = p & 63;
    int wci0 = tid >> 4, wco4 = (tid & 15) * 4;   // W staging coords

    uint32_t sh0 = (uint32_t)__cvta_generic_to_shared(dyn);
    uint32_t a_dst0 = sh0 + (uint32_t)((p * 68 + ch) * 4);
    const float* xb = x + (size_t)b * 64 * 64 * 64;
    const float* wbase = wg + (size_t)br * 9 * 4096;

#define PREFETCH_A(tap, bi) do {                                             \
        int ky_ = (tap) / 3, kx_ = (tap) - ky_ * 3;                          \
        int iy_ = y0 + prow + d * (ky_ - 1);                                 \
        int ix_ = pcol + d * (kx_ - 1);                                      \
        int val_ = (((unsigned)iy_ < 64u) & ((unsigned)ix_ < 64u)) ? 16 : 0; \
        int iyc_ = min(max(iy_, 0), 63), ixc_ = min(max(ix_, 0), 63);        \
        const float* asrc_ = xb + (((size_t)iyc_ * 64 + ixc_) * 64 + ch);    \
        uint32_t ad_ = a_dst0 + (uint32_t)(bi) * 34816u;                     \
        _Pragma("unroll")                                                    \
        for (int i_ = 0; i_ < 8; ++i_) cpa16z(ad_ + i_ * 16, asrc_ + i_ * 4, val_); \
        asm volatile("cp.async.commit_group;");                              \
    } while (0)

    PREFETCH_A(0, 0);
    PREFETCH_A(1, 1);
    // stage W tap 0 into W0 (LDG + cvt.rna + STS transposed)
    {
        uint32_t* W0 = dyn + 17408;
#pragma unroll
        for (int i = 0; i < 4; ++i) {
            int ci = wci0 + i * 16;
            float4 v = *(const float4*)(wbase + ci * 64 + wco4);
            W0[(wco4 + 0) * 68 + ci] = f2tf32(v.x);
            W0[(wco4 + 1) * 68 + ci] = f2tf32(v.y);
            W0[(wco4 + 2) * 68 + ci] = f2tf32(v.z);
            W0[(wco4 + 3) * 68 + ci] = f2tf32(v.w);
        }
    }
    asm volatile("cp.async.wait_group 1;");
    __syncthreads();

#pragma unroll 1
    for (int tap = 0; tap < 9; ++tap) {
        // W(tap+1) -> registers early (overlaps LDG latency with mma)
        float4 wr[4];
        if (tap + 1 < 9) {
            const float* wt1 = wbase + (size_t)(tap + 1) * 4096;
#pragma unroll
            for (int i = 0; i < 4; ++i)
                wr[i] = *(const float4*)(wt1 + (wci0 + i * 16) * 64 + wco4);
        }
        const uint32_t* Ab = dyn + (tap & 1) * 8704;
        const uint32_t* Wb = dyn + 17408 + (tap & 1) * 4352;
        const uint32_t* Ar0 = Ab + (m0 + g) * 68 + t;
        const uint32_t* Ar1 = Ab + (m0 + g + 8) * 68 + t;
        const uint32_t* Wg_ = Wb + g * 68 + t;
#pragma unroll
        for (int k0 = 0; k0 < 64; k0 += 8) {
            uint32_t a0 = Ar0[k0], a1 = Ar1[k0];
            uint32_t a2 = Ar0[k0 + 4], a3 = Ar1[k0 + 4];
#pragma unroll
            for (int nb = 0; nb < 8; ++nb)
                mma_tf32(c[nb], a0, a1, a2, a3,
                         Wg_[nb * 8 * 68 + k0], Wg_[nb * 8 * 68 + k0 + 4]);
        }
        // store W(tap+1) into the other W buffer
        if (tap + 1 < 9) {
            uint32_t* Wn = dyn + 17408 + ((tap + 1) & 1) * 4352;
#pragma unroll
            for (int i = 0; i < 4; ++i) {
                int ci = wci0 + i * 16;
                Wn[(wco4 + 0) * 68 + ci] = f2tf32(wr[i].x);
                Wn[(wco4 + 1) * 68 + ci] = f2tf32(wr[i].y);
                Wn[(wco4 + 2) * 68 + ci] = f2tf32(wr[i].z);
                Wn[(wco4 + 3) * 68 + ci] = f2tf32(wr[i].w);
            }
        }
        __syncthreads();
        if (tap + 2 < 9) {
            PREFETCH_A(tap + 2, (tap & 1));
            asm volatile("cp.async.wait_group 1;");
            __syncthreads();
        } else if (tap + 1 < 9) {
            asm volatile("cp.async.wait_group 0;");
            __syncthreads();
        }
    }
#undef PREFETCH_A

    // ---- epilogue: BN + ReLU -> g_fused + registers ----
    float rv[8][4];
    float* f0 = g_fused + ((size_t)b * HW + pix0 + m0 + g) * 256 + br * 64;
    float* f1 = f0 + 8 * 256;
#pragma unroll
    for (int nb = 0; nb < 8; ++nb) {
        int col = nb * 8 + 2 * t;
        rv[nb][0] = fmaxf(c[nb][0] * scs[col] + shs[col], 0.f);
        rv[nb][1] = fmaxf(c[nb][1] * scs[col + 1] + shs[col + 1], 0.f);
        rv[nb][2] = fmaxf(c[nb][2] * scs[col] + shs[col], 0.f);
        rv[nb][3] = fmaxf(c[nb][3] * scs[col + 1] + shs[col + 1], 0.f);
        *(float2*)(f0 + col) = make_float2(rv[nb][0], rv[nb][1]);
        *(float2*)(f1 + col) = make_float2(rv[nb][2], rv[nb][3]);
    }
    __syncthreads();
    // ---- Bt (tf32 branch tile) into A0 region ----
    uint32_t* As = dyn;
#pragma unroll
    for (int nb = 0; nb < 8; ++nb) {
        int col = nb * 8 + 2 * t;
        *(uint2*)&As[(m0 + g) * 68 + col] =
            make_uint2(f2tf32(rv[nb][0]), f2tf32(rv[nb][1]));
        *(uint2*)&As[(m0 + g + 8) * 68 + col] =
            make_uint2(f2tf32(rv[nb][2]), f2tf32(rv[nb][3]));
    }
    // ---- stage Wv into W0 region; Wq/Wk ----
    uint32_t* Wv = dyn + 17408;
#pragma unroll
    for (int i = 0; i < 4; ++i) {
        int ci = wci0 + i * 16;
        float4 v = *(const float4*)(vw + br * 4096 + ci * 64 + wco4);
        Wv[(wco4 + 0) * 68 + ci] = f2tf32(v.x);
        Wv[(wco4 + 1) * 68 + ci] = f2tf32(v.y);
        Wv[(wco4 + 2) * 68 + ci] = f2tf32(v.z);
        Wv[(wco4 + 3) * 68 + ci] = f2tf32(v.w);
    }
    if (tid < 128) {
        int ci = tid >> 1, d4 = (tid & 1) * 4;
        float4 v = *(const float4*)(qw + br * 512 + ci * 8 + d4);
        QW[(d4 + 0) * 68 + ci] = f2tf32(v.x * LOG2E);
        QW[(d4 + 1) * 68 + ci] = f2tf32(v.y * LOG2E);
        QW[(d4 + 2) * 68 + ci] = f2tf32(v.z * LOG2E);
        QW[(d4 + 3) * 68 + ci] = f2tf32(v.w * LOG2E);
    } else {
        int id = tid - 128;
        int ci = id >> 1, d4 = (id & 1) * 4;
        float4 v = *(const float4*)(kw + br * 512 + ci * 8 + d4);
        KW[(d4 + 0) * 68 + ci] = f2tf32(v.x);
        KW[(d4 + 1) * 68 + ci] = f2tf32(v.y);
        KW[(d4 + 2) * 68 + ci] = f2tf32(v.z);
        KW[(d4 + 3) * 68 + ci] = f2tf32(v.w);
    }
    if (tid < 64) vbs[tid] = vb[br * 64 + tid];
    if (tid >= 64 && tid < 72) qkb[tid - 64] = qb[br * 8 + tid - 64] * LOG2E;
    if (tid >= 72 && tid < 80) qkb[8 + tid - 72] = kb_[br * 8 + tid - 72];
    __syncthreads();
    const uint32_t* Ar0 = As + (m0 + g) * 68 + t;
    const uint32_t* Ar1 = As + (m0 + g + 8) * 68 + t;
    const uint32_t* Wg_ = Wv + g * 68 + t;
    // ---- V = Bt * Wv^T ----
    float vac[8][4];
#pragma unroll
    for (int nb = 0; nb < 8; ++nb) vac[nb][0] = vac[nb][1] = vac[nb][2] = vac[nb][3] = 0.f;
#pragma unroll
    for (int k0 = 0; k0 < 64; k0 += 8) {
        uint32_t a0 = Ar0[k0], a1 = Ar1[k0];
        uint32_t a2 = Ar0[k0 + 4], a3 = Ar1[k0 + 4];
#pragma unroll
        for (int nb = 0; nb < 8; ++nb)
            mma_tf32(vac[nb], a0, a1, a2, a3, Wg_[nb * 8 * 68 + k0], Wg_[nb * 8 * 68 + k0 + 4]);
    }
    // ---- Q, K ----
    float qa_[4] = {0.f, 0.f, 0.f, 0.f}, ka_[4] = {0.f, 0.f, 0.f, 0.f};
    const uint32_t* Qg_ = QW + g * 68 + t;
    const uint32_t* Kg_ = KW + g * 68 + t;
#pragma unroll
    for (int k0 = 0; k0 < 64; k0 += 8) {
        uint32_t a0 = Ar0[k0], a1 = Ar1[k0];
        uint32_t a2 = Ar0[k0 + 4], a3 = Ar1[k0 + 4];
        mma_tf32(qa_, a0, a1, a2, a3, Qg_[k0], Qg_[k0 + 4]);
        mma_tf32(ka_, a0, a1, a2, a3, Kg_[k0], Kg_[k0 + 4]);
    }
    {
        float b0f = qkb[2 * t], b1f = qkb[2 * t + 1];
        uint32_t* qd = g_q + ((size_t)bb * HW + pix0 + m0 + g) * 8 + 2 * t;
        *(uint2*)qd = make_uint2(f2tf32(qa_[0] + b0f), f2tf32(qa_[1] + b1f));
        *(uint2*)(qd + 64) = make_uint2(f2tf32(qa_[2] + b0f), f2tf32(qa_[3] + b1f));
        float c0f = qkb[8 + 2 * t], c1f = qkb[8 + 2 * t + 1];
        uint32_t* kd = g_k + ((size_t)bb * HW + pix0 + m0 + g) * 8 + 2 * t;
        *(uint2*)kd = make_uint2(f2tf32(ka_[0] + c0f), f2tf32(ka_[1] + c1f));
        *(uint2*)(kd + 64) = make_uint2(f2tf32(ka_[2] + c0f), f2tf32(ka_[3] + c1f));
    }
    // ---- V pack into Vt[px][33] ----
#pragma unroll
    for (int nb = 0; nb < 8; ++nb) {
        int col = nb * 8 + 2 * t;
        Vt[(m0 + g) * 33 + nb * 4 + t] =
            packbf(vac[nb][1] + vbs[col + 1], vac[nb][0] + vbs[col]);
        Vt[(m0 + g + 8) * 33 + nb * 4 + t] =
            packbf(vac[nb][3] + vbs[col + 1], vac[nb][2] + vbs[col]);
    }
    __syncthreads();
    // ---- scatter Vt -> g_vp (tile-major ldmatrix order) ----
    uint32_t* vout = g_vp + ((size_t)bb * 32 + blockIdx.x) * 4096;
#pragma unroll
    for (int i = 0; i < 16; ++i) {
        int o = tid + i * 256;
        int col = o & 3, row = (o >> 2) & 7, mat = o >> 5;
        int kpt = ((mat >> 3) << 2) | col;
        int cch = ((mat & 7) << 3) | row;
        uint32_t lo = Vt[(2 * kpt) * 33 + (cch >> 1)];
        uint32_t hi = Vt[(2 * kpt + 1) * 33 + (cch >> 1)];
        vout[o] = (cch & 1) ? ((lo >> 16) | (hi & 0xFFFF0000u))
                            : ((lo & 0xFFFFu) | (hi << 16));
    }
}

// ---------------- K3: flash attention (no-max softmax), 2 CTA/SM -----------
__global__ void __launch_bounds__(256, 2) k_attn(const float* __restrict__ gamma) {
    __shared__ __align__(16) uint32_t Qs[1024];
    __shared__ __align__(16) uint32_t Ks[2][1024];
    __shared__ __align__(16) uint32_t Vs[2][4096];
    int tid = threadIdx.x;
    int br = blockIdx.y, b = blockIdx.z;
    int bb = b * NB + br;
    int n0 = blockIdx.x * 128;
    int w = tid >> 5, lane = tid & 31;
    int g = lane >> 2, t = lane & 3;

    const uint32_t* kgm = g_k + (size_t)bb * HW * 8;
    const uint32_t* vgm = g_vp + (size_t)bb * 32 * 4096;

    uint32_t ksa[2], vsa[2];
    ksa[0] = (uint32_t)__cvta_generic_to_shared(Ks[0]);
    ksa[1] = (uint32_t)__cvta_generic_to_shared(Ks[1]);
    vsa[0] = (uint32_t)__cvta_generic_to_shared(Vs[0]);
    vsa[1] = (uint32_t)__cvta_generic_to_shared(Vs[1]);

    cpa16(ksa[0] + tid * 16, kgm + tid * 4);
#pragma unroll
    for (int j = 0; j < 4; ++j)
        cpa16(vsa[0] + (tid + j * 256) * 16, vgm + (tid + j * 256) * 4);
    asm volatile("cp.async.commit_group;");
    ((uint4*)Qs)[tid] = ((const uint4*)(g_q + ((size_t)bb * HW + n0) * 8))[tid];
    cpa16(ksa[1] + tid * 16, kgm + 1024 + tid * 4);
#pragma unroll
    for (int j = 0; j < 4; ++j)
        cpa16(vsa[1] + (tid + j * 256) * 16, vgm + 4096 + (tid + j * 256) * 4);
    asm volatile("cp.async.commit_group;");
    asm volatile("cp.async.wait_group 1;");
    __syncthreads();

    int r0i = w * 16 + g;
    uint32_t qa0 = Qs[r0i * 8 + t];
    uint32_t qa1 = Qs[(r0i + 8) * 8 + t];
    uint32_t qa2 = Qs[r0i * 8 + t + 4];
    uint32_t qa3 = Qs[(r0i + 8) * 8 + t + 4];

    int midx = lane >> 3;
    int lane_const = (midx & 1) * 8 + (midx >> 1);
    uint32_t lboff = (uint32_t)((lane_const * 32 + (lane & 7) * 4) * 4);

    float o[8][4];
#pragma unroll
    for (int nb = 0; nb < 8; ++nb) { o[nb][0] = o[nb][1] = o[nb][2] = o[nb][3] = 0.f; }
    float Z0 = 0.f, Z1 = 0.f;

#pragma unroll 1
    for (int it = 0; it < 32; ++it) {
        int cur = it & 1;
        const uint32_t* Kc = Ks[cur];
        uint32_t lb = vsa[cur] + lboff;

        uint32_t pa[16][2];
#pragma unroll
        for (int half = 0; half < 2; ++half) {
            float s[8][4];
#pragma unroll
            for (int n2 = 0; n2 < 8; ++n2) {
                int nb = half * 8 + n2;
                uint32_t b0 = Kc[(nb * 8 + g) * 8 + t];
                uint32_t b1 = Kc[(nb * 8 + g) * 8 + t + 4];
                s[n2][0] = s[n2][1] = s[n2][2] = s[n2][3] = 0.f;
                mma_tf32(s[n2], qa0, qa1, qa2, qa3, b0, b1);
            }
#pragma unroll
            for (int n2 = 0; n2 < 8; ++n2) {
                int j = half * 8 + n2;
                float p0 = ex2(s[n2][0]), p1 = ex2(s[n2][1]);
                float p2 = ex2(s[n2][2]), p3 = ex2(s[n2][3]);
                Z0 += p0 + p1; Z1 += p2 + p3;
                pa[j][0] = packbf(p1, p0);
                pa[j][1] = packbf(p3, p2);
            }
        }
#pragma unroll
        for (int ks = 0; ks < 8; ++ks) {
#pragma unroll
            for (int nbp = 0; nbp < 4; ++nbp) {
                uint32_t b00, b10, b01, b11;
                ldsm_x4(b00, b10, b01, b11, lb + (uint32_t)((16 * ks + 2 * nbp) * 128));
                mma_bf16(o[2 * nbp], pa[2 * ks][0], pa[2 * ks][1],
                         pa[2 * ks + 1][0], pa[2 * ks + 1][1], b00, b10);
                mma_bf16(o[2 * nbp + 1], pa[2 * ks][0], pa[2 * ks][1],
                         pa[2 * ks + 1][0], pa[2 * ks + 1][1], b01, b11);
            }
        }
        __syncthreads();
        if (it + 2 < 32) {
            int t2 = it + 2;
            cpa16(ksa[cur] + tid * 16, kgm + (size_t)t2 * 1024 + tid * 4);
#pragma unroll
            for (int j = 0; j < 4; ++j)
                cpa16(vsa[cur] + (tid + j * 256) * 16,
                      vgm + (size_t)t2 * 4096 + (tid + j * 256) * 4);
            asm volatile("cp.async.commit_group;");
            asm volatile("cp.async.wait_group 1;");
            __syncthreads();
        } else if (it + 1 < 32) {
            asm volatile("cp.async.wait_group 0;");
            __syncthreads();
        }
    }
    Z0 += __shfl_xor_sync(0xffffffffu, Z0, 1);
    Z0 += __shfl_xor_sync(0xffffffffu, Z0, 2);
    Z1 += __shfl_xor_sync(0xffffffffu, Z1, 1);
    Z1 += __shfl_xor_sync(0xffffffffu, Z1, 2);
    float ga = gamma[br];
    float i0 = ga / Z0, i1 = ga / Z1;
    float* base0 = g_fused + ((size_t)b * HW + n0 + w * 16 + g) * 256 + br * 64 + 2 * t;
    float* base1 = base0 + 8 * 256;
#pragma unroll
    for (int nb = 0; nb < 8; ++nb) {
        float2 v0 = *(float2*)(base0 + nb * 8);
        v0.x += o[nb][0] * i0; v0.y += o[nb][1] * i0;
        *(float2*)(base0 + nb * 8) = v0;
        float2 v1 = *(float2*)(base1 + nb * 8);
        v1.x += o[nb][2] * i1; v1.y += o[nb][3] * i1;
        *(float2*)(base1 + nb * 8) = v1;
    }
}

// ---------------- K4: ps>=2 avg-pool(SAME) + 1x1 conv + BN -----------------
template<int PS, int PLO>
__device__ __forceinline__ float pool_win(int b, int oy, int ox, int tt) {
    int ys0 = oy * PS - PLO, xs0 = ox * PS - PLO;
    float s = 0.f;
    int cnt = 0;
#pragma unroll
    for (int dy = 0; dy < PS; ++dy) {
        int yy = ys0 + dy;
        bool vy = (unsigned)yy < 64u;
        int yyc = min(max(yy, 0), 63);
#pragma unroll
        for (int dx = 0; dx < PS; ++dx) {
            int xx = xs0 + dx;
            bool v = vy && ((unsigned)xx < 64u);
            int xxc = min(max(xx, 0), 63);
            float val = g_fused[((size_t)(b * HW) + yyc * 64 + xxc) * 256 + tt];
            if (v) { s += val; ++cnt; }
        }
    }
    return s * (1.f / (float)cnt);
}

__global__ void k_pool(const float* __restrict__ pw, const float* __restrict__ pb,
                       const float* __restrict__ pg, const float* __restrict__ pbe,
                       const float* __restrict__ pm, const float* __restrict__ pv) {
    int b = blockIdx.y;
    int lin = blockIdx.x;
    int j, r;
    if (lin < 1024)      { j = 1; r = lin; }
    else if (lin < 1508) { j = 2; r = lin - 1024; }
    else                 { j = 3; r = lin - 1508; }
    const int HPs[4] = {64, 32, 22, 11};
    int hp = HPs[j];
    int oy = r / hp, ox = r % hp;
    __shared__ float avg[256];
    __shared__ float part[256];
    int tt = threadIdx.x;
    if (j == 1)      avg[tt] = pool_win<2, 0>(b, oy, ox, tt);
    else if (j == 2) avg[tt] = pool_win<3, 1>(b, oy, ox, tt);
    else             avg[tt] = pool_win<6, 1>(b, oy, ox, tt);
    __syncthreads();
    int o = tt & 15, ck = tt >> 4;
    const float* wp = pw + j * 256 * 16 + o;
    float a = 0.f;
#pragma unroll
    for (int q = 0; q < 16; ++q) {
        int ci = ck * 16 + q;
        a += avg[ci] * wp[ci * 16];
    }
    part[ck * 16 + o] = a;
    __syncthreads();
    if (tt < 16) {
        float acc = pb[j * 16 + tt];
#pragma unroll
        for (int k2 = 0; k2 < 16; ++k2) acc += part[k2 * 16 + tt];
        int idx = j * 16 + tt;
        float sc = pg[idx] * rsqrtf(pv[idx] + 1e-3f);
        float sh = pbe[idx] - pm[idx] * sc;
        g_pool[((size_t)((j * 2 + b) * HW) + oy * hp + ox) * 16 + tt] = acc * sc + sh;
    }
}

// ---------------- K5: fused ps=1 conv + upsample + proj (16 tokens/CTA) ----
__global__ void __launch_bounds__(256) k_proj(
        const float* __restrict__ w, const float* __restrict__ pb,
        const float* __restrict__ g, const float* __restrict__ be,
        const float* __restrict__ m, const float* __restrict__ v,
        const float* __restrict__ pplw, const float* __restrict__ pplb,
        const float* __restrict__ ppg, const float* __restrict__ ppbe,
        const float* __restrict__ ppm, const float* __restrict__ ppv,
        float* __restrict__ out) {
    __shared__ float fv[16][324];
    __shared__ float ws[256 * 16];
    int tid = threadIdx.x;
    int tok0 = blockIdx.x * 16;
    int b2 = tok0 >> 12;
    int pos0 = tok0 & 4095;
    int yy = pos0 >> 6, xx0 = pos0 & 63;
#pragma unroll
    for (int i = 0; i < 4; ++i) {
        int fid = tid + i * 256;
        int px = fid >> 6, c4 = (fid & 63) * 4;
        *(float4*)&fv[px][c4] = *(const float4*)(g_fused + (size_t)(tok0 + px) * 256 + c4);
        *(float4*)&ws[fid * 4] = *(const float4*)(pplw + fid * 4);
    }
    __syncthreads();
    {
        int o = tid & 15, px = tid >> 4;
        float acc = pplb[o];
#pragma unroll 8
        for (int ci = 0; ci < 256; ci += 4) {
            float4 xv = *(const float4*)&fv[px][ci];
            acc += xv.x * ws[ci * 16 + o] + xv.y * ws[(ci + 1) * 16 + o]
                 + xv.z * ws[(ci + 2) * 16 + o] + xv.w * ws[(ci + 3) * 16 + o];
        }
        float sc = ppg[o] * rsqrtf(ppv[o] + 1e-3f);
        float sh = ppbe[o] - ppm[o] * sc;
        fv[px][256 + o] = acc * sc + sh;
    }
    {
        const int HP[3] = {32, 22, 11};
#pragma unroll
        for (int k = 0; k < 3; ++k) {
            int id = tid + k * 256;
            int j = id >> 8;
            int rem = id & 255;
            int c = rem & 15, px = rem >> 4;
            int hp = HP[j];
            float scale = hp * (1.f / 64.f);
            float fy = (yy + 0.5f) * scale - 0.5f;
            float fx = (xx0 + px + 0.5f) * scale - 0.5f;
            float y0f = floorf(fy), x0f = floorf(fx);
            float ty = fy - y0f, tx = fx - x0f;
            int yA = min(max((int)y0f, 0), hp - 1);
            int yB = min(max((int)y0f + 1, 0), hp - 1);
            int xA = min(max((int)x0f, 0), hp - 1);
            int xB = min(max((int)x0f + 1, 0), hp - 1);
            const float* P = g_pool + (size_t)(((j + 1) * 2 + b2) * HW) * 16 + c;
            float v00 = P[(yA * hp + xA) * 16], v01 = P[(yA * hp + xB) * 16];
            float v10 = P[(yB * hp + xA) * 16], v11 = P[(yB * hp + xB) * 16];
            fv[px][272 + j * 16 + c] =
                (1.f - ty) * ((1.f - tx) * v00 + tx * v01)
                + ty * ((1.f - tx) * v10 + tx * v11);
        }
    }
    __syncthreads();
    int co = tid & 63, tg = tid >> 6;
    int r0 = tg * 4;
    float a0 = pb[co], a1 = a0, a2 = a0, a3 = a0;
    const float* wp = w + co;
#pragma unroll 8
    for (int ci = 0; ci < 320; ci += 4) {
        float w0 = wp[ci * 64], w1 = wp[(ci + 1) * 64];
        float w2 = wp[(ci + 2) * 64], w3 = wp[(ci + 3) * 64];
        float4 x0 = *(const float4*)&fv[r0][ci];
        float4 x1 = *(const float4*)&fv[r0 + 1][ci];
        float4 x2 = *(const float4*)&fv[r0 + 2][ci];
        float4 x3 = *(const float4*)&fv[r0 + 3][ci];
        a0 += x0.x * w0 + x0.y * w1 + x0.z * w2 + x0.w * w3;
        a1 += x1.x * w0 + x1.y * w1 + x1.z * w2 + x1.w * w3;
        a2 += x2.x * w0 + x2.y * w1 + x2.z * w2 + x2.w * w3;
        a3 += x3.x * w0 + x3.y * w1 + x3.z * w2 + x3.w * w3;
    }
    float sc = g[co] * rsqrtf(v[co] + 1e-3f);
    float sh = be[co] - m[co] * sc;
    float* op = out + (size_t)(tok0 + r0) * 64 + co;
    op[0]   = fmaxf(a0 * sc + sh, 0.f);
    op[64]  = fmaxf(a1 * sc + sh, 0.f);
    op[128] = fmaxf(a2 * sc + sh, 0.f);
    op[192] = fmaxf(a3 * sc + sh, 0.f);
}

// ---------------- launch ---------------------------------------------------
extern "C" void kernel_launch(void* const* d_in, const int* in_sizes, int n_in,
                              void* d_out, int out_size) {
    const float* x       = (const float*)d_in[0];
    const float* conv_w  = (const float*)d_in[1];
    const float* conv_b  = (const float*)d_in[2];
    const float* bn_g    = (const float*)d_in[3];
    const float* bn_b    = (const float*)d_in[4];
    const float* bn_m    = (const float*)d_in[5];
    const float* bn_v    = (const float*)d_in[6];
    const float* q_w     = (const float*)d_in[7];
    const float* q_b     = (const float*)d_in[8];
    const float* k_w     = (const float*)d_in[9];
    const float* k_b     = (const float*)d_in[10];
    const float* v_w     = (const float*)d_in[11];
    const float* v_b     = (const float*)d_in[12];
    const float* attn_g  = (const float*)d_in[13];
    const float* ppl_w   = (const float*)d_in[14];
    const float* ppl_b   = (const float*)d_in[15];
    const float* ppl_bng = (const float*)d_in[16];
    const float* ppl_bnb = (const float*)d_in[17];
    const float* ppl_bnm = (const float*)d_in[18];
    const float* ppl_bnv = (const float*)d_in[19];
    const float* proj_w  = (const float*)d_in[20];
    const float* proj_b  = (const float*)d_in[21];
    const float* pbn_g   = (const float*)d_in[22];
    const float* pbn_b   = (const float*)d_in[23];
    const float* pbn_m   = (const float*)d_in[24];
    const float* pbn_v   = (const float*)d_in[25];
    float* out = (float*)d_out;

    const int CONV_SMEM = 31632 * 4;  // 126,528 B
    cudaFuncSetAttribute(k_conv, cudaFuncAttributeMaxDynamicSharedMemorySize, CONV_SMEM);

    k_conv<<<dim3(32, 8), 256, CONV_SMEM>>>(x, conv_w, conv_b, bn_g, bn_b, bn_m, bn_v,
                                            q_w, q_b, k_w, k_b, v_w, v_b);
    k_attn<<<dim3(32, 4, 2), 256>>>(attn_g);
    k_pool<<<dim3(1629, 2), 256>>>(ppl_w, ppl_b, ppl_bng, ppl_bnb, ppl_bnm, ppl_bnv);
    k_proj<<<512, 256>>>(proj_w, proj_b, pbn_g, pbn_b, pbn_m, pbn_v,
                         ppl_w, ppl_b, ppl_bng, ppl_bnb, ppl_bnm, ppl_bnv, out);
}

// round 10
// speedup vs baseline: 1.0883x; 1.0764x over previous
#include <cuda_runtime.h>
#include <cuda_bf16.h>
#include <math.h>
#include <stdint.h>

#define NB 4
#define BATCH 2
#define HW 4096
#define F 64
#define LOG2E 1.4426950408889634f

// ---------------- scratch (device globals; no allocation allowed) ----------
__device__ float    g_fused[BATCH * HW * 256];
__device__ uint32_t g_q[BATCH * NB * HW * 8];
__device__ uint32_t g_k[BATCH * NB * HW * 8];
__device__ uint32_t g_vp[BATCH * NB * 32 * 4096];
__device__ float    g_pool[NB * BATCH * HW * 16];

// ---------------- helpers ---------------------------------------------------
__device__ __forceinline__ uint32_t f2tf32(float f) {
    uint32_t r; asm("cvt.rna.tf32.f32 %0, %1;" : "=r"(r) : "f"(f)); return r;
}
__device__ __forceinline__ uint32_t packbf(float hi, float lo) {
    uint32_t r; asm("cvt.rn.bf16x2.f32 %0, %1, %2;" : "=r"(r) : "f"(hi), "f"(lo)); return r;
}
__device__ __forceinline__ float ex2(float x) {
    float y; asm("ex2.approx.f32 %0, %1;" : "=f"(y) : "f"(x)); return y;
}
__device__ __forceinline__ void mma_tf32(float c[4], uint32_t a0, uint32_t a1,
                                         uint32_t a2, uint32_t a3,
                                         uint32_t b0, uint32_t b1) {
    asm volatile(
        "mma.sync.aligned.m16n8k8.row.col.f32.tf32.tf32.f32 "
        "{%0,%1,%2,%3},{%4,%5,%6,%7},{%8,%9},{%0,%1,%2,%3};"
        : "+f"(c[0]), "+f"(c[1]), "+f"(c[2]), "+f"(c[3])
        : "r"(a0), "r"(a1), "r"(a2), "r"(a3), "r"(b0), "r"(b1));
}
__device__ __forceinline__ void mma_bf16(float c[4], uint32_t a0, uint32_t a1,
                                         uint32_t a2, uint32_t a3,
                                         uint32_t b0, uint32_t b1) {
    asm volatile(
        "mma.sync.aligned.m16n8k16.row.col.f32.bf16.bf16.f32 "
        "{%0,%1,%2,%3},{%4,%5,%6,%7},{%8,%9},{%0,%1,%2,%3};"
        : "+f"(c[0]), "+f"(c[1]), "+f"(c[2]), "+f"(c[3])
        : "r"(a0), "r"(a1), "r"(a2), "r"(a3), "r"(b0), "r"(b1));
}
__device__ __forceinline__ void ldsm_x4(uint32_t& r0, uint32_t& r1,
                                        uint32_t& r2, uint32_t& r3, uint32_t addr) {
    asm volatile("ldmatrix.sync.aligned.m8n8.x4.shared.b16 {%0,%1,%2,%3}, [%4];"
        : "=r"(r0), "=r"(r1), "=r"(r2), "=r"(r3) : "r"(addr));
}
__device__ __forceinline__ void cpa16(uint32_t s, const void* g) {
    asm volatile("cp.async.cg.shared.global [%0], [%1], 16;" :: "r"(s), "l"(g));
}
__device__ __forceinline__ void cpa16z(uint32_t s, const void* g, int sz) {
    asm volatile("cp.async.cg.shared.global [%0], [%1], 16, %2;" :: "r"(s), "l"(g), "r"(sz));
}

// ---------------- K1: dilated conv, A double-buffered, W reg-pipelined -----
// (unchanged from measured 185us baseline)
__global__ void __launch_bounds__(256) k_conv(
        const float* __restrict__ x, const float* __restrict__ wg,
        const float* __restrict__ cb, const float* __restrict__ bg,
        const float* __restrict__ bbe, const float* __restrict__ bm,
        const float* __restrict__ bv,
        const float* __restrict__ qw, const float* __restrict__ qb,
        const float* __restrict__ kw, const float* __restrict__ kb_,
        const float* __restrict__ vw, const float* __restrict__ vb) {
    extern __shared__ uint32_t dyn[];
    uint32_t* Vt = dyn + 26112;
    uint32_t* QW = dyn + 30336;
    uint32_t* KW = dyn + 30880;
    float* scs = (float*)(dyn + 31424);
    float* shs = (float*)(dyn + 31488);
    float* vbs = (float*)(dyn + 31552);
    float* qkb = (float*)(dyn + 31616);

    int tid = threadIdx.x;
    int bb = blockIdx.y, b = bb >> 2, br = bb & 3;
    int d = 1 << br;
    int pix0 = blockIdx.x * 128;
    int y0 = blockIdx.x * 2;

    if (tid < 64) {
        int idx = br * 64 + tid;
        float sc = bg[idx] * rsqrtf(bv[idx] + 1e-3f);
        scs[tid] = sc;
        shs[tid] = bbe[idx] - bm[idx] * sc + cb[idx] * sc;
    }

    int w = tid >> 5, lane = tid & 31;
    int g = lane >> 2, t = lane & 3;
    int m0 = w * 16;

    float c[8][4];
#pragma unroll
    for (int nb = 0; nb < 8; ++nb) c[nb][0] = c[nb][1] = c[nb][2] = c[nb][3] = 0.f;

    int p = tid >> 1, ch = (tid & 1) * 32;
    int prow = p >> 6, pcol = p & 63;
    int wci0 = tid >> 4, wco4 = (tid & 15) * 4;

    uint32_t sh0 = (uint32_t)__cvta_generic_to_shared(dyn);
    uint32_t a_dst0 = sh0 + (uint32_t)((p * 68 + ch) * 4);
    const float* xb = x + (size_t)b * 64 * 64 * 64;
    const float* wbase = wg + (size_t)br * 9 * 4096;

#define PREFETCH_A(tap, bi) do {                                             \
        int ky_ = (tap) / 3, kx_ = (tap) - ky_ * 3;                          \
        int iy_ = y0 + prow + d * (ky_ - 1);                                 \
        int ix_ = pcol + d * (kx_ - 1);                                      \
        int val_ = (((unsigned)iy_ < 64u) & ((unsigned)ix_ < 64u)) ? 16 : 0; \
        int iyc_ = min(max(iy_, 0), 63), ixc_ = min(max(ix_, 0), 63);        \
        const float* asrc_ = xb + (((size_t)iyc_ * 64 + ixc_) * 64 + ch);    \
        uint32_t ad_ = a_dst0 + (uint32_t)(bi) * 34816u;                     \
        _Pragma("unroll")                                                    \
        for (int i_ = 0; i_ < 8; ++i_) cpa16z(ad_ + i_ * 16, asrc_ + i_ * 4, val_); \
        asm volatile("cp.async.commit_group;");                              \
    } while (0)

    PREFETCH_A(0, 0);
    PREFETCH_A(1, 1);
    {
        uint32_t* W0 = dyn + 17408;
#pragma unroll
        for (int i = 0; i < 4; ++i) {
            int ci = wci0 + i * 16;
            float4 v = *(const float4*)(wbase + ci * 64 + wco4);
            W0[(wco4 + 0) * 68 + ci] = f2tf32(v.x);
            W0[(wco4 + 1) * 68 + ci] = f2tf32(v.y);
            W0[(wco4 + 2) * 68 + ci] = f2tf32(v.z);
            W0[(wco4 + 3) * 68 + ci] = f2tf32(v.w);
        }
    }
    asm volatile("cp.async.wait_group 1;");
    __syncthreads();

#pragma unroll 1
    for (int tap = 0; tap < 9; ++tap) {
        float4 wr[4];
        if (tap + 1 < 9) {
            const float* wt1 = wbase + (size_t)(tap + 1) * 4096;
#pragma unroll
            for (int i = 0; i < 4; ++i)
                wr[i] = *(const float4*)(wt1 + (wci0 + i * 16) * 64 + wco4);
        }
        const uint32_t* Ab = dyn + (tap & 1) * 8704;
        const uint32_t* Wb = dyn + 17408 + (tap & 1) * 4352;
        const uint32_t* Ar0 = Ab + (m0 + g) * 68 + t;
        const uint32_t* Ar1 = Ab + (m0 + g + 8) * 68 + t;
        const uint32_t* Wg_ = Wb + g * 68 + t;
#pragma unroll
        for (int k0 = 0; k0 < 64; k0 += 8) {
            uint32_t a0 = Ar0[k0], a1 = Ar1[k0];
            uint32_t a2 = Ar0[k0 + 4], a3 = Ar1[k0 + 4];
#pragma unroll
            for (int nb = 0; nb < 8; ++nb)
                mma_tf32(c[nb], a0, a1, a2, a3,
                         Wg_[nb * 8 * 68 + k0], Wg_[nb * 8 * 68 + k0 + 4]);
        }
        if (tap + 1 < 9) {
            uint32_t* Wn = dyn + 17408 + ((tap + 1) & 1) * 4352;
#pragma unroll
            for (int i = 0; i < 4; ++i) {
                int ci = wci0 + i * 16;
                Wn[(wco4 + 0) * 68 + ci] = f2tf32(wr[i].x);
                Wn[(wco4 + 1) * 68 + ci] = f2tf32(wr[i].y);
                Wn[(wco4 + 2) * 68 + ci] = f2tf32(wr[i].z);
                Wn[(wco4 + 3) * 68 + ci] = f2tf32(wr[i].w);
            }
        }
        __syncthreads();
        if (tap + 2 < 9) {
            PREFETCH_A(tap + 2, (tap & 1));
            asm volatile("cp.async.wait_group 1;");
            __syncthreads();
        } else if (tap + 1 < 9) {
            asm volatile("cp.async.wait_group 0;");
            __syncthreads();
        }
    }
#undef PREFETCH_A

    float rv[8][4];
    float* f0 = g_fused + ((size_t)b * HW + pix0 + m0 + g) * 256 + br * 64;
    float* f1 = f0 + 8 * 256;
#pragma unroll
    for (int nb = 0; nb < 8; ++nb) {
        int col = nb * 8 + 2 * t;
        rv[nb][0] = fmaxf(c[nb][0] * scs[col] + shs[col], 0.f);
        rv[nb][1] = fmaxf(c[nb][1] * scs[col + 1] + shs[col + 1], 0.f);
        rv[nb][2] = fmaxf(c[nb][2] * scs[col] + shs[col], 0.f);
        rv[nb][3] = fmaxf(c[nb][3] * scs[col + 1] + shs[col + 1], 0.f);
        *(float2*)(f0 + col) = make_float2(rv[nb][0], rv[nb][1]);
        *(float2*)(f1 + col) = make_float2(rv[nb][2], rv[nb][3]);
    }
    __syncthreads();
    uint32_t* As = dyn;
#pragma unroll
    for (int nb = 0; nb < 8; ++nb) {
        int col = nb * 8 + 2 * t;
        *(uint2*)&As[(m0 + g) * 68 + col] =
            make_uint2(f2tf32(rv[nb][0]), f2tf32(rv[nb][1]));
        *(uint2*)&As[(m0 + g + 8) * 68 + col] =
            make_uint2(f2tf32(rv[nb][2]), f2tf32(rv[nb][3]));
    }
    uint32_t* Wv = dyn + 17408;
#pragma unroll
    for (int i = 0; i < 4; ++i) {
        int ci = wci0 + i * 16;
        float4 v = *(const float4*)(vw + br * 4096 + ci * 64 + wco4);
        Wv[(wco4 + 0) * 68 + ci] = f2tf32(v.x);
        Wv[(wco4 + 1) * 68 + ci] = f2tf32(v.y);
        Wv[(wco4 + 2) * 68 + ci] = f2tf32(v.z);
        Wv[(wco4 + 3) * 68 + ci] = f2tf32(v.w);
    }
    if (tid < 128) {
        int ci = tid >> 1, d4 = (tid & 1) * 4;
        float4 v = *(const float4*)(qw + br * 512 + ci * 8 + d4);
        QW[(d4 + 0) * 68 + ci] = f2tf32(v.x * LOG2E);
        QW[(d4 + 1) * 68 + ci] = f2tf32(v.y * LOG2E);
        QW[(d4 + 2) * 68 + ci] = f2tf32(v.z * LOG2E);
        QW[(d4 + 3) * 68 + ci] = f2tf32(v.w * LOG2E);
    } else {
        int id = tid - 128;
        int ci = id >> 1, d4 = (id & 1) * 4;
        float4 v = *(const float4*)(kw + br * 512 + ci * 8 + d4);
        KW[(d4 + 0) * 68 + ci] = f2tf32(v.x);
        KW[(d4 + 1) * 68 + ci] = f2tf32(v.y);
        KW[(d4 + 2) * 68 + ci] = f2tf32(v.z);
        KW[(d4 + 3) * 68 + ci] = f2tf32(v.w);
    }
    if (tid < 64) vbs[tid] = vb[br * 64 + tid];
    if (tid >= 64 && tid < 72) qkb[tid - 64] = qb[br * 8 + tid - 64] * LOG2E;
    if (tid >= 72 && tid < 80) qkb[8 + tid - 72] = kb_[br * 8 + tid - 72];
    __syncthreads();
    const uint32_t* Ar0 = As + (m0 + g) * 68 + t;
    const uint32_t* Ar1 = As + (m0 + g + 8) * 68 + t;
    const uint32_t* Wg_ = Wv + g * 68 + t;
    float vac[8][4];
#pragma unroll
    for (int nb = 0; nb < 8; ++nb) vac[nb][0] = vac[nb][1] = vac[nb][2] = vac[nb][3] = 0.f;
#pragma unroll
    for (int k0 = 0; k0 < 64; k0 += 8) {
        uint32_t a0 = Ar0[k0], a1 = Ar1[k0];
        uint32_t a2 = Ar0[k0 + 4], a3 = Ar1[k0 + 4];
#pragma unroll
        for (int nb = 0; nb < 8; ++nb)
            mma_tf32(vac[nb], a0, a1, a2, a3, Wg_[nb * 8 * 68 + k0], Wg_[nb * 8 * 68 + k0 + 4]);
    }
    float qa_[4] = {0.f, 0.f, 0.f, 0.f}, ka_[4] = {0.f, 0.f, 0.f, 0.f};
    const uint32_t* Qg_ = QW + g * 68 + t;
    const uint32_t* Kg_ = KW + g * 68 + t;
#pragma unroll
    for (int k0 = 0; k0 < 64; k0 += 8) {
        uint32_t a0 = Ar0[k0], a1 = Ar1[k0];
        uint32_t a2 = Ar0[k0 + 4], a3 = Ar1[k0 + 4];
        mma_tf32(qa_, a0, a1, a2, a3, Qg_[k0], Qg_[k0 + 4]);
        mma_tf32(ka_, a0, a1, a2, a3, Kg_[k0], Kg_[k0 + 4]);
    }
    {
        float b0f = qkb[2 * t], b1f = qkb[2 * t + 1];
        uint32_t* qd = g_q + ((size_t)bb * HW + pix0 + m0 + g) * 8 + 2 * t;
        *(uint2*)qd = make_uint2(f2tf32(qa_[0] + b0f), f2tf32(qa_[1] + b1f));
        *(uint2*)(qd + 64) = make_uint2(f2tf32(qa_[2] + b0f), f2tf32(qa_[3] + b1f));
        float c0f = qkb[8 + 2 * t], c1f = qkb[8 + 2 * t + 1];
        uint32_t* kd = g_k + ((size_t)bb * HW + pix0 + m0 + g) * 8 + 2 * t;
        *(uint2*)kd = make_uint2(f2tf32(ka_[0] + c0f), f2tf32(ka_[1] + c1f));
        *(uint2*)(kd + 64) = make_uint2(f2tf32(ka_[2] + c0f), f2tf32(ka_[3] + c1f));
    }
#pragma unroll
    for (int nb = 0; nb < 8; ++nb) {
        int col = nb * 8 + 2 * t;
        Vt[(m0 + g) * 33 + nb * 4 + t] =
            packbf(vac[nb][1] + vbs[col + 1], vac[nb][0] + vbs[col]);
        Vt[(m0 + g + 8) * 33 + nb * 4 + t] =
            packbf(vac[nb][3] + vbs[col + 1], vac[nb][2] + vbs[col]);
    }
    __syncthreads();
    uint32_t* vout = g_vp + ((size_t)bb * 32 + blockIdx.x) * 4096;
#pragma unroll
    for (int i = 0; i < 16; ++i) {
        int o = tid + i * 256;
        int col = o & 3, row = (o >> 2) & 7, mat = o >> 5;
        int kpt = ((mat >> 3) << 2) | col;
        int cch = ((mat & 7) << 3) | row;
        uint32_t lo = Vt[(2 * kpt) * 33 + (cch >> 1)];
        uint32_t hi = Vt[(2 * kpt + 1) * 33 + (cch >> 1)];
        vout[o] = (cch & 1) ? ((lo >> 16) | (hi & 0xFFFF0000u))
                            : ((lo & 0xFFFFu) | (hi << 16));
    }
}

// ---------------- K3: flash attention (unchanged) --------------------------
__global__ void __launch_bounds__(256, 2) k_attn(const float* __restrict__ gamma) {
    __shared__ __align__(16) uint32_t Qs[1024];
    __shared__ __align__(16) uint32_t Ks[2][1024];
    __shared__ __align__(16) uint32_t Vs[2][4096];
    int tid = threadIdx.x;
    int br = blockIdx.y, b = blockIdx.z;
    int bb = b * NB + br;
    int n0 = blockIdx.x * 128;
    int w = tid >> 5, lane = tid & 31;
    int g = lane >> 2, t = lane & 3;

    const uint32_t* kgm = g_k + (size_t)bb * HW * 8;
    const uint32_t* vgm = g_vp + (size_t)bb * 32 * 4096;

    uint32_t ksa[2], vsa[2];
    ksa[0] = (uint32_t)__cvta_generic_to_shared(Ks[0]);
    ksa[1] = (uint32_t)__cvta_generic_to_shared(Ks[1]);
    vsa[0] = (uint32_t)__cvta_generic_to_shared(Vs[0]);
    vsa[1] = (uint32_t)__cvta_generic_to_shared(Vs[1]);

    cpa16(ksa[0] + tid * 16, kgm + tid * 4);
#pragma unroll
    for (int j = 0; j < 4; ++j)
        cpa16(vsa[0] + (tid + j * 256) * 16, vgm + (tid + j * 256) * 4);
    asm volatile("cp.async.commit_group;");
    ((uint4*)Qs)[tid] = ((const uint4*)(g_q + ((size_t)bb * HW + n0) * 8))[tid];
    cpa16(ksa[1] + tid * 16, kgm + 1024 + tid * 4);
#pragma unroll
    for (int j = 0; j < 4; ++j)
        cpa16(vsa[1] + (tid + j * 256) * 16, vgm + 4096 + (tid + j * 256) * 4);
    asm volatile("cp.async.commit_group;");
    asm volatile("cp.async.wait_group 1;");
    __syncthreads();

    int r0i = w * 16 + g;
    uint32_t qa0 = Qs[r0i * 8 + t];
    uint32_t qa1 = Qs[(r0i + 8) * 8 + t];
    uint32_t qa2 = Qs[r0i * 8 + t + 4];
    uint32_t qa3 = Qs[(r0i + 8) * 8 + t + 4];

    int midx = lane >> 3;
    int lane_const = (midx & 1) * 8 + (midx >> 1);
    uint32_t lboff = (uint32_t)((lane_const * 32 + (lane & 7) * 4) * 4);

    float o[8][4];
#pragma unroll
    for (int nb = 0; nb < 8; ++nb) { o[nb][0] = o[nb][1] = o[nb][2] = o[nb][3] = 0.f; }
    float Z0 = 0.f, Z1 = 0.f;

#pragma unroll 1
    for (int it = 0; it < 32; ++it) {
        int cur = it & 1;
        const uint32_t* Kc = Ks[cur];
        uint32_t lb = vsa[cur] + lboff;

        uint32_t pa[16][2];
#pragma unroll
        for (int half = 0; half < 2; ++half) {
            float s[8][4];
#pragma unroll
            for (int n2 = 0; n2 < 8; ++n2) {
                int nb = half * 8 + n2;
                uint32_t b0 = Kc[(nb * 8 + g) * 8 + t];
                uint32_t b1 = Kc[(nb * 8 + g) * 8 + t + 4];
                s[n2][0] = s[n2][1] = s[n2][2] = s[n2][3] = 0.f;
                mma_tf32(s[n2], qa0, qa1, qa2, qa3, b0, b1);
            }
#pragma unroll
            for (int n2 = 0; n2 < 8; ++n2) {
                int j = half * 8 + n2;
                float p0 = ex2(s[n2][0]), p1 = ex2(s[n2][1]);
                float p2 = ex2(s[n2][2]), p3 = ex2(s[n2][3]);
                Z0 += p0 + p1; Z1 += p2 + p3;
                pa[j][0] = packbf(p1, p0);
                pa[j][1] = packbf(p3, p2);
            }
        }
#pragma unroll
        for (int ks = 0; ks < 8; ++ks) {
#pragma unroll
            for (int nbp = 0; nbp < 4; ++nbp) {
                uint32_t b00, b10, b01, b11;
                ldsm_x4(b00, b10, b01, b11, lb + (uint32_t)((16 * ks + 2 * nbp) * 128));
                mma_bf16(o[2 * nbp], pa[2 * ks][0], pa[2 * ks][1],
                         pa[2 * ks + 1][0], pa[2 * ks + 1][1], b00, b10);
                mma_bf16(o[2 * nbp + 1], pa[2 * ks][0], pa[2 * ks][1],
                         pa[2 * ks + 1][0], pa[2 * ks + 1][1], b01, b11);
            }
        }
        __syncthreads();
        if (it + 2 < 32) {
            int t2 = it + 2;
            cpa16(ksa[cur] + tid * 16, kgm + (size_t)t2 * 1024 + tid * 4);
#pragma unroll
            for (int j = 0; j < 4; ++j)
                cpa16(vsa[cur] + (tid + j * 256) * 16,
                      vgm + (size_t)t2 * 4096 + (tid + j * 256) * 4);
            asm volatile("cp.async.commit_group;");
            asm volatile("cp.async.wait_group 1;");
            __syncthreads();
        } else if (it + 1 < 32) {
            asm volatile("cp.async.wait_group 0;");
            __syncthreads();
        }
    }
    Z0 += __shfl_xor_sync(0xffffffffu, Z0, 1);
    Z0 += __shfl_xor_sync(0xffffffffu, Z0, 2);
    Z1 += __shfl_xor_sync(0xffffffffu, Z1, 1);
    Z1 += __shfl_xor_sync(0xffffffffu, Z1, 2);
    float ga = gamma[br];
    float i0 = ga / Z0, i1 = ga / Z1;
    float* base0 = g_fused + ((size_t)b * HW + n0 + w * 16 + g) * 256 + br * 64 + 2 * t;
    float* base1 = base0 + 8 * 256;
#pragma unroll
    for (int nb = 0; nb < 8; ++nb) {
        float2 v0 = *(float2*)(base0 + nb * 8);
        v0.x += o[nb][0] * i0; v0.y += o[nb][1] * i0;
        *(float2*)(base0 + nb * 8) = v0;
        float2 v1 = *(float2*)(base1 + nb * 8);
        v1.x += o[nb][2] * i1; v1.y += o[nb][3] * i1;
        *(float2*)(base1 + nb * 8) = v1;
    }
}

// ---------------- K4: ps>=2 avg-pool(SAME) + 1x1 conv + BN (unchanged) -----
template<int PS, int PLO>
__device__ __forceinline__ float pool_win(int b, int oy, int ox, int tt) {
    int ys0 = oy * PS - PLO, xs0 = ox * PS - PLO;
    float s = 0.f;
    int cnt = 0;
#pragma unroll
    for (int dy = 0; dy < PS; ++dy) {
        int yy = ys0 + dy;
        bool vy = (unsigned)yy < 64u;
        int yyc = min(max(yy, 0), 63);
#pragma unroll
        for (int dx = 0; dx < PS; ++dx) {
            int xx = xs0 + dx;
            bool v = vy && ((unsigned)xx < 64u);
            int xxc = min(max(xx, 0), 63);
            float val = g_fused[((size_t)(b * HW) + yyc * 64 + xxc) * 256 + tt];
            if (v) { s += val; ++cnt; }
        }
    }
    return s * (1.f / (float)cnt);
}

__global__ void k_pool(const float* __restrict__ pw, const float* __restrict__ pb,
                       const float* __restrict__ pg, const float* __restrict__ pbe,
                       const float* __restrict__ pm, const float* __restrict__ pv) {
    int b = blockIdx.y;
    int lin = blockIdx.x;
    int j, r;
    if (lin < 1024)      { j = 1; r = lin; }
    else if (lin < 1508) { j = 2; r = lin - 1024; }
    else                 { j = 3; r = lin - 1508; }
    const int HPs[4] = {64, 32, 22, 11};
    int hp = HPs[j];
    int oy = r / hp, ox = r % hp;
    __shared__ float avg[256];
    __shared__ float part[256];
    int tt = threadIdx.x;
    if (j == 1)      avg[tt] = pool_win<2, 0>(b, oy, ox, tt);
    else if (j == 2) avg[tt] = pool_win<3, 1>(b, oy, ox, tt);
    else             avg[tt] = pool_win<6, 1>(b, oy, ox, tt);
    __syncthreads();
    int o = tt & 15, ck = tt >> 4;
    const float* wp = pw + j * 256 * 16 + o;
    float a = 0.f;
#pragma unroll
    for (int q = 0; q < 16; ++q) {
        int ci = ck * 16 + q;
        a += avg[ci] * wp[ci * 16];
    }
    part[ck * 16 + o] = a;
    __syncthreads();
    if (tt < 16) {
        float acc = pb[j * 16 + tt];
#pragma unroll
        for (int k2 = 0; k2 < 16; ++k2) acc += part[k2 * 16 + tt];
        int idx = j * 16 + tt;
        float sc = pg[idx] * rsqrtf(pv[idx] + 1e-3f);
        float sh = pbe[idx] - pm[idx] * sc;
        g_pool[((size_t)((j * 2 + b) * HW) + oy * hp + ox) * 16 + tt] = acc * sc + sh;
    }
}

// ---------------- K5: proj as 2-stage tf32 mma GEMM ------------------------
// 128 tokens/CTA, grid 64. dyn layout (words):
//   A0 @0 (8704, reused as X2), A1 @8704, W1 @17408 (4x5440=21760: [80n][68]),
//   W2 @39168 (4352), scs2 @43520 (64), shs2 @43584 (64), psc @43648(16), psh @43664(16)
__global__ void __launch_bounds__(256) k_proj(
        const float* __restrict__ w, const float* __restrict__ pb,
        const float* __restrict__ g2, const float* __restrict__ be,
        const float* __restrict__ m, const float* __restrict__ v,
        const float* __restrict__ pplw, const float* __restrict__ pplb,
        const float* __restrict__ ppg, const float* __restrict__ ppbe,
        const float* __restrict__ ppm, const float* __restrict__ ppv,
        float* __restrict__ out) {
    extern __shared__ uint32_t dyn[];
    uint32_t* W1 = dyn + 17408;
    uint32_t* W2 = dyn + 39168;
    float* scs2 = (float*)(dyn + 43520);
    float* shs2 = (float*)(dyn + 43584);
    float* psc = (float*)(dyn + 43648);
    float* psh = (float*)(dyn + 43664);

    int tid = threadIdx.x;
    int tok0 = blockIdx.x * 128;
    int b2 = tok0 >> 12;
    int yy = (tok0 & 4095) >> 6;
    int wp_ = tid >> 5, lane = tid & 31;
    int g = lane >> 2, t = lane & 3;
    int m0 = wp_ * 16;

    int p = tid >> 1, ch32 = (tid & 1) * 32;
    uint32_t sh0 = (uint32_t)__cvta_generic_to_shared(dyn);
    uint32_t a_dst0 = sh0 + (uint32_t)((p * 68 + ch32) * 4);

#define PRE_F(ckk, bi) do {                                                   \
        const float* src_ = g_fused + ((size_t)(tok0 + p)) * 256 + (ckk) * 64 + ch32; \
        uint32_t ad_ = a_dst0 + (uint32_t)(bi) * 34816u;                      \
        _Pragma("unroll")                                                     \
        for (int i_ = 0; i_ < 8; ++i_) cpa16(ad_ + i_ * 16, src_ + i_ * 4);   \
        asm volatile("cp.async.commit_group;");                               \
    } while (0)

    PRE_F(0, 0);
    PRE_F(1, 1);
    // ---- stage W1 (proj rows 0..255 + pool0 W), W2, BN consts ----
#pragma unroll
    for (int i = 0; i < 16; ++i) {
        int id = tid + i * 256;
        int ci = id >> 4, co4 = (id & 15) * 4;
        int ck = ci >> 6, k = ci & 63;
        float4 vv = *(const float4*)(w + ci * 64 + co4);
        uint32_t* Wc = W1 + ck * 5440;
        Wc[(co4 + 0) * 68 + k] = f2tf32(vv.x);
        Wc[(co4 + 1) * 68 + k] = f2tf32(vv.y);
        Wc[(co4 + 2) * 68 + k] = f2tf32(vv.z);
        Wc[(co4 + 3) * 68 + k] = f2tf32(vv.w);
    }
#pragma unroll
    for (int i = 0; i < 4; ++i) {
        int id = tid + i * 256;
        int ci = id >> 2, o4 = (id & 3) * 4;
        int ck = ci >> 6, k = ci & 63;
        float4 vv = *(const float4*)(pplw + ci * 16 + o4);
        uint32_t* Wc = W1 + ck * 5440;
        Wc[(64 + o4 + 0) * 68 + k] = f2tf32(vv.x);
        Wc[(64 + o4 + 1) * 68 + k] = f2tf32(vv.y);
        Wc[(64 + o4 + 2) * 68 + k] = f2tf32(vv.z);
        Wc[(64 + o4 + 3) * 68 + k] = f2tf32(vv.w);
    }
#pragma unroll
    for (int i = 0; i < 4; ++i) {
        int id = tid + i * 256;
        int k = id >> 4, co4 = (id & 15) * 4;
        float4 vv = *(const float4*)(w + (256 + k) * 64 + co4);
        W2[(co4 + 0) * 68 + k] = f2tf32(vv.x);
        W2[(co4 + 1) * 68 + k] = f2tf32(vv.y);
        W2[(co4 + 2) * 68 + k] = f2tf32(vv.z);
        W2[(co4 + 3) * 68 + k] = f2tf32(vv.w);
    }
    if (tid < 64) {
        float sc = g2[tid] * rsqrtf(v[tid] + 1e-3f);
        scs2[tid] = sc;
        shs2[tid] = be[tid] - m[tid] * sc + pb[tid] * sc;
    } else if (tid < 80) {
        int o = tid - 64;
        float sc = ppg[o] * rsqrtf(ppv[o] + 1e-3f);
        psc[o] = sc;
        psh[o] = ppbe[o] - ppm[o] * sc + pplb[o] * sc;
    }
    asm volatile("cp.async.wait_group 1;");
    __syncthreads();

    // ---- GEMM1: [128,256] x [256,80] ----
    float a1c[10][4];
#pragma unroll
    for (int nb = 0; nb < 10; ++nb) a1c[nb][0] = a1c[nb][1] = a1c[nb][2] = a1c[nb][3] = 0.f;
#pragma unroll 1
    for (int ck = 0; ck < 4; ++ck) {
        const uint32_t* Ab = dyn + (ck & 1) * 8704;
        const uint32_t* Ar0 = Ab + (m0 + g) * 68 + t;
        const uint32_t* Ar1 = Ab + (m0 + g + 8) * 68 + t;
        const uint32_t* Wc = W1 + ck * 5440 + g * 68 + t;
#pragma unroll
        for (int k0 = 0; k0 < 64; k0 += 8) {
            uint32_t a0 = Ar0[k0], a1 = Ar1[k0];
            uint32_t a2 = Ar0[k0 + 4], a3 = Ar1[k0 + 4];
#pragma unroll
            for (int nb = 0; nb < 10; ++nb)
                mma_tf32(a1c[nb], a0, a1, a2, a3,
                         Wc[nb * 8 * 68 + k0], Wc[nb * 8 * 68 + k0 + 4]);
        }
        __syncthreads();
        if (ck + 2 < 4) {
            PRE_F(ck + 2, (ck & 1));
            asm volatile("cp.async.wait_group 1;");
            __syncthreads();
        } else if (ck + 1 < 4) {
            asm volatile("cp.async.wait_group 0;");
            __syncthreads();
        }
    }
#undef PRE_F

    // ---- X2 assembly (reuses A0 region): pool0 BN cols 0..15, upsample 16..63
    uint32_t* X2 = dyn;
#pragma unroll
    for (int nb = 8; nb < 10; ++nb) {
        int o = (nb - 8) * 8 + 2 * t;
        float s0 = psc[o], s1 = psc[o + 1], h0 = psh[o], h1 = psh[o + 1];
        *(uint2*)&X2[(m0 + g) * 68 + o] =
            make_uint2(f2tf32(a1c[nb][0] * s0 + h0), f2tf32(a1c[nb][1] * s1 + h1));
        *(uint2*)&X2[(m0 + g + 8) * 68 + o] =
            make_uint2(f2tf32(a1c[nb][2] * s0 + h0), f2tf32(a1c[nb][3] * s1 + h1));
    }
    {
        const int HP[3] = {32, 22, 11};
#pragma unroll
        for (int lvl = 0; lvl < 3; ++lvl) {
            int hp = HP[lvl];
            float scale = hp * (1.f / 64.f);
            const float* P0 = g_pool + (size_t)(((lvl + 1) * 2 + b2) * HW) * 16;
#pragma unroll
            for (int i = 0; i < 8; ++i) {
                int id = tid + i * 256;        // 0..2047
                int px = id >> 4, c = id & 15;
                int ty_ = yy + (px >> 6), tx_ = px & 63;
                float fy = (ty_ + 0.5f) * scale - 0.5f;
                float fx = (tx_ + 0.5f) * scale - 0.5f;
                float y0f = floorf(fy), x0f = floorf(fx);
                float ty = fy - y0f, tx = fx - x0f;
                int yA = min(max((int)y0f, 0), hp - 1);
                int yB = min(max((int)y0f + 1, 0), hp - 1);
                int xA = min(max((int)x0f, 0), hp - 1);
                int xB = min(max((int)x0f + 1, 0), hp - 1);
                const float* P = P0 + c;
                float v00 = P[(yA * hp + xA) * 16], v01 = P[(yA * hp + xB) * 16];
                float v10 = P[(yB * hp + xA) * 16], v11 = P[(yB * hp + xB) * 16];
                float val = (1.f - ty) * ((1.f - tx) * v00 + tx * v01)
                          + ty * ((1.f - tx) * v10 + tx * v11);
                X2[px * 68 + 16 + lvl * 16 + c] = f2tf32(val);
            }
        }
    }
    __syncthreads();

    // ---- GEMM2: X2[128,64] x W2[64,64], added to proj partials ----
    float a2c[8][4];
#pragma unroll
    for (int nb = 0; nb < 8; ++nb) a2c[nb][0] = a2c[nb][1] = a2c[nb][2] = a2c[nb][3] = 0.f;
    {
        const uint32_t* Ar0 = X2 + (m0 + g) * 68 + t;
        const uint32_t* Ar1 = X2 + (m0 + g + 8) * 68 + t;
        const uint32_t* Wc = W2 + g * 68 + t;
#pragma unroll
        for (int k0 = 0; k0 < 64; k0 += 8) {
            uint32_t a0 = Ar0[k0], a1 = Ar1[k0];
            uint32_t a2 = Ar0[k0 + 4], a3 = Ar1[k0 + 4];
#pragma unroll
            for (int nb = 0; nb < 8; ++nb)
                mma_tf32(a2c[nb], a0, a1, a2, a3,
                         Wc[nb * 8 * 68 + k0], Wc[nb * 8 * 68 + k0 + 4]);
        }
    }
    // ---- epilogue: BN + ReLU -> out ----
    float* o0 = out + (size_t)(tok0 + m0 + g) * 64;
    float* o1 = o0 + 8 * 64;
#pragma unroll
    for (int nb = 0; nb < 8; ++nb) {
        int col = nb * 8 + 2 * t;
        float s0 = scs2[col], s1 = scs2[col + 1];
        float h0 = shs2[col], h1 = shs2[col + 1];
        float2 r0, r1;
        r0.x = fmaxf((a1c[nb][0] + a2c[nb][0]) * s0 + h0, 0.f);
        r0.y = fmaxf((a1c[nb][1] + a2c[nb][1]) * s1 + h1, 0.f);
        r1.x = fmaxf((a1c[nb][2] + a2c[nb][2]) * s0 + h0, 0.f);
        r1.y = fmaxf((a1c[nb][3] + a2c[nb][3]) * s1 + h1, 0.f);
        *(float2*)(o0 + col) = r0;
        *(float2*)(o1 + col) = r1;
    }
}

// ---------------- launch ---------------------------------------------------
extern "C" void kernel_launch(void* const* d_in, const int* in_sizes, int n_in,
                              void* d_out, int out_size) {
    const float* x       = (const float*)d_in[0];
    const float* conv_w  = (const float*)d_in[1];
    const float* conv_b  = (const float*)d_in[2];
    const float* bn_g    = (const float*)d_in[3];
    const float* bn_b    = (const float*)d_in[4];
    const float* bn_m    = (const float*)d_in[5];
    const float* bn_v    = (const float*)d_in[6];
    const float* q_w     = (const float*)d_in[7];
    const float* q_b     = (const float*)d_in[8];
    const float* k_w     = (const float*)d_in[9];
    const float* k_b     = (const float*)d_in[10];
    const float* v_w     = (const float*)d_in[11];
    const float* v_b     = (const float*)d_in[12];
    const float* attn_g  = (const float*)d_in[13];
    const float* ppl_w   = (const float*)d_in[14];
    const float* ppl_b   = (const float*)d_in[15];
    const float* ppl_bng = (const float*)d_in[16];
    const float* ppl_bnb = (const float*)d_in[17];
    const float* ppl_bnm = (const float*)d_in[18];
    const float* ppl_bnv = (const float*)d_in[19];
    const float* proj_w  = (const float*)d_in[20];
    const float* proj_b  = (const float*)d_in[21];
    const float* pbn_g   = (const float*)d_in[22];
    const float* pbn_b   = (const float*)d_in[23];
    const float* pbn_m   = (const float*)d_in[24];
    const float* pbn_v   = (const float*)d_in[25];
    float* out = (float*)d_out;

    const int CONV_SMEM = 31632 * 4;  // 126,528 B
    const int PROJ_SMEM = 43680 * 4;  // 174,720 B
    cudaFuncSetAttribute(k_conv, cudaFuncAttributeMaxDynamicSharedMemorySize, CONV_SMEM);
    cudaFuncSetAttribute(k_proj, cudaFuncAttributeMaxDynamicSharedMemorySize, PROJ_SMEM);

    k_conv<<<dim3(32, 8), 256, CONV_SMEM>>>(x, conv_w, conv_b, bn_g, bn_b, bn_m, bn_v,
                                            q_w, q_b, k_w, k_b, v_w, v_b);
    k_attn<<<dim3(32, 4, 2), 256>>>(attn_g);
    k_pool<<<dim3(1629, 2), 256>>>(ppl_w, ppl_b, ppl_bng, ppl_bnb, ppl_bnm, ppl_bnv);
    k_proj<<<64, 256, PROJ_SMEM>>>(proj_w, proj_b, pbn_g, pbn_b, pbn_m, pbn_v,
                                   ppl_w, ppl_b, ppl_bng, ppl_bnb, ppl_bnm, ppl_bnv, out);
}

// round 11
// speedup vs baseline: 1.1140x; 1.0236x over previous
#include <cuda_runtime.h>
#include <cuda_bf16.h>
#include <math.h>
#include <stdint.h>

#define NB 4
#define BATCH 2
#define HW 4096
#define F 64
#define LOG2E 1.4426950408889634f

// ---------------- scratch (device globals; no allocation allowed) ----------
__device__ float    g_fused[BATCH * HW * 256];
__device__ uint32_t g_q[BATCH * NB * HW * 8];
__device__ uint32_t g_k[BATCH * NB * HW * 8];
__device__ uint32_t g_vp[BATCH * NB * 32 * 4096];
__device__ float    g_pool[NB * BATCH * HW * 16];

// ---------------- helpers ---------------------------------------------------
__device__ __forceinline__ uint32_t f2tf32(float f) {
    uint32_t r; asm("cvt.rna.tf32.f32 %0, %1;" : "=r"(r) : "f"(f)); return r;
}
__device__ __forceinline__ uint32_t packbf(float hi, float lo) {
    uint32_t r; asm("cvt.rn.bf16x2.f32 %0, %1, %2;" : "=r"(r) : "f"(hi), "f"(lo)); return r;
}
__device__ __forceinline__ float ex2(float x) {
    float y; asm("ex2.approx.f32 %0, %1;" : "=f"(y) : "f"(x)); return y;
}
__device__ __forceinline__ void mma_tf32(float c[4], uint32_t a0, uint32_t a1,
                                         uint32_t a2, uint32_t a3,
                                         uint32_t b0, uint32_t b1) {
    asm volatile(
        "mma.sync.aligned.m16n8k8.row.col.f32.tf32.tf32.f32 "
        "{%0,%1,%2,%3},{%4,%5,%6,%7},{%8,%9},{%0,%1,%2,%3};"
        : "+f"(c[0]), "+f"(c[1]), "+f"(c[2]), "+f"(c[3])
        : "r"(a0), "r"(a1), "r"(a2), "r"(a3), "r"(b0), "r"(b1));
}
__device__ __forceinline__ void mma_bf16(float c[4], uint32_t a0, uint32_t a1,
                                         uint32_t a2, uint32_t a3,
                                         uint32_t b0, uint32_t b1) {
    asm volatile(
        "mma.sync.aligned.m16n8k16.row.col.f32.bf16.bf16.f32 "
        "{%0,%1,%2,%3},{%4,%5,%6,%7},{%8,%9},{%0,%1,%2,%3};"
        : "+f"(c[0]), "+f"(c[1]), "+f"(c[2]), "+f"(c[3])
        : "r"(a0), "r"(a1), "r"(a2), "r"(a3), "r"(b0), "r"(b1));
}
__device__ __forceinline__ void ldsm_x4(uint32_t& r0, uint32_t& r1,
                                        uint32_t& r2, uint32_t& r3, uint32_t addr) {
    asm volatile("ldmatrix.sync.aligned.m8n8.x4.shared.b16 {%0,%1,%2,%3}, [%4];"
        : "=r"(r0), "=r"(r1), "=r"(r2), "=r"(r3) : "r"(addr));
}
__device__ __forceinline__ void cpa16(uint32_t s, const void* g) {
    asm volatile("cp.async.cg.shared.global [%0], [%1], 16;" :: "r"(s), "l"(g));
}
__device__ __forceinline__ void cpa16z(uint32_t s, const void* g, int sz) {
    asm volatile("cp.async.cg.shared.global [%0], [%1], 16, %2;" :: "r"(s), "l"(g), "r"(sz));
}

// ---------------- K1: dilated conv + fused QKV, compact smem (2 CTA/SM) ----
// dyn layout (uint32): A0 @0 (8704), A1 @8704 (8704),
//   post-mainloop reuse of A1: Vt @8704 (4224), QW @12928 (544), KW @13472 (544),
//   vbs @14016 (64), qkb @14080 (16)
//   W0 @17408 (4352), W1 @21760 (4352), scs @26112 (64), shs @26176 (64)
//   total 26240 words = 104,960 B
__global__ void __launch_bounds__(256, 2) k_conv(
        const float* __restrict__ x, const float* __restrict__ wg,
        const float* __restrict__ cb, const float* __restrict__ bg,
        const float* __restrict__ bbe, const float* __restrict__ bm,
        const float* __restrict__ bv,
        const float* __restrict__ qw, const float* __restrict__ qb,
        const float* __restrict__ kw, const float* __restrict__ kb_,
        const float* __restrict__ vw, const float* __restrict__ vb) {
    extern __shared__ uint32_t dyn[];
    uint32_t* Vt = dyn + 8704;
    uint32_t* QW = dyn + 12928;
    uint32_t* KW = dyn + 13472;
    float* vbs = (float*)(dyn + 14016);
    float* qkb = (float*)(dyn + 14080);
    float* scs = (float*)(dyn + 26112);
    float* shs = (float*)(dyn + 26176);

    int tid = threadIdx.x;
    int bb = blockIdx.y, b = bb >> 2, br = bb & 3;
    int d = 1 << br;
    int pix0 = blockIdx.x * 128;
    int y0 = blockIdx.x * 2;

    if (tid < 64) {
        int idx = br * 64 + tid;
        float sc = bg[idx] * rsqrtf(bv[idx] + 1e-3f);
        scs[tid] = sc;
        shs[tid] = bbe[idx] - bm[idx] * sc + cb[idx] * sc;
    }

    int w = tid >> 5, lane = tid & 31;
    int g = lane >> 2, t = lane & 3;
    int m0 = w * 16;

    float c[8][4];
#pragma unroll
    for (int nb = 0; nb < 8; ++nb) c[nb][0] = c[nb][1] = c[nb][2] = c[nb][3] = 0.f;

    int p = tid >> 1, ch = (tid & 1) * 32;
    int prow = p >> 6, pcol = p & 63;
    int wci0 = tid >> 4, wco4 = (tid & 15) * 4;

    uint32_t sh0 = (uint32_t)__cvta_generic_to_shared(dyn);
    uint32_t a_dst0 = sh0 + (uint32_t)((p * 68 + ch) * 4);
    const float* xb = x + (size_t)b * 64 * 64 * 64;
    const float* wbase = wg + (size_t)br * 9 * 4096;

#define PREFETCH_A(tap, bi) do {                                             \
        int ky_ = (tap) / 3, kx_ = (tap) - ky_ * 3;                          \
        int iy_ = y0 + prow + d * (ky_ - 1);                                 \
        int ix_ = pcol + d * (kx_ - 1);                                      \
        int val_ = (((unsigned)iy_ < 64u) & ((unsigned)ix_ < 64u)) ? 16 : 0; \
        int iyc_ = min(max(iy_, 0), 63), ixc_ = min(max(ix_, 0), 63);        \
        const float* asrc_ = xb + (((size_t)iyc_ * 64 + ixc_) * 64 + ch);    \
        uint32_t ad_ = a_dst0 + (uint32_t)(bi) * 34816u;                     \
        _Pragma("unroll")                                                    \
        for (int i_ = 0; i_ < 8; ++i_) cpa16z(ad_ + i_ * 16, asrc_ + i_ * 4, val_); \
        asm volatile("cp.async.commit_group;");                              \
    } while (0)

    PREFETCH_A(0, 0);
    PREFETCH_A(1, 1);
    {
        uint32_t* W0 = dyn + 17408;
#pragma unroll
        for (int i = 0; i < 4; ++i) {
            int ci = wci0 + i * 16;
            float4 v = *(const float4*)(wbase + ci * 64 + wco4);
            W0[(wco4 + 0) * 68 + ci] = f2tf32(v.x);
            W0[(wco4 + 1) * 68 + ci] = f2tf32(v.y);
            W0[(wco4 + 2) * 68 + ci] = f2tf32(v.z);
            W0[(wco4 + 3) * 68 + ci] = f2tf32(v.w);
        }
    }
    asm volatile("cp.async.wait_group 1;");
    __syncthreads();

#pragma unroll 1
    for (int tap = 0; tap < 9; ++tap) {
        float4 wr[4];
        if (tap + 1 < 9) {
            const float* wt1 = wbase + (size_t)(tap + 1) * 4096;
#pragma unroll
            for (int i = 0; i < 4; ++i)
                wr[i] = *(const float4*)(wt1 + (wci0 + i * 16) * 64 + wco4);
        }
        const uint32_t* Ab = dyn + (tap & 1) * 8704;
        const uint32_t* Wb = dyn + 17408 + (tap & 1) * 4352;
        const uint32_t* Ar0 = Ab + (m0 + g) * 68 + t;
        const uint32_t* Ar1 = Ab + (m0 + g + 8) * 68 + t;
        const uint32_t* Wg_ = Wb + g * 68 + t;
#pragma unroll
        for (int k0 = 0; k0 < 64; k0 += 8) {
            uint32_t a0 = Ar0[k0], a1 = Ar1[k0];
            uint32_t a2 = Ar0[k0 + 4], a3 = Ar1[k0 + 4];
#pragma unroll
            for (int nb = 0; nb < 8; ++nb)
                mma_tf32(c[nb], a0, a1, a2, a3,
                         Wg_[nb * 8 * 68 + k0], Wg_[nb * 8 * 68 + k0 + 4]);
        }
        if (tap + 1 < 9) {
            uint32_t* Wn = dyn + 17408 + ((tap + 1) & 1) * 4352;
#pragma unroll
            for (int i = 0; i < 4; ++i) {
                int ci = wci0 + i * 16;
                Wn[(wco4 + 0) * 68 + ci] = f2tf32(wr[i].x);
                Wn[(wco4 + 1) * 68 + ci] = f2tf32(wr[i].y);
                Wn[(wco4 + 2) * 68 + ci] = f2tf32(wr[i].z);
                Wn[(wco4 + 3) * 68 + ci] = f2tf32(wr[i].w);
            }
        }
        __syncthreads();
        if (tap + 2 < 9) {
            PREFETCH_A(tap + 2, (tap & 1));
            asm volatile("cp.async.wait_group 1;");
            __syncthreads();
        } else if (tap + 1 < 9) {
            asm volatile("cp.async.wait_group 0;");
            __syncthreads();
        }
    }
#undef PREFETCH_A

    float rv[8][4];
    float* f0 = g_fused + ((size_t)b * HW + pix0 + m0 + g) * 256 + br * 64;
    float* f1 = f0 + 8 * 256;
#pragma unroll
    for (int nb = 0; nb < 8; ++nb) {
        int col = nb * 8 + 2 * t;
        rv[nb][0] = fmaxf(c[nb][0] * scs[col] + shs[col], 0.f);
        rv[nb][1] = fmaxf(c[nb][1] * scs[col + 1] + shs[col + 1], 0.f);
        rv[nb][2] = fmaxf(c[nb][2] * scs[col] + shs[col], 0.f);
        rv[nb][3] = fmaxf(c[nb][3] * scs[col + 1] + shs[col + 1], 0.f);
        *(float2*)(f0 + col) = make_float2(rv[nb][0], rv[nb][1]);
        *(float2*)(f1 + col) = make_float2(rv[nb][2], rv[nb][3]);
    }
    __syncthreads();
    uint32_t* As = dyn;
#pragma unroll
    for (int nb = 0; nb < 8; ++nb) {
        int col = nb * 8 + 2 * t;
        *(uint2*)&As[(m0 + g) * 68 + col] =
            make_uint2(f2tf32(rv[nb][0]), f2tf32(rv[nb][1]));
        *(uint2*)&As[(m0 + g + 8) * 68 + col] =
            make_uint2(f2tf32(rv[nb][2]), f2tf32(rv[nb][3]));
    }
    uint32_t* Wv = dyn + 17408;
#pragma unroll
    for (int i = 0; i < 4; ++i) {
        int ci = wci0 + i * 16;
        float4 v = *(const float4*)(vw + br * 4096 + ci * 64 + wco4);
        Wv[(wco4 + 0) * 68 + ci] = f2tf32(v.x);
        Wv[(wco4 + 1) * 68 + ci] = f2tf32(v.y);
        Wv[(wco4 + 2) * 68 + ci] = f2tf32(v.z);
        Wv[(wco4 + 3) * 68 + ci] = f2tf32(v.w);
    }
    if (tid < 128) {
        int ci = tid >> 1, d4 = (tid & 1) * 4;
        float4 v = *(const float4*)(qw + br * 512 + ci * 8 + d4);
        QW[(d4 + 0) * 68 + ci] = f2tf32(v.x * LOG2E);
        QW[(d4 + 1) * 68 + ci] = f2tf32(v.y * LOG2E);
        QW[(d4 + 2) * 68 + ci] = f2tf32(v.z * LOG2E);
        QW[(d4 + 3) * 68 + ci] = f2tf32(v.w * LOG2E);
    } else {
        int id = tid - 128;
        int ci = id >> 1, d4 = (id & 1) * 4;
        float4 v = *(const float4*)(kw + br * 512 + ci * 8 + d4);
        KW[(d4 + 0) * 68 + ci] = f2tf32(v.x);
        KW[(d4 + 1) * 68 + ci] = f2tf32(v.y);
        KW[(d4 + 2) * 68 + ci] = f2tf32(v.z);
        KW[(d4 + 3) * 68 + ci] = f2tf32(v.w);
    }
    if (tid < 64) vbs[tid] = vb[br * 64 + tid];
    if (tid >= 64 && tid < 72) qkb[tid - 64] = qb[br * 8 + tid - 64] * LOG2E;
    if (tid >= 72 && tid < 80) qkb[8 + tid - 72] = kb_[br * 8 + tid - 72];
    __syncthreads();
    const uint32_t* Ar0 = As + (m0 + g) * 68 + t;
    const uint32_t* Ar1 = As + (m0 + g + 8) * 68 + t;
    const uint32_t* Wg_ = Wv + g * 68 + t;
    float vac[8][4];
#pragma unroll
    for (int nb = 0; nb < 8; ++nb) vac[nb][0] = vac[nb][1] = vac[nb][2] = vac[nb][3] = 0.f;
#pragma unroll
    for (int k0 = 0; k0 < 64; k0 += 8) {
        uint32_t a0 = Ar0[k0], a1 = Ar1[k0];
        uint32_t a2 = Ar0[k0 + 4], a3 = Ar1[k0 + 4];
#pragma unroll
        for (int nb = 0; nb < 8; ++nb)
            mma_tf32(vac[nb], a0, a1, a2, a3, Wg_[nb * 8 * 68 + k0], Wg_[nb * 8 * 68 + k0 + 4]);
    }
    float qa_[4] = {0.f, 0.f, 0.f, 0.f}, ka_[4] = {0.f, 0.f, 0.f, 0.f};
    const uint32_t* Qg_ = QW + g * 68 + t;
    const uint32_t* Kg_ = KW + g * 68 + t;
#pragma unroll
    for (int k0 = 0; k0 < 64; k0 += 8) {
        uint32_t a0 = Ar0[k0], a1 = Ar1[k0];
        uint32_t a2 = Ar0[k0 + 4], a3 = Ar1[k0 + 4];
        mma_tf32(qa_, a0, a1, a2, a3, Qg_[k0], Qg_[k0 + 4]);
        mma_tf32(ka_, a0, a1, a2, a3, Kg_[k0], Kg_[k0 + 4]);
    }
    {
        float b0f = qkb[2 * t], b1f = qkb[2 * t + 1];
        uint32_t* qd = g_q + ((size_t)bb * HW + pix0 + m0 + g) * 8 + 2 * t;
        *(uint2*)qd = make_uint2(f2tf32(qa_[0] + b0f), f2tf32(qa_[1] + b1f));
        *(uint2*)(qd + 64) = make_uint2(f2tf32(qa_[2] + b0f), f2tf32(qa_[3] + b1f));
        float c0f = qkb[8 + 2 * t], c1f = qkb[8 + 2 * t + 1];
        uint32_t* kd = g_k + ((size_t)bb * HW + pix0 + m0 + g) * 8 + 2 * t;
        *(uint2*)kd = make_uint2(f2tf32(ka_[0] + c0f), f2tf32(ka_[1] + c1f));
        *(uint2*)(kd + 64) = make_uint2(f2tf32(ka_[2] + c0f), f2tf32(ka_[3] + c1f));
    }
#pragma unroll
    for (int nb = 0; nb < 8; ++nb) {
        int col = nb * 8 + 2 * t;
        Vt[(m0 + g) * 33 + nb * 4 + t] =
            packbf(vac[nb][1] + vbs[col + 1], vac[nb][0] + vbs[col]);
        Vt[(m0 + g + 8) * 33 + nb * 4 + t] =
            packbf(vac[nb][3] + vbs[col + 1], vac[nb][2] + vbs[col]);
    }
    __syncthreads();
    uint32_t* vout = g_vp + ((size_t)bb * 32 + blockIdx.x) * 4096;
#pragma unroll
    for (int i = 0; i < 16; ++i) {
        int o = tid + i * 256;
        int col = o & 3, row = (o >> 2) & 7, mat = o >> 5;
        int kpt = ((mat >> 3) << 2) | col;
        int cch = ((mat & 7) << 3) | row;
        uint32_t lo = Vt[(2 * kpt) * 33 + (cch >> 1)];
        uint32_t hi = Vt[(2 * kpt + 1) * 33 + (cch >> 1)];
        vout[o] = (cch & 1) ? ((lo >> 16) | (hi & 0xFFFF0000u))
                            : ((lo & 0xFFFFu) | (hi << 16));
    }
}

// ---------------- K3: flash attention (unchanged) --------------------------
__global__ void __launch_bounds__(256, 2) k_attn(const float* __restrict__ gamma) {
    __shared__ __align__(16) uint32_t Qs[1024];
    __shared__ __align__(16) uint32_t Ks[2][1024];
    __shared__ __align__(16) uint32_t Vs[2][4096];
    int tid = threadIdx.x;
    int br = blockIdx.y, b = blockIdx.z;
    int bb = b * NB + br;
    int n0 = blockIdx.x * 128;
    int w = tid >> 5, lane = tid & 31;
    int g = lane >> 2, t = lane & 3;

    const uint32_t* kgm = g_k + (size_t)bb * HW * 8;
    const uint32_t* vgm = g_vp + (size_t)bb * 32 * 4096;

    uint32_t ksa[2], vsa[2];
    ksa[0] = (uint32_t)__cvta_generic_to_shared(Ks[0]);
    ksa[1] = (uint32_t)__cvta_generic_to_shared(Ks[1]);
    vsa[0] = (uint32_t)__cvta_generic_to_shared(Vs[0]);
    vsa[1] = (uint32_t)__cvta_generic_to_shared(Vs[1]);

    cpa16(ksa[0] + tid * 16, kgm + tid * 4);
#pragma unroll
    for (int j = 0; j < 4; ++j)
        cpa16(vsa[0] + (tid + j * 256) * 16, vgm + (tid + j * 256) * 4);
    asm volatile("cp.async.commit_group;");
    ((uint4*)Qs)[tid] = ((const uint4*)(g_q + ((size_t)bb * HW + n0) * 8))[tid];
    cpa16(ksa[1] + tid * 16, kgm + 1024 + tid * 4);
#pragma unroll
    for (int j = 0; j < 4; ++j)
        cpa16(vsa[1] + (tid + j * 256) * 16, vgm + 4096 + (tid + j * 256) * 4);
    asm volatile("cp.async.commit_group;");
    asm volatile("cp.async.wait_group 1;");
    __syncthreads();

    int r0i = w * 16 + g;
    uint32_t qa0 = Qs[r0i * 8 + t];
    uint32_t qa1 = Qs[(r0i + 8) * 8 + t];
    uint32_t qa2 = Qs[r0i * 8 + t + 4];
    uint32_t qa3 = Qs[(r0i + 8) * 8 + t + 4];

    int midx = lane >> 3;
    int lane_const = (midx & 1) * 8 + (midx >> 1);
    uint32_t lboff = (uint32_t)((lane_const * 32 + (lane & 7) * 4) * 4);

    float o[8][4];
#pragma unroll
    for (int nb = 0; nb < 8; ++nb) { o[nb][0] = o[nb][1] = o[nb][2] = o[nb][3] = 0.f; }
    float Z0 = 0.f, Z1 = 0.f;

#pragma unroll 1
    for (int it = 0; it < 32; ++it) {
        int cur = it & 1;
        const uint32_t* Kc = Ks[cur];
        uint32_t lb = vsa[cur] + lboff;

        uint32_t pa[16][2];
#pragma unroll
        for (int half = 0; half < 2; ++half) {
            float s[8][4];
#pragma unroll
            for (int n2 = 0; n2 < 8; ++n2) {
                int nb = half * 8 + n2;
                uint32_t b0 = Kc[(nb * 8 + g) * 8 + t];
                uint32_t b1 = Kc[(nb * 8 + g) * 8 + t + 4];
                s[n2][0] = s[n2][1] = s[n2][2] = s[n2][3] = 0.f;
                mma_tf32(s[n2], qa0, qa1, qa2, qa3, b0, b1);
            }
#pragma unroll
            for (int n2 = 0; n2 < 8; ++n2) {
                int j = half * 8 + n2;
                float p0 = ex2(s[n2][0]), p1 = ex2(s[n2][1]);
                float p2 = ex2(s[n2][2]), p3 = ex2(s[n2][3]);
                Z0 += p0 + p1; Z1 += p2 + p3;
                pa[j][0] = packbf(p1, p0);
                pa[j][1] = packbf(p3, p2);
            }
        }
#pragma unroll
        for (int ks = 0; ks < 8; ++ks) {
#pragma unroll
            for (int nbp = 0; nbp < 4; ++nbp) {
                uint32_t b00, b10, b01, b11;
                ldsm_x4(b00, b10, b01, b11, lb + (uint32_t)((16 * ks + 2 * nbp) * 128));
                mma_bf16(o[2 * nbp], pa[2 * ks][0], pa[2 * ks][1],
                         pa[2 * ks + 1][0], pa[2 * ks + 1][1], b00, b10);
                mma_bf16(o[2 * nbp + 1], pa[2 * ks][0], pa[2 * ks][1],
                         pa[2 * ks + 1][0], pa[2 * ks + 1][1], b01, b11);
            }
        }
        __syncthreads();
        if (it + 2 < 32) {
            int t2 = it + 2;
            cpa16(ksa[cur] + tid * 16, kgm + (size_t)t2 * 1024 + tid * 4);
#pragma unroll
            for (int j = 0; j < 4; ++j)
                cpa16(vsa[cur] + (tid + j * 256) * 16,
                      vgm + (size_t)t2 * 4096 + (tid + j * 256) * 4);
            asm volatile("cp.async.commit_group;");
            asm volatile("cp.async.wait_group 1;");
            __syncthreads();
        } else if (it + 1 < 32) {
            asm volatile("cp.async.wait_group 0;");
            __syncthreads();
        }
    }
    Z0 += __shfl_xor_sync(0xffffffffu, Z0, 1);
    Z0 += __shfl_xor_sync(0xffffffffu, Z0, 2);
    Z1 += __shfl_xor_sync(0xffffffffu, Z1, 1);
    Z1 += __shfl_xor_sync(0xffffffffu, Z1, 2);
    float ga = gamma[br];
    float i0 = ga / Z0, i1 = ga / Z1;
    float* base0 = g_fused + ((size_t)b * HW + n0 + w * 16 + g) * 256 + br * 64 + 2 * t;
    float* base1 = base0 + 8 * 256;
#pragma unroll
    for (int nb = 0; nb < 8; ++nb) {
        float2 v0 = *(float2*)(base0 + nb * 8);
        v0.x += o[nb][0] * i0; v0.y += o[nb][1] * i0;
        *(float2*)(base0 + nb * 8) = v0;
        float2 v1 = *(float2*)(base1 + nb * 8);
        v1.x += o[nb][2] * i1; v1.y += o[nb][3] * i1;
        *(float2*)(base1 + nb * 8) = v1;
    }
}

// ---------------- K4: ps>=2 avg-pool(SAME) + 1x1 conv + BN (unchanged) -----
template<int PS, int PLO>
__device__ __forceinline__ float pool_win(int b, int oy, int ox, int tt) {
    int ys0 = oy * PS - PLO, xs0 = ox * PS - PLO;
    float s = 0.f;
    int cnt = 0;
#pragma unroll
    for (int dy = 0; dy < PS; ++dy) {
        int yy = ys0 + dy;
        bool vy = (unsigned)yy < 64u;
        int yyc = min(max(yy, 0), 63);
#pragma unroll
        for (int dx = 0; dx < PS; ++dx) {
            int xx = xs0 + dx;
            bool v = vy && ((unsigned)xx < 64u);
            int xxc = min(max(xx, 0), 63);
            float val = g_fused[((size_t)(b * HW) + yyc * 64 + xxc) * 256 + tt];
            if (v) { s += val; ++cnt; }
        }
    }
    return s * (1.f / (float)cnt);
}

__global__ void k_pool(const float* __restrict__ pw, const float* __restrict__ pb,
                       const float* __restrict__ pg, const float* __restrict__ pbe,
                       const float* __restrict__ pm, const float* __restrict__ pv) {
    int b = blockIdx.y;
    int lin = blockIdx.x;
    int j, r;
    if (lin < 1024)      { j = 1; r = lin; }
    else if (lin < 1508) { j = 2; r = lin - 1024; }
    else                 { j = 3; r = lin - 1508; }
    const int HPs[4] = {64, 32, 22, 11};
    int hp = HPs[j];
    int oy = r / hp, ox = r % hp;
    __shared__ float avg[256];
    __shared__ float part[256];
    int tt = threadIdx.x;
    if (j == 1)      avg[tt] = pool_win<2, 0>(b, oy, ox, tt);
    else if (j == 2) avg[tt] = pool_win<3, 1>(b, oy, ox, tt);
    else             avg[tt] = pool_win<6, 1>(b, oy, ox, tt);
    __syncthreads();
    int o = tt & 15, ck = tt >> 4;
    const float* wp = pw + j * 256 * 16 + o;
    float a = 0.f;
#pragma unroll
    for (int q = 0; q < 16; ++q) {
        int ci = ck * 16 + q;
        a += avg[ci] * wp[ci * 16];
    }
    part[ck * 16 + o] = a;
    __syncthreads();
    if (tt < 16) {
        float acc = pb[j * 16 + tt];
#pragma unroll
        for (int k2 = 0; k2 < 16; ++k2) acc += part[k2 * 16 + tt];
        int idx = j * 16 + tt;
        float sc = pg[idx] * rsqrtf(pv[idx] + 1e-3f);
        float sh = pbe[idx] - pm[idx] * sc;
        g_pool[((size_t)((j * 2 + b) * HW) + oy * hp + ox) * 16 + tt] = acc * sc + sh;
    }
}

// ---------------- K5: proj GEMM, 64 tokens/CTA, grid 128, rna A staging ----
// warps: wm = w&3 (M band of 16), wn = w>>2 (N half of 40 cols).
// W1 column order: [proj 0..31 | pool0 0..7 | proj 32..63 | pool0 8..15]
// dyn (words): A0 @0 (4352, reused as X2), A1 @4352, W1 @8704 (4x5440),
//   W2 @30464 (4352), scs2 @34816, shs2 @34880, psc @34944, psh @34960..34976
__global__ void __launch_bounds__(256) k_proj(
        const float* __restrict__ w, const float* __restrict__ pb,
        const float* __restrict__ g2, const float* __restrict__ be,
        const float* __restrict__ m, const float* __restrict__ v,
        const float* __restrict__ pplw, const float* __restrict__ pplb,
        const float* __restrict__ ppg, const float* __restrict__ ppbe,
        const float* __restrict__ ppm, const float* __restrict__ ppv,
        float* __restrict__ out) {
    extern __shared__ uint32_t dyn[];
    uint32_t* W1 = dyn + 8704;
    uint32_t* W2 = dyn + 30464;
    float* scs2 = (float*)(dyn + 34816);
    float* shs2 = (float*)(dyn + 34880);
    float* psc = (float*)(dyn + 34944);
    float* psh = (float*)(dyn + 34960);

    int tid = threadIdx.x;
    int tok0 = blockIdx.x * 64;
    int b2 = tok0 >> 12;
    int yy = (tok0 & 4095) >> 6;
    int w_ = tid >> 5, lane = tid & 31;
    int wm = w_ & 3, wn = w_ >> 2;
    int g = lane >> 2, t = lane & 3;
    int m0 = wm * 16;

    int p4 = tid >> 2, cs = (tid & 3) * 16;
    const float* asrc = g_fused + (size_t)(tok0 + p4) * 256 + cs;
    float4 ar[4];

#define LOADA(ck) do {                                                      \
        const float* s_ = asrc + (ck) * 64;                                 \
        ar[0] = *(const float4*)(s_);      ar[1] = *(const float4*)(s_ + 4); \
        ar[2] = *(const float4*)(s_ + 8);  ar[3] = *(const float4*)(s_ + 12); \
    } while (0)
#define STOREA(bi) do {                                                     \
        uint32_t* d_ = dyn + (bi) * 4352 + p4 * 68 + cs;                    \
        _Pragma("unroll")                                                   \
        for (int i_ = 0; i_ < 4; ++i_) {                                    \
            *(uint2*)(d_ + i_ * 4) =                                        \
                make_uint2(f2tf32(ar[i_].x), f2tf32(ar[i_].y));             \
            *(uint2*)(d_ + i_ * 4 + 2) =                                    \
                make_uint2(f2tf32(ar[i_].z), f2tf32(ar[i_].w));             \
        }                                                                   \
    } while (0)

    LOADA(0); STOREA(0);
    // ---- stage W1 (proj remapped + pool0), W2, BN consts ----
#pragma unroll
    for (int i = 0; i < 16; ++i) {
        int id = tid + i * 256;
        int ci = id >> 4, co4 = (id & 15) * 4;
        int ck = ci >> 6, k = ci & 63;
        int sc4 = co4 + (co4 >= 32 ? 8 : 0);
        float4 vv = *(const float4*)(w + ci * 64 + co4);
        uint32_t* Wc = W1 + ck * 5440;
        Wc[(sc4 + 0) * 68 + k] = f2tf32(vv.x);
        Wc[(sc4 + 1) * 68 + k] = f2tf32(vv.y);
        Wc[(sc4 + 2) * 68 + k] = f2tf32(vv.z);
        Wc[(sc4 + 3) * 68 + k] = f2tf32(vv.w);
    }
#pragma unroll
    for (int i = 0; i < 4; ++i) {
        int id = tid + i * 256;
        int ci = id >> 2, o4 = (id & 3) * 4;
        int ck = ci >> 6, k = ci & 63;
        int sc4 = (o4 < 8) ? (32 + o4) : (64 + o4);   // o4 in {0,4,8,12} -> 32,36,72,76
        float4 vv = *(const float4*)(pplw + ci * 16 + o4);
        uint32_t* Wc = W1 + ck * 5440;
        Wc[(sc4 + 0) * 68 + k] = f2tf32(vv.x);
        Wc[(sc4 + 1) * 68 + k] = f2tf32(vv.y);
        Wc[(sc4 + 2) * 68 + k] = f2tf32(vv.z);
        Wc[(sc4 + 3) * 68 + k] = f2tf32(vv.w);
    }
#pragma unroll
    for (int i = 0; i < 4; ++i) {
        int id = tid + i * 256;
        int k = id >> 4, co4 = (id & 15) * 4;
        float4 vv = *(const float4*)(w + (256 + k) * 64 + co4);
        W2[(co4 + 0) * 68 + k] = f2tf32(vv.x);
        W2[(co4 + 1) * 68 + k] = f2tf32(vv.y);
        W2[(co4 + 2) * 68 + k] = f2tf32(vv.z);
        W2[(co4 + 3) * 68 + k] = f2tf32(vv.w);
    }
    if (tid < 64) {
        float sc = g2[tid] * rsqrtf(v[tid] + 1e-3f);
        scs2[tid] = sc;
        shs2[tid] = be[tid] - m[tid] * sc + pb[tid] * sc;
    } else if (tid < 80) {
        int o = tid - 64;
        float sc = ppg[o] * rsqrtf(ppv[o] + 1e-3f);
        psc[o] = sc;
        psh[o] = ppbe[o] - ppm[o] * sc + pplb[o] * sc;
    }
    LOADA(1);
    __syncthreads();

    // ---- GEMM1: [64,256] x [256,40] per N-half ----
    float a1c[5][4];
#pragma unroll
    for (int nb = 0; nb < 5; ++nb) a1c[nb][0] = a1c[nb][1] = a1c[nb][2] = a1c[nb][3] = 0.f;
    int wn40 = wn * 40;
#pragma unroll 1
    for (int ck = 0; ck < 4; ++ck) {
        const uint32_t* Ab = dyn + (ck & 1) * 4352;
        const uint32_t* Ar0 = Ab + (m0 + g) * 68 + t;
        const uint32_t* Ar1 = Ab + (m0 + g + 8) * 68 + t;
        const uint32_t* Wc = W1 + ck * 5440 + (wn40 + g) * 68 + t;
#pragma unroll
        for (int k0 = 0; k0 < 64; k0 += 8) {
            uint32_t a0 = Ar0[k0], a1 = Ar1[k0];
            uint32_t a2 = Ar0[k0 + 4], a3 = Ar1[k0 + 4];
#pragma unroll
            for (int nb = 0; nb < 5; ++nb)
                mma_tf32(a1c[nb], a0, a1, a2, a3,
                         Wc[nb * 544 + k0], Wc[nb * 544 + k0 + 4]);
        }
        if (ck + 1 < 4) STOREA((ck + 1) & 1);
        __syncthreads();
        if (ck + 2 < 4) LOADA(ck + 2);
    }
#undef LOADA
#undef STOREA

    // ---- X2 assembly in A0: pool0 cols 0..15 (from a1c[4]), upsample 16..63
    uint32_t* X2 = dyn;
    {
        int o = wn * 8 + 2 * t;
        float s0 = psc[o], s1 = psc[o + 1], h0 = psh[o], h1 = psh[o + 1];
        *(uint2*)&X2[(m0 + g) * 68 + o] =
            make_uint2(f2tf32(a1c[4][0] * s0 + h0), f2tf32(a1c[4][1] * s1 + h1));
        *(uint2*)&X2[(m0 + g + 8) * 68 + o] =
            make_uint2(f2tf32(a1c[4][2] * s0 + h0), f2tf32(a1c[4][3] * s1 + h1));
    }
    {
        const int HP[3] = {32, 22, 11};
#pragma unroll
        for (int lvl = 0; lvl < 3; ++lvl) {
            int hp = HP[lvl];
            float scale = hp * (1.f / 64.f);
            const float* P0 = g_pool + (size_t)(((lvl + 1) * 2 + b2) * HW) * 16;
            float fy = (yy + 0.5f) * scale - 0.5f;
            float y0f = floorf(fy);
            float ty = fy - y0f;
            int yA = min(max((int)y0f, 0), hp - 1);
            int yB = min(max((int)y0f + 1, 0), hp - 1);
#pragma unroll
            for (int i = 0; i < 4; ++i) {
                int id = tid + i * 256;        // 0..1023 = 64px x 16ch
                int px = id >> 4, c = id & 15;
                float fx = (px + 0.5f) * scale - 0.5f;
                float x0f = floorf(fx);
                float tx = fx - x0f;
                int xA = min(max((int)x0f, 0), hp - 1);
                int xB = min(max((int)x0f + 1, 0), hp - 1);
                const float* P = P0 + c;
                float v00 = P[(yA * hp + xA) * 16], v01 = P[(yA * hp + xB) * 16];
                float v10 = P[(yB * hp + xA) * 16], v11 = P[(yB * hp + xB) * 16];
                float val = (1.f - ty) * ((1.f - tx) * v00 + tx * v01)
                          + ty * ((1.f - tx) * v10 + tx * v11);
                X2[px * 68 + 16 + lvl * 16 + c] = f2tf32(val);
            }
        }
    }
    __syncthreads();

    // ---- GEMM2: X2[64,64] x W2 (N half = 32 cols) ----
    float a2c[4][4];
#pragma unroll
    for (int nb = 0; nb < 4; ++nb) a2c[nb][0] = a2c[nb][1] = a2c[nb][2] = a2c[nb][3] = 0.f;
    {
        const uint32_t* Ar0 = X2 + (m0 + g) * 68 + t;
        const uint32_t* Ar1 = X2 + (m0 + g + 8) * 68 + t;
        const uint32_t* Wc = W2 + (wn * 32 + g) * 68 + t;
#pragma unroll
        for (int k0 = 0; k0 < 64; k0 += 8) {
            uint32_t a0 = Ar0[k0], a1 = Ar1[k0];
            uint32_t a2 = Ar0[k0 + 4], a3 = Ar1[k0 + 4];
#pragma unroll
            for (int nb = 0; nb < 4; ++nb)
                mma_tf32(a2c[nb], a0, a1, a2, a3,
                         Wc[nb * 544 + k0], Wc[nb * 544 + k0 + 4]);
        }
    }
    // ---- epilogue: BN + ReLU -> out ----
    float* o0 = out + (size_t)(tok0 + m0 + g) * 64;
    float* o1 = o0 + 8 * 64;
#pragma unroll
    for (int nb = 0; nb < 4; ++nb) {
        int col = wn * 32 + nb * 8 + 2 * t;
        float s0 = scs2[col], s1 = scs2[col + 1];
        float h0 = shs2[col], h1 = shs2[col + 1];
        float2 r0, r1;
        r0.x = fmaxf((a1c[nb][0] + a2c[nb][0]) * s0 + h0, 0.f);
        r0.y = fmaxf((a1c[nb][1] + a2c[nb][1]) * s1 + h1, 0.f);
        r1.x = fmaxf((a1c[nb][2] + a2c[nb][2]) * s0 + h0, 0.f);
        r1.y = fmaxf((a1c[nb][3] + a2c[nb][3]) * s1 + h1, 0.f);
        *(float2*)(o0 + col) = r0;
        *(float2*)(o1 + col) = r1;
    }
}

// ---------------- launch ---------------------------------------------------
extern "C" void kernel_launch(void* const* d_in, const int* in_sizes, int n_in,
                              void* d_out, int out_size) {
    const float* x       = (const float*)d_in[0];
    const float* conv_w  = (const float*)d_in[1];
    const float* conv_b  = (const float*)d_in[2];
    const float* bn_g    = (const float*)d_in[3];
    const float* bn_b    = (const float*)d_in[4];
    const float* bn_m    = (const float*)d_in[5];
    const float* bn_v    = (const float*)d_in[6];
    const float* q_w     = (const float*)d_in[7];
    const float* q_b     = (const float*)d_in[8];
    const float* k_w     = (const float*)d_in[9];
    const float* k_b     = (const float*)d_in[10];
    const float* v_w     = (const float*)d_in[11];
    const float* v_b     = (const float*)d_in[12];
    const float* attn_g  = (const float*)d_in[13];
    const float* ppl_w   = (const float*)d_in[14];
    const float* ppl_b   = (const float*)d_in[15];
    const float* ppl_bng = (const float*)d_in[16];
    const float* ppl_bnb = (const float*)d_in[17];
    const float* ppl_bnm = (const float*)d_in[18];
    const float* ppl_bnv = (const float*)d_in[19];
    const float* proj_w  = (const float*)d_in[20];
    const float* proj_b  = (const float*)d_in[21];
    const float* pbn_g   = (const float*)d_in[22];
    const float* pbn_b   = (const float*)d_in[23];
    const float* pbn_m   = (const float*)d_in[24];
    const float* pbn_v   = (const float*)d_in[25];
    float* out = (float*)d_out;

    const int CONV_SMEM = 26240 * 4;  // 104,960 B -> 2 CTA/SM
    const int PROJ_SMEM = 34976 * 4;  // 139,904 B
    cudaFuncSetAttribute(k_conv, cudaFuncAttributeMaxDynamicSharedMemorySize, CONV_SMEM);
    cudaFuncSetAttribute(k_proj, cudaFuncAttributeMaxDynamicSharedMemorySize, PROJ_SMEM);

    k_conv<<<dim3(32, 8), 256, CONV_SMEM>>>(x, conv_w, conv_b, bn_g, bn_b, bn_m, bn_v,
                                            q_w, q_b, k_w, k_b, v_w, v_b);
    k_attn<<<dim3(32, 4, 2), 256>>>(attn_g);
    k_pool<<<dim3(1629, 2), 256>>>(ppl_w, ppl_b, ppl_bng, ppl_bnb, ppl_bnm, ppl_bnv);
    k_proj<<<128, 256, PROJ_SMEM>>>(proj_w, proj_b, pbn_g, pbn_b, pbn_m, pbn_v,
                                    ppl_w, ppl_b, ppl_bng, ppl_bnb, ppl_bnm, ppl_bnv, out);
}

// round 12
// speedup vs baseline: 1.1504x; 1.0326x over previous
#include <cuda_runtime.h>
#include <cuda_bf16.h>
#include <math.h>
#include <stdint.h>

#define NB 4
#define BATCH 2
#define HW 4096
#define F 64
#define LOG2E 1.4426950408889634f

// ---------------- scratch (device globals; no allocation allowed) ----------
__device__ float    g_fused[BATCH * HW * 256];
__device__ uint32_t g_q[BATCH * NB * HW * 8];
__device__ uint32_t g_k[BATCH * NB * HW * 8];
__device__ uint32_t g_vp[BATCH * NB * 32 * 4096];
__device__ float    g_pool[NB * BATCH * HW * 16];

// ---------------- helpers ---------------------------------------------------
__device__ __forceinline__ uint32_t f2tf32(float f) {
    uint32_t r; asm("cvt.rna.tf32.f32 %0, %1;" : "=r"(r) : "f"(f)); return r;
}
__device__ __forceinline__ uint32_t packbf(float hi, float lo) {
    uint32_t r; asm("cvt.rn.bf16x2.f32 %0, %1, %2;" : "=r"(r) : "f"(hi), "f"(lo)); return r;
}
__device__ __forceinline__ float ex2(float x) {
    float y; asm("ex2.approx.f32 %0, %1;" : "=f"(y) : "f"(x)); return y;
}
__device__ __forceinline__ void mma_tf32(float c[4], uint32_t a0, uint32_t a1,
                                         uint32_t a2, uint32_t a3,
                                         uint32_t b0, uint32_t b1) {
    asm volatile(
        "mma.sync.aligned.m16n8k8.row.col.f32.tf32.tf32.f32 "
        "{%0,%1,%2,%3},{%4,%5,%6,%7},{%8,%9},{%0,%1,%2,%3};"
        : "+f"(c[0]), "+f"(c[1]), "+f"(c[2]), "+f"(c[3])
        : "r"(a0), "r"(a1), "r"(a2), "r"(a3), "r"(b0), "r"(b1));
}
__device__ __forceinline__ void mma_bf16(float c[4], uint32_t a0, uint32_t a1,
                                         uint32_t a2, uint32_t a3,
                                         uint32_t b0, uint32_t b1) {
    asm volatile(
        "mma.sync.aligned.m16n8k16.row.col.f32.bf16.bf16.f32 "
        "{%0,%1,%2,%3},{%4,%5,%6,%7},{%8,%9},{%0,%1,%2,%3};"
        : "+f"(c[0]), "+f"(c[1]), "+f"(c[2]), "+f"(c[3])
        : "r"(a0), "r"(a1), "r"(a2), "r"(a3), "r"(b0), "r"(b1));
}
__device__ __forceinline__ void ldsm_x4(uint32_t& r0, uint32_t& r1,
                                        uint32_t& r2, uint32_t& r3, uint32_t addr) {
    asm volatile("ldmatrix.sync.aligned.m8n8.x4.shared.b16 {%0,%1,%2,%3}, [%4];"
        : "=r"(r0), "=r"(r1), "=r"(r2), "=r"(r3) : "r"(addr));
}
__device__ __forceinline__ void cpa16(uint32_t s, const void* g) {
    asm volatile("cp.async.cg.shared.global [%0], [%1], 16;" :: "r"(s), "l"(g));
}
__device__ __forceinline__ void cpa16z(uint32_t s, const void* g, int sz) {
    asm volatile("cp.async.cg.shared.global [%0], [%1], 16, %2;" :: "r"(s), "l"(g), "r"(sz));
}

// ---------------- K1: dilated conv + fused QKV (unchanged from R10) --------
__global__ void __launch_bounds__(256, 2) k_conv(
        const float* __restrict__ x, const float* __restrict__ wg,
        const float* __restrict__ cb, const float* __restrict__ bg,
        const float* __restrict__ bbe, const float* __restrict__ bm,
        const float* __restrict__ bv,
        const float* __restrict__ qw, const float* __restrict__ qb,
        const float* __restrict__ kw, const float* __restrict__ kb_,
        const float* __restrict__ vw, const float* __restrict__ vb) {
    extern __shared__ uint32_t dyn[];
    uint32_t* Vt = dyn + 8704;
    uint32_t* QW = dyn + 12928;
    uint32_t* KW = dyn + 13472;
    float* vbs = (float*)(dyn + 14016);
    float* qkb = (float*)(dyn + 14080);
    float* scs = (float*)(dyn + 26112);
    float* shs = (float*)(dyn + 26176);

    int tid = threadIdx.x;
    int bb = blockIdx.y, b = bb >> 2, br = bb & 3;
    int d = 1 << br;
    int pix0 = blockIdx.x * 128;
    int y0 = blockIdx.x * 2;

    if (tid < 64) {
        int idx = br * 64 + tid;
        float sc = bg[idx] * rsqrtf(bv[idx] + 1e-3f);
        scs[tid] = sc;
        shs[tid] = bbe[idx] - bm[idx] * sc + cb[idx] * sc;
    }

    int w = tid >> 5, lane = tid & 31;
    int g = lane >> 2, t = lane & 3;
    int m0 = w * 16;

    float c[8][4];
#pragma unroll
    for (int nb = 0; nb < 8; ++nb) c[nb][0] = c[nb][1] = c[nb][2] = c[nb][3] = 0.f;

    int p = tid >> 1, ch = (tid & 1) * 32;
    int prow = p >> 6, pcol = p & 63;
    int wci0 = tid >> 4, wco4 = (tid & 15) * 4;

    uint32_t sh0 = (uint32_t)__cvta_generic_to_shared(dyn);
    uint32_t a_dst0 = sh0 + (uint32_t)((p * 68 + ch) * 4);
    const float* xb = x + (size_t)b * 64 * 64 * 64;
    const float* wbase = wg + (size_t)br * 9 * 4096;

#define PREFETCH_A(tap, bi) do {                                             \
        int ky_ = (tap) / 3, kx_ = (tap) - ky_ * 3;                          \
        int iy_ = y0 + prow + d * (ky_ - 1);                                 \
        int ix_ = pcol + d * (kx_ - 1);                                      \
        int val_ = (((unsigned)iy_ < 64u) & ((unsigned)ix_ < 64u)) ? 16 : 0; \
        int iyc_ = min(max(iy_, 0), 63), ixc_ = min(max(ix_, 0), 63);        \
        const float* asrc_ = xb + (((size_t)iyc_ * 64 + ixc_) * 64 + ch);    \
        uint32_t ad_ = a_dst0 + (uint32_t)(bi) * 34816u;                     \
        _Pragma("unroll")                                                    \
        for (int i_ = 0; i_ < 8; ++i_) cpa16z(ad_ + i_ * 16, asrc_ + i_ * 4, val_); \
        asm volatile("cp.async.commit_group;");                              \
    } while (0)

    PREFETCH_A(0, 0);
    PREFETCH_A(1, 1);
    {
        uint32_t* W0 = dyn + 17408;
#pragma unroll
        for (int i = 0; i < 4; ++i) {
            int ci = wci0 + i * 16;
            float4 v = *(const float4*)(wbase + ci * 64 + wco4);
            W0[(wco4 + 0) * 68 + ci] = f2tf32(v.x);
            W0[(wco4 + 1) * 68 + ci] = f2tf32(v.y);
            W0[(wco4 + 2) * 68 + ci] = f2tf32(v.z);
            W0[(wco4 + 3) * 68 + ci] = f2tf32(v.w);
        }
    }
    asm volatile("cp.async.wait_group 1;");
    __syncthreads();

#pragma unroll 1
    for (int tap = 0; tap < 9; ++tap) {
        float4 wr[4];
        if (tap + 1 < 9) {
            const float* wt1 = wbase + (size_t)(tap + 1) * 4096;
#pragma unroll
            for (int i = 0; i < 4; ++i)
                wr[i] = *(const float4*)(wt1 + (wci0 + i * 16) * 64 + wco4);
        }
        const uint32_t* Ab = dyn + (tap & 1) * 8704;
        const uint32_t* Wb = dyn + 17408 + (tap & 1) * 4352;
        const uint32_t* Ar0 = Ab + (m0 + g) * 68 + t;
        const uint32_t* Ar1 = Ab + (m0 + g + 8) * 68 + t;
        const uint32_t* Wg_ = Wb + g * 68 + t;
#pragma unroll
        for (int k0 = 0; k0 < 64; k0 += 8) {
            uint32_t a0 = Ar0[k0], a1 = Ar1[k0];
            uint32_t a2 = Ar0[k0 + 4], a3 = Ar1[k0 + 4];
#pragma unroll
            for (int nb = 0; nb < 8; ++nb)
                mma_tf32(c[nb], a0, a1, a2, a3,
                         Wg_[nb * 8 * 68 + k0], Wg_[nb * 8 * 68 + k0 + 4]);
        }
        if (tap + 1 < 9) {
            uint32_t* Wn = dyn + 17408 + ((tap + 1) & 1) * 4352;
#pragma unroll
            for (int i = 0; i < 4; ++i) {
                int ci = wci0 + i * 16;
                Wn[(wco4 + 0) * 68 + ci] = f2tf32(wr[i].x);
                Wn[(wco4 + 1) * 68 + ci] = f2tf32(wr[i].y);
                Wn[(wco4 + 2) * 68 + ci] = f2tf32(wr[i].z);
                Wn[(wco4 + 3) * 68 + ci] = f2tf32(wr[i].w);
            }
        }
        __syncthreads();
        if (tap + 2 < 9) {
            PREFETCH_A(tap + 2, (tap & 1));
            asm volatile("cp.async.wait_group 1;");
            __syncthreads();
        } else if (tap + 1 < 9) {
            asm volatile("cp.async.wait_group 0;");
            __syncthreads();
        }
    }
#undef PREFETCH_A

    float rv[8][4];
    float* f0 = g_fused + ((size_t)b * HW + pix0 + m0 + g) * 256 + br * 64;
    float* f1 = f0 + 8 * 256;
#pragma unroll
    for (int nb = 0; nb < 8; ++nb) {
        int col = nb * 8 + 2 * t;
        rv[nb][0] = fmaxf(c[nb][0] * scs[col] + shs[col], 0.f);
        rv[nb][1] = fmaxf(c[nb][1] * scs[col + 1] + shs[col + 1], 0.f);
        rv[nb][2] = fmaxf(c[nb][2] * scs[col] + shs[col], 0.f);
        rv[nb][3] = fmaxf(c[nb][3] * scs[col + 1] + shs[col + 1], 0.f);
        *(float2*)(f0 + col) = make_float2(rv[nb][0], rv[nb][1]);
        *(float2*)(f1 + col) = make_float2(rv[nb][2], rv[nb][3]);
    }
    __syncthreads();
    uint32_t* As = dyn;
#pragma unroll
    for (int nb = 0; nb < 8; ++nb) {
        int col = nb * 8 + 2 * t;
        *(uint2*)&As[(m0 + g) * 68 + col] =
            make_uint2(f2tf32(rv[nb][0]), f2tf32(rv[nb][1]));
        *(uint2*)&As[(m0 + g + 8) * 68 + col] =
            make_uint2(f2tf32(rv[nb][2]), f2tf32(rv[nb][3]));
    }
    uint32_t* Wv = dyn + 17408;
#pragma unroll
    for (int i = 0; i < 4; ++i) {
        int ci = wci0 + i * 16;
        float4 v = *(const float4*)(vw + br * 4096 + ci * 64 + wco4);
        Wv[(wco4 + 0) * 68 + ci] = f2tf32(v.x);
        Wv[(wco4 + 1) * 68 + ci] = f2tf32(v.y);
        Wv[(wco4 + 2) * 68 + ci] = f2tf32(v.z);
        Wv[(wco4 + 3) * 68 + ci] = f2tf32(v.w);
    }
    if (tid < 128) {
        int ci = tid >> 1, d4 = (tid & 1) * 4;
        float4 v = *(const float4*)(qw + br * 512 + ci * 8 + d4);
        QW[(d4 + 0) * 68 + ci] = f2tf32(v.x * LOG2E);
        QW[(d4 + 1) * 68 + ci] = f2tf32(v.y * LOG2E);
        QW[(d4 + 2) * 68 + ci] = f2tf32(v.z * LOG2E);
        QW[(d4 + 3) * 68 + ci] = f2tf32(v.w * LOG2E);
    } else {
        int id = tid - 128;
        int ci = id >> 1, d4 = (id & 1) * 4;
        float4 v = *(const float4*)(kw + br * 512 + ci * 8 + d4);
        KW[(d4 + 0) * 68 + ci] = f2tf32(v.x);
        KW[(d4 + 1) * 68 + ci] = f2tf32(v.y);
        KW[(d4 + 2) * 68 + ci] = f2tf32(v.z);
        KW[(d4 + 3) * 68 + ci] = f2tf32(v.w);
    }
    if (tid < 64) vbs[tid] = vb[br * 64 + tid];
    if (tid >= 64 && tid < 72) qkb[tid - 64] = qb[br * 8 + tid - 64] * LOG2E;
    if (tid >= 72 && tid < 80) qkb[8 + tid - 72] = kb_[br * 8 + tid - 72];
    __syncthreads();
    const uint32_t* Ar0 = As + (m0 + g) * 68 + t;
    const uint32_t* Ar1 = As + (m0 + g + 8) * 68 + t;
    const uint32_t* Wg_ = Wv + g * 68 + t;
    float vac[8][4];
#pragma unroll
    for (int nb = 0; nb < 8; ++nb) vac[nb][0] = vac[nb][1] = vac[nb][2] = vac[nb][3] = 0.f;
#pragma unroll
    for (int k0 = 0; k0 < 64; k0 += 8) {
        uint32_t a0 = Ar0[k0], a1 = Ar1[k0];
        uint32_t a2 = Ar0[k0 + 4], a3 = Ar1[k0 + 4];
#pragma unroll
        for (int nb = 0; nb < 8; ++nb)
            mma_tf32(vac[nb], a0, a1, a2, a3, Wg_[nb * 8 * 68 + k0], Wg_[nb * 8 * 68 + k0 + 4]);
    }
    float qa_[4] = {0.f, 0.f, 0.f, 0.f}, ka_[4] = {0.f, 0.f, 0.f, 0.f};
    const uint32_t* Qg_ = QW + g * 68 + t;
    const uint32_t* Kg_ = KW + g * 68 + t;
#pragma unroll
    for (int k0 = 0; k0 < 64; k0 += 8) {
        uint32_t a0 = Ar0[k0], a1 = Ar1[k0];
        uint32_t a2 = Ar0[k0 + 4], a3 = Ar1[k0 + 4];
        mma_tf32(qa_, a0, a1, a2, a3, Qg_[k0], Qg_[k0 + 4]);
        mma_tf32(ka_, a0, a1, a2, a3, Kg_[k0], Kg_[k0 + 4]);
    }
    {
        float b0f = qkb[2 * t], b1f = qkb[2 * t + 1];
        uint32_t* qd = g_q + ((size_t)bb * HW + pix0 + m0 + g) * 8 + 2 * t;
        *(uint2*)qd = make_uint2(f2tf32(qa_[0] + b0f), f2tf32(qa_[1] + b1f));
        *(uint2*)(qd + 64) = make_uint2(f2tf32(qa_[2] + b0f), f2tf32(qa_[3] + b1f));
        float c0f = qkb[8 + 2 * t], c1f = qkb[8 + 2 * t + 1];
        uint32_t* kd = g_k + ((size_t)bb * HW + pix0 + m0 + g) * 8 + 2 * t;
        *(uint2*)kd = make_uint2(f2tf32(ka_[0] + c0f), f2tf32(ka_[1] + c1f));
        *(uint2*)(kd + 64) = make_uint2(f2tf32(ka_[2] + c0f), f2tf32(ka_[3] + c1f));
    }
#pragma unroll
    for (int nb = 0; nb < 8; ++nb) {
        int col = nb * 8 + 2 * t;
        Vt[(m0 + g) * 33 + nb * 4 + t] =
            packbf(vac[nb][1] + vbs[col + 1], vac[nb][0] + vbs[col]);
        Vt[(m0 + g + 8) * 33 + nb * 4 + t] =
            packbf(vac[nb][3] + vbs[col + 1], vac[nb][2] + vbs[col]);
    }
    __syncthreads();
    uint32_t* vout = g_vp + ((size_t)bb * 32 + blockIdx.x) * 4096;
#pragma unroll
    for (int i = 0; i < 16; ++i) {
        int o = tid + i * 256;
        int col = o & 3, row = (o >> 2) & 7, mat = o >> 5;
        int kpt = ((mat >> 3) << 2) | col;
        int cch = ((mat & 7) << 3) | row;
        uint32_t lo = Vt[(2 * kpt) * 33 + (cch >> 1)];
        uint32_t hi = Vt[(2 * kpt + 1) * 33 + (cch >> 1)];
        vout[o] = (cch & 1) ? ((lo >> 16) | (hi & 0xFFFF0000u))
                            : ((lo & 0xFFFFu) | (hi << 16));
    }
}

// ---------------- K3: flash attention, 3-stage pipeline, 1 sync/iter -------
// dynamic smem (words): Qs @0 (1024), Ks @1024 (3x1024), Vs @4096 (3x4096)
// total 16384 words = 65,536 B
__global__ void __launch_bounds__(256, 2) k_attn(const float* __restrict__ gamma) {
    extern __shared__ uint32_t dsh[];
    uint32_t* Qs = dsh;
    int tid = threadIdx.x;
    int br = blockIdx.y, b = blockIdx.z;
    int bb = b * NB + br;
    int n0 = blockIdx.x * 128;
    int w = tid >> 5, lane = tid & 31;
    int g = lane >> 2, t = lane & 3;

    const uint32_t* kgm = g_k + (size_t)bb * HW * 8;
    const uint32_t* vgm = g_vp + (size_t)bb * 32 * 4096;

    uint32_t shb = (uint32_t)__cvta_generic_to_shared(dsh);
    uint32_t ksa[3], vsa[3];
#pragma unroll
    for (int i = 0; i < 3; ++i) {
        ksa[i] = shb + (1024u + i * 1024u) * 4u;
        vsa[i] = shb + (4096u + i * 4096u) * 4u;
    }

    // prologue: prefetch tiles 0,1 into bufs 0,1; load Q
    cpa16(ksa[0] + tid * 16, kgm + tid * 4);
#pragma unroll
    for (int j = 0; j < 4; ++j)
        cpa16(vsa[0] + (tid + j * 256) * 16, vgm + (tid + j * 256) * 4);
    asm volatile("cp.async.commit_group;");
    ((uint4*)Qs)[tid] = ((const uint4*)(g_q + ((size_t)bb * HW + n0) * 8))[tid];
    cpa16(ksa[1] + tid * 16, kgm + 1024 + tid * 4);
#pragma unroll
    for (int j = 0; j < 4; ++j)
        cpa16(vsa[1] + (tid + j * 256) * 16, vgm + 4096 + (tid + j * 256) * 4);
    asm volatile("cp.async.commit_group;");
    __syncthreads();   // Qs visible

    int r0i = w * 16 + g;
    uint32_t qa0 = Qs[r0i * 8 + t];
    uint32_t qa1 = Qs[(r0i + 8) * 8 + t];
    uint32_t qa2 = Qs[r0i * 8 + t + 4];
    uint32_t qa3 = Qs[(r0i + 8) * 8 + t + 4];

    int midx = lane >> 3;
    int lane_const = (midx & 1) * 8 + (midx >> 1);
    uint32_t lboff = (uint32_t)((lane_const * 32 + (lane & 7) * 4) * 4);

    float o[8][4];
#pragma unroll
    for (int nb = 0; nb < 8; ++nb) { o[nb][0] = o[nb][1] = o[nb][2] = o[nb][3] = 0.f; }
    float Z0 = 0.f, Z1 = 0.f;

    int cur = 0, pf = 2;
#pragma unroll 1
    for (int it = 0; it < 32; ++it) {
        if (it < 31) asm volatile("cp.async.wait_group 1;");
        else         asm volatile("cp.async.wait_group 0;");
        __syncthreads();
        const uint32_t* Kc = dsh + 1024 + cur * 1024;
        uint32_t lb = vsa[cur] + lboff;

        uint32_t pa[16][2];
#pragma unroll
        for (int half = 0; half < 2; ++half) {
            float s[8][4];
#pragma unroll
            for (int n2 = 0; n2 < 8; ++n2) {
                int nb = half * 8 + n2;
                uint32_t b0 = Kc[(nb * 8 + g) * 8 + t];
                uint32_t b1 = Kc[(nb * 8 + g) * 8 + t + 4];
                s[n2][0] = s[n2][1] = s[n2][2] = s[n2][3] = 0.f;
                mma_tf32(s[n2], qa0, qa1, qa2, qa3, b0, b1);
            }
#pragma unroll
            for (int n2 = 0; n2 < 8; ++n2) {
                int j = half * 8 + n2;
                float p0 = ex2(s[n2][0]), p1 = ex2(s[n2][1]);
                float p2 = ex2(s[n2][2]), p3 = ex2(s[n2][3]);
                Z0 += p0 + p1; Z1 += p2 + p3;
                pa[j][0] = packbf(p1, p0);
                pa[j][1] = packbf(p3, p2);
            }
        }
#pragma unroll
        for (int ks = 0; ks < 8; ++ks) {
#pragma unroll
            for (int nbp = 0; nbp < 4; ++nbp) {
                uint32_t b00, b10, b01, b11;
                ldsm_x4(b00, b10, b01, b11, lb + (uint32_t)((16 * ks + 2 * nbp) * 128));
                mma_bf16(o[2 * nbp], pa[2 * ks][0], pa[2 * ks][1],
                         pa[2 * ks + 1][0], pa[2 * ks + 1][1], b00, b10);
                mma_bf16(o[2 * nbp + 1], pa[2 * ks][0], pa[2 * ks][1],
                         pa[2 * ks + 1][0], pa[2 * ks + 1][1], b01, b11);
            }
        }
        if (it + 2 < 32) {
            int t2 = it + 2;
            cpa16(ksa[pf] + tid * 16, kgm + (size_t)t2 * 1024 + tid * 4);
#pragma unroll
            for (int j = 0; j < 4; ++j)
                cpa16(vsa[pf] + (tid + j * 256) * 16,
                      vgm + (size_t)t2 * 4096 + (tid + j * 256) * 4);
            asm volatile("cp.async.commit_group;");
        }
        cur = (cur == 2) ? 0 : cur + 1;
        pf = (pf == 2) ? 0 : pf + 1;
    }
    Z0 += __shfl_xor_sync(0xffffffffu, Z0, 1);
    Z0 += __shfl_xor_sync(0xffffffffu, Z0, 2);
    Z1 += __shfl_xor_sync(0xffffffffu, Z1, 1);
    Z1 += __shfl_xor_sync(0xffffffffu, Z1, 2);
    float ga = gamma[br];
    float i0 = ga / Z0, i1 = ga / Z1;
    float* base0 = g_fused + ((size_t)b * HW + n0 + w * 16 + g) * 256 + br * 64 + 2 * t;
    float* base1 = base0 + 8 * 256;
#pragma unroll
    for (int nb = 0; nb < 8; ++nb) {
        float2 v0 = *(float2*)(base0 + nb * 8);
        v0.x += o[nb][0] * i0; v0.y += o[nb][1] * i0;
        *(float2*)(base0 + nb * 8) = v0;
        float2 v1 = *(float2*)(base1 + nb * 8);
        v1.x += o[nb][2] * i1; v1.y += o[nb][3] * i1;
        *(float2*)(base1 + nb * 8) = v1;
    }
}

// ---------------- K4: pool, float4 channels, 4 outputs/block ---------------
template<int PS, int PLO>
__device__ __forceinline__ float4 pool_win4(int b, int oy, int ox, int c4) {
    int ys0 = oy * PS - PLO, xs0 = ox * PS - PLO;
    float4 s = make_float4(0.f, 0.f, 0.f, 0.f);
    int cnt = 0;
#pragma unroll
    for (int dy = 0; dy < PS; ++dy) {
        int yy = ys0 + dy;
        bool vy = (unsigned)yy < 64u;
        int yyc = min(max(yy, 0), 63);
#pragma unroll
        for (int dx = 0; dx < PS; ++dx) {
            int xx = xs0 + dx;
            bool v = vy && ((unsigned)xx < 64u);
            int xxc = min(max(xx, 0), 63);
            float4 val = *(const float4*)(g_fused + ((size_t)(b * HW) + yyc * 64 + xxc) * 256 + c4);
            if (v) { s.x += val.x; s.y += val.y; s.z += val.z; s.w += val.w; ++cnt; }
        }
    }
    float inv = 1.f / (float)cnt;
    s.x *= inv; s.y *= inv; s.z *= inv; s.w *= inv;
    return s;
}

__global__ void k_pool(const float* __restrict__ pw, const float* __restrict__ pb,
                       const float* __restrict__ pg, const float* __restrict__ pbe,
                       const float* __restrict__ pm, const float* __restrict__ pv) {
    __shared__ float avg[4][256];
    __shared__ float part[4][64];
    int b = blockIdx.y;
    int slot = threadIdx.x >> 6;
    int l64 = threadIdx.x & 63;
    int lin = blockIdx.x * 4 + slot;
    bool valid = lin < 1629;
    int linc = valid ? lin : 1628;
    int j, r;
    if (linc < 1024)      { j = 1; r = linc; }
    else if (linc < 1508) { j = 2; r = linc - 1024; }
    else                  { j = 3; r = linc - 1508; }
    const int HPs[4] = {64, 32, 22, 11};
    int hp = HPs[j];
    int oy = r / hp, ox = r % hp;
    int c4 = l64 * 4;
    float4 s;
    if (j == 1)      s = pool_win4<2, 0>(b, oy, ox, c4);
    else if (j == 2) s = pool_win4<3, 1>(b, oy, ox, c4);
    else             s = pool_win4<6, 1>(b, oy, ox, c4);
    *(float4*)&avg[slot][c4] = s;
    __syncthreads();
    // conv 256->16: per output, 64 threads: o = l64&15, q = l64>>4 owns ci in [q*64, q*64+64)
    int o = l64 & 15, q = l64 >> 4;
    const float* wp = pw + j * 4096 + o;
    float a = 0.f;
#pragma unroll 16
    for (int i = 0; i < 64; ++i) {
        int ci = q * 64 + i;
        a += avg[slot][ci] * wp[ci * 16];
    }
    part[slot][q * 16 + o] = a;
    __syncthreads();
    if (l64 < 16 && valid) {
        float acc = pb[j * 16 + l64] + part[slot][l64] + part[slot][16 + l64]
                  + part[slot][32 + l64] + part[slot][48 + l64];
        int idx = j * 16 + l64;
        float sc = pg[idx] * rsqrtf(pv[idx] + 1e-3f);
        float sh = pbe[idx] - pm[idx] * sc;
        g_pool[((size_t)((j * 2 + b) * HW) + oy * hp + ox) * 16 + l64] = acc * sc + sh;
    }
}

// ---------------- K5: proj GEMM, W1 staged per-chunk (pipelined) -----------
// dyn (words): A0 @0 (4352, reused as X2), A1 @4352, Wb0 @8704 (5440),
//   Wb1 @14144, W2 @19584 (4352), scs2 @23936, shs2 @24000, psc @24064,
//   psh @24080 .. 24096  -> 96,384 B
__global__ void __launch_bounds__(256) k_proj(
        const float* __restrict__ w, const float* __restrict__ pb,
        const float* __restrict__ g2, const float* __restrict__ be,
        const float* __restrict__ m, const float* __restrict__ v,
        const float* __restrict__ pplw, const float* __restrict__ pplb,
        const float* __restrict__ ppg, const float* __restrict__ ppbe,
        const float* __restrict__ ppm, const float* __restrict__ ppv,
        float* __restrict__ out) {
    extern __shared__ uint32_t dyn[];
    uint32_t* W2 = dyn + 19584;
    float* scs2 = (float*)(dyn + 23936);
    float* shs2 = (float*)(dyn + 24000);
    float* psc = (float*)(dyn + 24064);
    float* psh = (float*)(dyn + 24080);

    int tid = threadIdx.x;
    int tok0 = blockIdx.x * 64;
    int b2 = tok0 >> 12;
    int yy = (tok0 & 4095) >> 6;
    int w_ = tid >> 5, lane = tid & 31;
    int wm = w_ & 3, wn = w_ >> 2;
    int g = lane >> 2, t = lane & 3;
    int m0 = wm * 16;

    int p4 = tid >> 2, cs = (tid & 3) * 16;
    const float* asrc = g_fused + (size_t)(tok0 + p4) * 256 + cs;
    float4 ar[4];
    // W staging coords
    int wcl = tid >> 4, wco4 = (tid & 15) * 4;       // proj rows
    int wsc4 = wco4 + (wco4 >= 32 ? 8 : 0);
    int qcl = tid >> 2, qo4 = (tid & 3) * 4;         // pool0 rows
    int qsc4 = (qo4 < 8) ? (32 + qo4) : (64 + qo4);

#define LOADA(ck) do {                                                      \
        const float* s_ = asrc + (ck) * 64;                                 \
        ar[0] = *(const float4*)(s_);      ar[1] = *(const float4*)(s_ + 4); \
        ar[2] = *(const float4*)(s_ + 8);  ar[3] = *(const float4*)(s_ + 12); \
    } while (0)
#define STOREA(bi) do {                                                     \
        uint32_t* d_ = dyn + (bi) * 4352 + p4 * 68 + cs;                    \
        _Pragma("unroll")                                                   \
        for (int i_ = 0; i_ < 4; ++i_) {                                    \
            *(uint2*)(d_ + i_ * 4) =                                        \
                make_uint2(f2tf32(ar[i_].x), f2tf32(ar[i_].y));             \
            *(uint2*)(d_ + i_ * 4 + 2) =                                    \
                make_uint2(f2tf32(ar[i_].z), f2tf32(ar[i_].w));             \
        }                                                                   \
    } while (0)

    LOADA(0); STOREA(0);
    // ---- stage W chunk 0 directly; W2; consts ----
    {
        uint32_t* Wb0 = dyn + 8704;
#pragma unroll
        for (int i = 0; i < 4; ++i) {
            int cl = wcl + i * 16;
            float4 vv = *(const float4*)(w + cl * 64 + wco4);
            Wb0[(wsc4 + 0) * 68 + cl] = f2tf32(vv.x);
            Wb0[(wsc4 + 1) * 68 + cl] = f2tf32(vv.y);
            Wb0[(wsc4 + 2) * 68 + cl] = f2tf32(vv.z);
            Wb0[(wsc4 + 3) * 68 + cl] = f2tf32(vv.w);
        }
        float4 vv = *(const float4*)(pplw + qcl * 16 + qo4);
        Wb0[(qsc4 + 0) * 68 + qcl] = f2tf32(vv.x);
        Wb0[(qsc4 + 1) * 68 + qcl] = f2tf32(vv.y);
        Wb0[(qsc4 + 2) * 68 + qcl] = f2tf32(vv.z);
        Wb0[(qsc4 + 3) * 68 + qcl] = f2tf32(vv.w);
    }
#pragma unroll
    for (int i = 0; i < 4; ++i) {
        int id = tid + i * 256;
        int k = id >> 4, co4 = (id & 15) * 4;
        float4 vv = *(const float4*)(w + (256 + k) * 64 + co4);
        W2[(co4 + 0) * 68 + k] = f2tf32(vv.x);
        W2[(co4 + 1) * 68 + k] = f2tf32(vv.y);
        W2[(co4 + 2) * 68 + k] = f2tf32(vv.z);
        W2[(co4 + 3) * 68 + k] = f2tf32(vv.w);
    }
    if (tid < 64) {
        float sc = g2[tid] * rsqrtf(v[tid] + 1e-3f);
        scs2[tid] = sc;
        shs2[tid] = be[tid] - m[tid] * sc + pb[tid] * sc;
    } else if (tid < 80) {
        int o = tid - 64;
        float sc = ppg[o] * rsqrtf(ppv[o] + 1e-3f);
        psc[o] = sc;
        psh[o] = ppbe[o] - ppm[o] * sc + pplb[o] * sc;
    }
    LOADA(1);
    __syncthreads();

    // ---- GEMM1: [64,256] x [256,40] per N-half, W chunk pipelined ----
    float a1c[5][4];
#pragma unroll
    for (int nb = 0; nb < 5; ++nb) a1c[nb][0] = a1c[nb][1] = a1c[nb][2] = a1c[nb][3] = 0.f;
    int wn40 = wn * 40;
#pragma unroll 1
    for (int ck = 0; ck < 4; ++ck) {
        float4 wrp[4], wrq;
        if (ck + 1 < 4) {
            int cb = (ck + 1) * 64;
#pragma unroll
            for (int i = 0; i < 4; ++i)
                wrp[i] = *(const float4*)(w + (cb + wcl + i * 16) * 64 + wco4);
            wrq = *(const float4*)(pplw + (cb + qcl) * 16 + qo4);
        }
        const uint32_t* Ab = dyn + (ck & 1) * 4352;
        const uint32_t* Ar0 = Ab + (m0 + g) * 68 + t;
        const uint32_t* Ar1 = Ab + (m0 + g + 8) * 68 + t;
        const uint32_t* Wc = dyn + 8704 + (ck & 1) * 5440 + (wn40 + g) * 68 + t;
#pragma unroll
        for (int k0 = 0; k0 < 64; k0 += 8) {
            uint32_t a0 = Ar0[k0], a1 = Ar1[k0];
            uint32_t a2 = Ar0[k0 + 4], a3 = Ar1[k0 + 4];
#pragma unroll
            for (int nb = 0; nb < 5; ++nb)
                mma_tf32(a1c[nb], a0, a1, a2, a3,
                         Wc[nb * 544 + k0], Wc[nb * 544 + k0 + 4]);
        }
        if (ck + 1 < 4) {
            uint32_t* Wn = dyn + 8704 + ((ck + 1) & 1) * 5440;
#pragma unroll
            for (int i = 0; i < 4; ++i) {
                int cl = wcl + i * 16;
                Wn[(wsc4 + 0) * 68 + cl] = f2tf32(wrp[i].x);
                Wn[(wsc4 + 1) * 68 + cl] = f2tf32(wrp[i].y);
                Wn[(wsc4 + 2) * 68 + cl] = f2tf32(wrp[i].z);
                Wn[(wsc4 + 3) * 68 + cl] = f2tf32(wrp[i].w);
            }
            Wn[(qsc4 + 0) * 68 + qcl] = f2tf32(wrq.x);
            Wn[(qsc4 + 1) * 68 + qcl] = f2tf32(wrq.y);
            Wn[(qsc4 + 2) * 68 + qcl] = f2tf32(wrq.z);
            Wn[(qsc4 + 3) * 68 + qcl] = f2tf32(wrq.w);
            STOREA((ck + 1) & 1);
        }
        __syncthreads();
        if (ck + 2 < 4) LOADA(ck + 2);
    }
#undef LOADA
#undef STOREA

    // ---- X2 assembly in A0 ----
    uint32_t* X2 = dyn;
    {
        int o = wn * 8 + 2 * t;
        float s0 = psc[o], s1 = psc[o + 1], h0 = psh[o], h1 = psh[o + 1];
        *(uint2*)&X2[(m0 + g) * 68 + o] =
            make_uint2(f2tf32(a1c[4][0] * s0 + h0), f2tf32(a1c[4][1] * s1 + h1));
        *(uint2*)&X2[(m0 + g + 8) * 68 + o] =
            make_uint2(f2tf32(a1c[4][2] * s0 + h0), f2tf32(a1c[4][3] * s1 + h1));
    }
    {
        const int HP[3] = {32, 22, 11};
#pragma unroll
        for (int lvl = 0; lvl < 3; ++lvl) {
            int hp = HP[lvl];
            float scale = hp * (1.f / 64.f);
            const float* P0 = g_pool + (size_t)(((lvl + 1) * 2 + b2) * HW) * 16;
            float fy = (yy + 0.5f) * scale - 0.5f;
            float y0f = floorf(fy);
            float ty = fy - y0f;
            int yA = min(max((int)y0f, 0), hp - 1);
            int yB = min(max((int)y0f + 1, 0), hp - 1);
#pragma unroll
            for (int i = 0; i < 4; ++i) {
                int id = tid + i * 256;
                int px = id >> 4, c = id & 15;
                float fx = (px + 0.5f) * scale - 0.5f;
                float x0f = floorf(fx);
                float tx = fx - x0f;
                int xA = min(max((int)x0f, 0), hp - 1);
                int xB = min(max((int)x0f + 1, 0), hp - 1);
                const float* P = P0 + c;
                float v00 = P[(yA * hp + xA) * 16], v01 = P[(yA * hp + xB) * 16];
                float v10 = P[(yB * hp + xA) * 16], v11 = P[(yB * hp + xB) * 16];
                float val = (1.f - ty) * ((1.f - tx) * v00 + tx * v01)
                          + ty * ((1.f - tx) * v10 + tx * v11);
                X2[px * 68 + 16 + lvl * 16 + c] = f2tf32(val);
            }
        }
    }
    __syncthreads();

    // ---- GEMM2: X2[64,64] x W2 (N half = 32 cols) ----
    float a2c[4][4];
#pragma unroll
    for (int nb = 0; nb < 4; ++nb) a2c[nb][0] = a2c[nb][1] = a2c[nb][2] = a2c[nb][3] = 0.f;
    {
        const uint32_t* Ar0 = X2 + (m0 + g) * 68 + t;
        const uint32_t* Ar1 = X2 + (m0 + g + 8) * 68 + t;
        const uint32_t* Wc = W2 + (wn * 32 + g) * 68 + t;
#pragma unroll
        for (int k0 = 0; k0 < 64; k0 += 8) {
            uint32_t a0 = Ar0[k0], a1 = Ar1[k0];
            uint32_t a2 = Ar0[k0 + 4], a3 = Ar1[k0 + 4];
#pragma unroll
            for (int nb = 0; nb < 4; ++nb)
                mma_tf32(a2c[nb], a0, a1, a2, a3,
                         Wc[nb * 544 + k0], Wc[nb * 544 + k0 + 4]);
        }
    }
    // ---- epilogue: BN + ReLU -> out ----
    float* o0 = out + (size_t)(tok0 + m0 + g) * 64;
    float* o1 = o0 + 8 * 64;
#pragma unroll
    for (int nb = 0; nb < 4; ++nb) {
        int col = wn * 32 + nb * 8 + 2 * t;
        float s0 = scs2[col], s1 = scs2[col + 1];
        float h0 = shs2[col], h1 = shs2[col + 1];
        float2 r0, r1;
        r0.x = fmaxf((a1c[nb][0] + a2c[nb][0]) * s0 + h0, 0.f);
        r0.y = fmaxf((a1c[nb][1] + a2c[nb][1]) * s1 + h1, 0.f);
        r1.x = fmaxf((a1c[nb][2] + a2c[nb][2]) * s0 + h0, 0.f);
        r1.y = fmaxf((a1c[nb][3] + a2c[nb][3]) * s1 + h1, 0.f);
        *(float2*)(o0 + col) = r0;
        *(float2*)(o1 + col) = r1;
    }
}

// ---------------- launch ---------------------------------------------------
extern "C" void kernel_launch(void* const* d_in, const int* in_sizes, int n_in,
                              void* d_out, int out_size) {
    const float* x       = (const float*)d_in[0];
    const float* conv_w  = (const float*)d_in[1];
    const float* conv_b  = (const float*)d_in[2];
    const float* bn_g    = (const float*)d_in[3];
    const float* bn_b    = (const float*)d_in[4];
    const float* bn_m    = (const float*)d_in[5];
    const float* bn_v    = (const float*)d_in[6];
    const float* q_w     = (const float*)d_in[7];
    const float* q_b     = (const float*)d_in[8];
    const float* k_w     = (const float*)d_in[9];
    const float* k_b     = (const float*)d_in[10];
    const float* v_w     = (const float*)d_in[11];
    const float* v_b     = (const float*)d_in[12];
    const float* attn_g  = (const float*)d_in[13];
    const float* ppl_w   = (const float*)d_in[14];
    const float* ppl_b   = (const float*)d_in[15];
    const float* ppl_bng = (const float*)d_in[16];
    const float* ppl_bnb = (const float*)d_in[17];
    const float* ppl_bnm = (const float*)d_in[18];
    const float* ppl_bnv = (const float*)d_in[19];
    const float* proj_w  = (const float*)d_in[20];
    const float* proj_b  = (const float*)d_in[21];
    const float* pbn_g   = (const float*)d_in[22];
    const float* pbn_b   = (const float*)d_in[23];
    const float* pbn_m   = (const float*)d_in[24];
    const float* pbn_v   = (const float*)d_in[25];
    float* out = (float*)d_out;

    const int CONV_SMEM = 26240 * 4;   // 104,960 B
    const int ATTN_SMEM = 16384 * 4;   // 65,536 B
    const int PROJ_SMEM = 24096 * 4;   // 96,384 B
    cudaFuncSetAttribute(k_conv, cudaFuncAttributeMaxDynamicSharedMemorySize, CONV_SMEM);
    cudaFuncSetAttribute(k_attn, cudaFuncAttributeMaxDynamicSharedMemorySize, ATTN_SMEM);
    cudaFuncSetAttribute(k_proj, cudaFuncAttributeMaxDynamicSharedMemorySize, PROJ_SMEM);

    k_conv<<<dim3(32, 8), 256, CONV_SMEM>>>(x, conv_w, conv_b, bn_g, bn_b, bn_m, bn_v,
                                            q_w, q_b, k_w, k_b, v_w, v_b);
    k_attn<<<dim3(32, 4, 2), 256, ATTN_SMEM>>>(attn_g);
    k_pool<<<dim3(408, 2), 256>>>(ppl_w, ppl_b, ppl_bng, ppl_bnb, ppl_bnm, ppl_bnv);
    k_proj<<<128, 256, PROJ_SMEM>>>(proj_w, proj_b, pbn_g, pbn_b, pbn_m, pbn_v,
                                    ppl_w, ppl_b, ppl_bng, ppl_bnb, ppl_bnm, ppl_bnv, out);
}

// round 13
// speedup vs baseline: 1.2192x; 1.0598x over previous
#include <cuda_runtime.h>
#include <cuda_bf16.h>
#include <math.h>
#include <stdint.h>

#define NB 4
#define BATCH 2
#define HW 4096
#define F 64
#define LOG2E 1.4426950408889634f

// ---------------- scratch (device globals; no allocation allowed) ----------
__device__ float    g_fused[BATCH * HW * 256];
__device__ uint32_t g_q[BATCH * NB * HW * 8];
__device__ uint32_t g_k[BATCH * NB * HW * 8];
__device__ uint32_t g_vp[BATCH * NB * 32 * 4096];   // f16x2 pairs, ldmatrix order
__device__ float    g_pool[NB * BATCH * HW * 16];

// ---------------- helpers ---------------------------------------------------
__device__ __forceinline__ uint32_t f2tf32(float f) {
    uint32_t r; asm("cvt.rna.tf32.f32 %0, %1;" : "=r"(r) : "f"(f)); return r;
}
__device__ __forceinline__ uint32_t packh(float hi, float lo) {
    uint32_t r; asm("cvt.rn.f16x2.f32 %0, %1, %2;" : "=r"(r) : "f"(hi), "f"(lo)); return r;
}
__device__ __forceinline__ uint32_t ex2h2(uint32_t x) {
    uint32_t y; asm("ex2.approx.f16x2 %0, %1;" : "=r"(y) : "r"(x)); return y;
}
__device__ __forceinline__ void mma_tf32(float c[4], uint32_t a0, uint32_t a1,
                                         uint32_t a2, uint32_t a3,
                                         uint32_t b0, uint32_t b1) {
    asm volatile(
        "mma.sync.aligned.m16n8k8.row.col.f32.tf32.tf32.f32 "
        "{%0,%1,%2,%3},{%4,%5,%6,%7},{%8,%9},{%0,%1,%2,%3};"
        : "+f"(c[0]), "+f"(c[1]), "+f"(c[2]), "+f"(c[3])
        : "r"(a0), "r"(a1), "r"(a2), "r"(a3), "r"(b0), "r"(b1));
}
__device__ __forceinline__ void mma_f16(float c[4], uint32_t a0, uint32_t a1,
                                        uint32_t a2, uint32_t a3,
                                        uint32_t b0, uint32_t b1) {
    asm volatile(
        "mma.sync.aligned.m16n8k16.row.col.f32.f16.f16.f32 "
        "{%0,%1,%2,%3},{%4,%5,%6,%7},{%8,%9},{%0,%1,%2,%3};"
        : "+f"(c[0]), "+f"(c[1]), "+f"(c[2]), "+f"(c[3])
        : "r"(a0), "r"(a1), "r"(a2), "r"(a3), "r"(b0), "r"(b1));
}
__device__ __forceinline__ void ldsm_x4(uint32_t& r0, uint32_t& r1,
                                        uint32_t& r2, uint32_t& r3, uint32_t addr) {
    asm volatile("ldmatrix.sync.aligned.m8n8.x4.shared.b16 {%0,%1,%2,%3}, [%4];"
        : "=r"(r0), "=r"(r1), "=r"(r2), "=r"(r3) : "r"(addr));
}
__device__ __forceinline__ void cpa16(uint32_t s, const void* g) {
    asm volatile("cp.async.cg.shared.global [%0], [%1], 16;" :: "r"(s), "l"(g));
}
__device__ __forceinline__ void cpa16z(uint32_t s, const void* g, int sz) {
    asm volatile("cp.async.cg.shared.global [%0], [%1], 16, %2;" :: "r"(s), "l"(g), "r"(sz));
}

// ---------------- K1: dilated conv + fused QKV --------------------------
__global__ void __launch_bounds__(256, 2) k_conv(
        const float* __restrict__ x, const float* __restrict__ wg,
        const float* __restrict__ cb, const float* __restrict__ bg,
        const float* __restrict__ bbe, const float* __restrict__ bm,
        const float* __restrict__ bv,
        const float* __restrict__ qw, const float* __restrict__ qb,
        const float* __restrict__ kw, const float* __restrict__ kb_,
        const float* __restrict__ vw, const float* __restrict__ vb) {
    extern __shared__ uint32_t dyn[];
    uint32_t* Vt = dyn + 8704;
    uint32_t* QW = dyn + 12928;
    uint32_t* KW = dyn + 13472;
    float* vbs = (float*)(dyn + 14016);
    float* qkb = (float*)(dyn + 14080);
    float* scs = (float*)(dyn + 26112);
    float* shs = (float*)(dyn + 26176);

    int tid = threadIdx.x;
    int bb = blockIdx.y, b = bb >> 2, br = bb & 3;
    int d = 1 << br;
    int pix0 = blockIdx.x * 128;
    int y0 = blockIdx.x * 2;

    if (tid < 64) {
        int idx = br * 64 + tid;
        float sc = bg[idx] * rsqrtf(bv[idx] + 1e-3f);
        scs[tid] = sc;
        shs[tid] = bbe[idx] - bm[idx] * sc + cb[idx] * sc;
    }

    int w = tid >> 5, lane = tid & 31;
    int g = lane >> 2, t = lane & 3;
    int m0 = w * 16;

    float c[8][4];
#pragma unroll
    for (int nb = 0; nb < 8; ++nb) c[nb][0] = c[nb][1] = c[nb][2] = c[nb][3] = 0.f;

    int p = tid >> 1, ch = (tid & 1) * 32;
    int prow = p >> 6, pcol = p & 63;
    int wci0 = tid >> 4, wco4 = (tid & 15) * 4;

    uint32_t sh0 = (uint32_t)__cvta_generic_to_shared(dyn);
    uint32_t a_dst0 = sh0 + (uint32_t)((p * 68 + ch) * 4);
    const float* xb = x + (size_t)b * 64 * 64 * 64;
    const float* wbase = wg + (size_t)br * 9 * 4096;

#define PREFETCH_A(tap, bi) do {                                             \
        int ky_ = (tap) / 3, kx_ = (tap) - ky_ * 3;                          \
        int iy_ = y0 + prow + d * (ky_ - 1);                                 \
        int ix_ = pcol + d * (kx_ - 1);                                      \
        int val_ = (((unsigned)iy_ < 64u) & ((unsigned)ix_ < 64u)) ? 16 : 0; \
        int iyc_ = min(max(iy_, 0), 63), ixc_ = min(max(ix_, 0), 63);        \
        const float* asrc_ = xb + (((size_t)iyc_ * 64 + ixc_) * 64 + ch);    \
        uint32_t ad_ = a_dst0 + (uint32_t)(bi) * 34816u;                     \
        _Pragma("unroll")                                                    \
        for (int i_ = 0; i_ < 8; ++i_) cpa16z(ad_ + i_ * 16, asrc_ + i_ * 4, val_); \
        asm volatile("cp.async.commit_group;");                              \
    } while (0)

    PREFETCH_A(0, 0);
    PREFETCH_A(1, 1);
    {
        uint32_t* W0 = dyn + 17408;
#pragma unroll
        for (int i = 0; i < 4; ++i) {
            int ci = wci0 + i * 16;
            float4 v = *(const float4*)(wbase + ci * 64 + wco4);
            W0[(wco4 + 0) * 68 + ci] = f2tf32(v.x);
            W0[(wco4 + 1) * 68 + ci] = f2tf32(v.y);
            W0[(wco4 + 2) * 68 + ci] = f2tf32(v.z);
            W0[(wco4 + 3) * 68 + ci] = f2tf32(v.w);
        }
    }
    asm volatile("cp.async.wait_group 1;");
    __syncthreads();

#pragma unroll 1
    for (int tap = 0; tap < 9; ++tap) {
        float4 wr[4];
        if (tap + 1 < 9) {
            const float* wt1 = wbase + (size_t)(tap + 1) * 4096;
#pragma unroll
            for (int i = 0; i < 4; ++i)
                wr[i] = *(const float4*)(wt1 + (wci0 + i * 16) * 64 + wco4);
        }
        const uint32_t* Ab = dyn + (tap & 1) * 8704;
        const uint32_t* Wb = dyn + 17408 + (tap & 1) * 4352;
        const uint32_t* Ar0 = Ab + (m0 + g) * 68 + t;
        const uint32_t* Ar1 = Ab + (m0 + g + 8) * 68 + t;
        const uint32_t* Wg_ = Wb + g * 68 + t;
#pragma unroll
        for (int k0 = 0; k0 < 64; k0 += 8) {
            uint32_t a0 = Ar0[k0], a1 = Ar1[k0];
            uint32_t a2 = Ar0[k0 + 4], a3 = Ar1[k0 + 4];
#pragma unroll
            for (int nb = 0; nb < 8; ++nb)
                mma_tf32(c[nb], a0, a1, a2, a3,
                         Wg_[nb * 8 * 68 + k0], Wg_[nb * 8 * 68 + k0 + 4]);
        }
        if (tap + 1 < 9) {
            uint32_t* Wn = dyn + 17408 + ((tap + 1) & 1) * 4352;
#pragma unroll
            for (int i = 0; i < 4; ++i) {
                int ci = wci0 + i * 16;
                Wn[(wco4 + 0) * 68 + ci] = f2tf32(wr[i].x);
                Wn[(wco4 + 1) * 68 + ci] = f2tf32(wr[i].y);
                Wn[(wco4 + 2) * 68 + ci] = f2tf32(wr[i].z);
                Wn[(wco4 + 3) * 68 + ci] = f2tf32(wr[i].w);
            }
        }
        __syncthreads();
        if (tap + 2 < 9) {
            PREFETCH_A(tap + 2, (tap & 1));
            asm volatile("cp.async.wait_group 1;");
            __syncthreads();
        } else if (tap + 1 < 9) {
            asm volatile("cp.async.wait_group 0;");
            __syncthreads();
        }
    }
#undef PREFETCH_A

    float rv[8][4];
    float* f0 = g_fused + ((size_t)b * HW + pix0 + m0 + g) * 256 + br * 64;
    float* f1 = f0 + 8 * 256;
#pragma unroll
    for (int nb = 0; nb < 8; ++nb) {
        int col = nb * 8 + 2 * t;
        rv[nb][0] = fmaxf(c[nb][0] * scs[col] + shs[col], 0.f);
        rv[nb][1] = fmaxf(c[nb][1] * scs[col + 1] + shs[col + 1], 0.f);
        rv[nb][2] = fmaxf(c[nb][2] * scs[col] + shs[col], 0.f);
        rv[nb][3] = fmaxf(c[nb][3] * scs[col + 1] + shs[col + 1], 0.f);
        *(float2*)(f0 + col) = make_float2(rv[nb][0], rv[nb][1]);
        *(float2*)(f1 + col) = make_float2(rv[nb][2], rv[nb][3]);
    }
    __syncthreads();
    uint32_t* As = dyn;
#pragma unroll
    for (int nb = 0; nb < 8; ++nb) {
        int col = nb * 8 + 2 * t;
        *(uint2*)&As[(m0 + g) * 68 + col] =
            make_uint2(f2tf32(rv[nb][0]), f2tf32(rv[nb][1]));
        *(uint2*)&As[(m0 + g + 8) * 68 + col] =
            make_uint2(f2tf32(rv[nb][2]), f2tf32(rv[nb][3]));
    }
    uint32_t* Wv = dyn + 17408;
#pragma unroll
    for (int i = 0; i < 4; ++i) {
        int ci = wci0 + i * 16;
        float4 v = *(const float4*)(vw + br * 4096 + ci * 64 + wco4);
        Wv[(wco4 + 0) * 68 + ci] = f2tf32(v.x);
        Wv[(wco4 + 1) * 68 + ci] = f2tf32(v.y);
        Wv[(wco4 + 2) * 68 + ci] = f2tf32(v.z);
        Wv[(wco4 + 3) * 68 + ci] = f2tf32(v.w);
    }
    if (tid < 128) {
        int ci = tid >> 1, d4 = (tid & 1) * 4;
        float4 v = *(const float4*)(qw + br * 512 + ci * 8 + d4);
        QW[(d4 + 0) * 68 + ci] = f2tf32(v.x * LOG2E);
        QW[(d4 + 1) * 68 + ci] = f2tf32(v.y * LOG2E);
        QW[(d4 + 2) * 68 + ci] = f2tf32(v.z * LOG2E);
        QW[(d4 + 3) * 68 + ci] = f2tf32(v.w * LOG2E);
    } else {
        int id = tid - 128;
        int ci = id >> 1, d4 = (id & 1) * 4;
        float4 v = *(const float4*)(kw + br * 512 + ci * 8 + d4);
        KW[(d4 + 0) * 68 + ci] = f2tf32(v.x);
        KW[(d4 + 1) * 68 + ci] = f2tf32(v.y);
        KW[(d4 + 2) * 68 + ci] = f2tf32(v.z);
        KW[(d4 + 3) * 68 + ci] = f2tf32(v.w);
    }
    if (tid < 64) vbs[tid] = vb[br * 64 + tid];
    if (tid >= 64 && tid < 72) qkb[tid - 64] = qb[br * 8 + tid - 64] * LOG2E;
    if (tid >= 72 && tid < 80) qkb[8 + tid - 72] = kb_[br * 8 + tid - 72];
    __syncthreads();
    const uint32_t* Ar0 = As + (m0 + g) * 68 + t;
    const uint32_t* Ar1 = As + (m0 + g + 8) * 68 + t;
    const uint32_t* Wg_ = Wv + g * 68 + t;
    float vac[8][4];
#pragma unroll
    for (int nb = 0; nb < 8; ++nb) vac[nb][0] = vac[nb][1] = vac[nb][2] = vac[nb][3] = 0.f;
#pragma unroll
    for (int k0 = 0; k0 < 64; k0 += 8) {
        uint32_t a0 = Ar0[k0], a1 = Ar1[k0];
        uint32_t a2 = Ar0[k0 + 4], a3 = Ar1[k0 + 4];
#pragma unroll
        for (int nb = 0; nb < 8; ++nb)
            mma_tf32(vac[nb], a0, a1, a2, a3, Wg_[nb * 8 * 68 + k0], Wg_[nb * 8 * 68 + k0 + 4]);
    }
    float qa_[4] = {0.f, 0.f, 0.f, 0.f}, ka_[4] = {0.f, 0.f, 0.f, 0.f};
    const uint32_t* Qg_ = QW + g * 68 + t;
    const uint32_t* Kg_ = KW + g * 68 + t;
#pragma unroll
    for (int k0 = 0; k0 < 64; k0 += 8) {
        uint32_t a0 = Ar0[k0], a1 = Ar1[k0];
        uint32_t a2 = Ar0[k0 + 4], a3 = Ar1[k0 + 4];
        mma_tf32(qa_, a0, a1, a2, a3, Qg_[k0], Qg_[k0 + 4]);
        mma_tf32(ka_, a0, a1, a2, a3, Kg_[k0], Kg_[k0 + 4]);
    }
    {
        float b0f = qkb[2 * t], b1f = qkb[2 * t + 1];
        uint32_t* qd = g_q + ((size_t)bb * HW + pix0 + m0 + g) * 8 + 2 * t;
        *(uint2*)qd = make_uint2(f2tf32(qa_[0] + b0f), f2tf32(qa_[1] + b1f));
        *(uint2*)(qd + 64) = make_uint2(f2tf32(qa_[2] + b0f), f2tf32(qa_[3] + b1f));
        float c0f = qkb[8 + 2 * t], c1f = qkb[8 + 2 * t + 1];
        uint32_t* kd = g_k + ((size_t)bb * HW + pix0 + m0 + g) * 8 + 2 * t;
        *(uint2*)kd = make_uint2(f2tf32(ka_[0] + c0f), f2tf32(ka_[1] + c1f));
        *(uint2*)(kd + 64) = make_uint2(f2tf32(ka_[2] + c0f), f2tf32(ka_[3] + c1f));
    }
    // ---- V pack (f16 pairs) into Vt[px][33] ----
#pragma unroll
    for (int nb = 0; nb < 8; ++nb) {
        int col = nb * 8 + 2 * t;
        Vt[(m0 + g) * 33 + nb * 4 + t] =
            packh(vac[nb][1] + vbs[col + 1], vac[nb][0] + vbs[col]);
        Vt[(m0 + g + 8) * 33 + nb * 4 + t] =
            packh(vac[nb][3] + vbs[col + 1], vac[nb][2] + vbs[col]);
    }
    __syncthreads();
    uint32_t* vout = g_vp + ((size_t)bb * 32 + blockIdx.x) * 4096;
#pragma unroll
    for (int i = 0; i < 16; ++i) {
        int o = tid + i * 256;
        int col = o & 3, row = (o >> 2) & 7, mat = o >> 5;
        int kpt = ((mat >> 3) << 2) | col;
        int cch = ((mat & 7) << 3) | row;
        uint32_t lo = Vt[(2 * kpt) * 33 + (cch >> 1)];
        uint32_t hi = Vt[(2 * kpt + 1) * 33 + (cch >> 1)];
        vout[o] = (cch & 1) ? ((lo >> 16) | (hi & 0xFFFF0000u))
                            : ((lo & 0xFFFFu) | (hi << 16));
    }
}

// ---------------- K3: flash attention, fp16 softmax + Z via ones-mma -------
__global__ void __launch_bounds__(256, 2) k_attn(const float* __restrict__ gamma) {
    extern __shared__ uint32_t dsh[];
    uint32_t* Qs = dsh;
    int tid = threadIdx.x;
    int br = blockIdx.y, b = blockIdx.z;
    int bb = b * NB + br;
    int n0 = blockIdx.x * 128;
    int w = tid >> 5, lane = tid & 31;
    int g = lane >> 2, t = lane & 3;

    const uint32_t* kgm = g_k + (size_t)bb * HW * 8;
    const uint32_t* vgm = g_vp + (size_t)bb * 32 * 4096;

    uint32_t shb = (uint32_t)__cvta_generic_to_shared(dsh);
    uint32_t ksa[3], vsa[3];
#pragma unroll
    for (int i = 0; i < 3; ++i) {
        ksa[i] = shb + (1024u + i * 1024u) * 4u;
        vsa[i] = shb + (4096u + i * 4096u) * 4u;
    }

    cpa16(ksa[0] + tid * 16, kgm + tid * 4);
#pragma unroll
    for (int j = 0; j < 4; ++j)
        cpa16(vsa[0] + (tid + j * 256) * 16, vgm + (tid + j * 256) * 4);
    asm volatile("cp.async.commit_group;");
    ((uint4*)Qs)[tid] = ((const uint4*)(g_q + ((size_t)bb * HW + n0) * 8))[tid];
    cpa16(ksa[1] + tid * 16, kgm + 1024 + tid * 4);
#pragma unroll
    for (int j = 0; j < 4; ++j)
        cpa16(vsa[1] + (tid + j * 256) * 16, vgm + 4096 + (tid + j * 256) * 4);
    asm volatile("cp.async.commit_group;");
    __syncthreads();

    int r0i = w * 16 + g;
    uint32_t qa0 = Qs[r0i * 8 + t];
    uint32_t qa1 = Qs[(r0i + 8) * 8 + t];
    uint32_t qa2 = Qs[r0i * 8 + t + 4];
    uint32_t qa3 = Qs[(r0i + 8) * 8 + t + 4];

    int midx = lane >> 3;
    int lane_const = (midx & 1) * 8 + (midx >> 1);
    uint32_t lboff = (uint32_t)((lane_const * 32 + (lane & 7) * 4) * 4);

    float o[8][4];
#pragma unroll
    for (int nb = 0; nb < 8; ++nb) { o[nb][0] = o[nb][1] = o[nb][2] = o[nb][3] = 0.f; }
    float zc[4] = {0.f, 0.f, 0.f, 0.f};
    const uint32_t ONES = 0x3C003C00u;   // (1.0h, 1.0h)

    int cur = 0, pf = 2;
#pragma unroll 1
    for (int it = 0; it < 32; ++it) {
        if (it < 31) asm volatile("cp.async.wait_group 1;");
        else         asm volatile("cp.async.wait_group 0;");
        __syncthreads();
        const uint32_t* Kc = dsh + 1024 + cur * 1024;
        uint32_t lb = vsa[cur] + lboff;

        uint32_t pa[16][2];
#pragma unroll
        for (int half = 0; half < 2; ++half) {
            float s[8][4];
#pragma unroll
            for (int n2 = 0; n2 < 8; ++n2) {
                int nb = half * 8 + n2;
                uint32_t b0 = Kc[(nb * 8 + g) * 8 + t];
                uint32_t b1 = Kc[(nb * 8 + g) * 8 + t + 4];
                s[n2][0] = s[n2][1] = s[n2][2] = s[n2][3] = 0.f;
                mma_tf32(s[n2], qa0, qa1, qa2, qa3, b0, b1);
            }
#pragma unroll
            for (int n2 = 0; n2 < 8; ++n2) {
                int j = half * 8 + n2;
                pa[j][0] = ex2h2(packh(s[n2][1], s[n2][0]));
                pa[j][1] = ex2h2(packh(s[n2][3], s[n2][2]));
            }
        }
#pragma unroll
        for (int ks = 0; ks < 8; ++ks) {
#pragma unroll
            for (int nbp = 0; nbp < 4; ++nbp) {
                uint32_t b00, b10, b01, b11;
                ldsm_x4(b00, b10, b01, b11, lb + (uint32_t)((16 * ks + 2 * nbp) * 128));
                mma_f16(o[2 * nbp], pa[2 * ks][0], pa[2 * ks][1],
                        pa[2 * ks + 1][0], pa[2 * ks + 1][1], b00, b10);
                mma_f16(o[2 * nbp + 1], pa[2 * ks][0], pa[2 * ks][1],
                        pa[2 * ks + 1][0], pa[2 * ks + 1][1], b01, b11);
            }
            // Z row-sums on tensor pipe (B = all ones)
            mma_f16(zc, pa[2 * ks][0], pa[2 * ks][1],
                    pa[2 * ks + 1][0], pa[2 * ks + 1][1], ONES, ONES);
        }
        if (it + 2 < 32) {
            int t2 = it + 2;
            cpa16(ksa[pf] + tid * 16, kgm + (size_t)t2 * 1024 + tid * 4);
#pragma unroll
            for (int j = 0; j < 4; ++j)
                cpa16(vsa[pf] + (tid + j * 256) * 16,
                      vgm + (size_t)t2 * 4096 + (tid + j * 256) * 4);
            asm volatile("cp.async.commit_group;");
        }
        cur = (cur == 2) ? 0 : cur + 1;
        pf = (pf == 2) ? 0 : pf + 1;
    }
    float ga = gamma[br];
    float i0 = ga / zc[0], i1 = ga / zc[2];
    float* base0 = g_fused + ((size_t)b * HW + n0 + w * 16 + g) * 256 + br * 64 + 2 * t;
    float* base1 = base0 + 8 * 256;
#pragma unroll
    for (int nb = 0; nb < 8; ++nb) {
        float2 v0 = *(float2*)(base0 + nb * 8);
        v0.x += o[nb][0] * i0; v0.y += o[nb][1] * i0;
        *(float2*)(base0 + nb * 8) = v0;
        float2 v1 = *(float2*)(base1 + nb * 8);
        v1.x += o[nb][2] * i1; v1.y += o[nb][3] * i1;
        *(float2*)(base1 + nb * 8) = v1;
    }
}

// ---------------- K4: pool, float4 channels, 4 outputs/block ---------------
template<int PS, int PLO>
__device__ __forceinline__ float4 pool_win4(int b, int oy, int ox, int c4) {
    int ys0 = oy * PS - PLO, xs0 = ox * PS - PLO;
    float4 s = make_float4(0.f, 0.f, 0.f, 0.f);
    int cnt = 0;
#pragma unroll
    for (int dy = 0; dy < PS; ++dy) {
        int yy = ys0 + dy;
        bool vy = (unsigned)yy < 64u;
        int yyc = min(max(yy, 0), 63);
#pragma unroll
        for (int dx = 0; dx < PS; ++dx) {
            int xx = xs0 + dx;
            bool v = vy && ((unsigned)xx < 64u);
            int xxc = min(max(xx, 0), 63);
            float4 val = *(const float4*)(g_fused + ((size_t)(b * HW) + yyc * 64 + xxc) * 256 + c4);
            if (v) { s.x += val.x; s.y += val.y; s.z += val.z; s.w += val.w; ++cnt; }
        }
    }
    float inv = 1.f / (float)cnt;
    s.x *= inv; s.y *= inv; s.z *= inv; s.w *= inv;
    return s;
}

__global__ void k_pool(const float* __restrict__ pw, const float* __restrict__ pb,
                       const float* __restrict__ pg, const float* __restrict__ pbe,
                       const float* __restrict__ pm, const float* __restrict__ pv) {
    __shared__ float avg[4][256];
    __shared__ float part[4][64];
    int b = blockIdx.y;
    int slot = threadIdx.x >> 6;
    int l64 = threadIdx.x & 63;
    int lin = blockIdx.x * 4 + slot;
    bool valid = lin < 1629;
    int linc = valid ? lin : 1628;
    int j, r;
    if (linc < 1024)      { j = 1; r = linc; }
    else if (linc < 1508) { j = 2; r = linc - 1024; }
    else                  { j = 3; r = linc - 1508; }
    const int HPs[4] = {64, 32, 22, 11};
    int hp = HPs[j];
    int oy = r / hp, ox = r % hp;
    int c4 = l64 * 4;
    float4 s;
    if (j == 1)      s = pool_win4<2, 0>(b, oy, ox, c4);
    else if (j == 2) s = pool_win4<3, 1>(b, oy, ox, c4);
    else             s = pool_win4<6, 1>(b, oy, ox, c4);
    *(float4*)&avg[slot][c4] = s;
    __syncthreads();
    int o = l64 & 15, q = l64 >> 4;
    const float* wp = pw + j * 4096 + o;
    float a = 0.f;
#pragma unroll 16
    for (int i = 0; i < 64; ++i) {
        int ci = q * 64 + i;
        a += avg[slot][ci] * wp[ci * 16];
    }
    part[slot][q * 16 + o] = a;
    __syncthreads();
    if (l64 < 16 && valid) {
        float acc = pb[j * 16 + l64] + part[slot][l64] + part[slot][16 + l64]
                  + part[slot][32 + l64] + part[slot][48 + l64];
        int idx = j * 16 + l64;
        float sc = pg[idx] * rsqrtf(pv[idx] + 1e-3f);
        float sh = pbe[idx] - pm[idx] * sc;
        g_pool[((size_t)((j * 2 + b) * HW) + oy * hp + ox) * 16 + l64] = acc * sc + sh;
    }
}

// ---------------- K5: proj GEMM (unchanged from R11) -----------------------
__global__ void __launch_bounds__(256) k_proj(
        const float* __restrict__ w, const float* __restrict__ pb,
        const float* __restrict__ g2, const float* __restrict__ be,
        const float* __restrict__ m, const float* __restrict__ v,
        const float* __restrict__ pplw, const float* __restrict__ pplb,
        const float* __restrict__ ppg, const float* __restrict__ ppbe,
        const float* __restrict__ ppm, const float* __restrict__ ppv,
        float* __restrict__ out) {
    extern __shared__ uint32_t dyn[];
    uint32_t* W2 = dyn + 19584;
    float* scs2 = (float*)(dyn + 23936);
    float* shs2 = (float*)(dyn + 24000);
    float* psc = (float*)(dyn + 24064);
    float* psh = (float*)(dyn + 24080);

    int tid = threadIdx.x;
    int tok0 = blockIdx.x * 64;
    int b2 = tok0 >> 12;
    int yy = (tok0 & 4095) >> 6;
    int w_ = tid >> 5, lane = tid & 31;
    int wm = w_ & 3, wn = w_ >> 2;
    int g = lane >> 2, t = lane & 3;
    int m0 = wm * 16;

    int p4 = tid >> 2, cs = (tid & 3) * 16;
    const float* asrc = g_fused + (size_t)(tok0 + p4) * 256 + cs;
    float4 ar[4];
    int wcl = tid >> 4, wco4 = (tid & 15) * 4;
    int wsc4 = wco4 + (wco4 >= 32 ? 8 : 0);
    int qcl = tid >> 2, qo4 = (tid & 3) * 4;
    int qsc4 = (qo4 < 8) ? (32 + qo4) : (64 + qo4);

#define LOADA(ck) do {                                                      \
        const float* s_ = asrc + (ck) * 64;                                 \
        ar[0] = *(const float4*)(s_);      ar[1] = *(const float4*)(s_ + 4); \
        ar[2] = *(const float4*)(s_ + 8);  ar[3] = *(const float4*)(s_ + 12); \
    } while (0)
#define STOREA(bi) do {                                                     \
        uint32_t* d_ = dyn + (bi) * 4352 + p4 * 68 + cs;                    \
        _Pragma("unroll")                                                   \
        for (int i_ = 0; i_ < 4; ++i_) {                                    \
            *(uint2*)(d_ + i_ * 4) =                                        \
                make_uint2(f2tf32(ar[i_].x), f2tf32(ar[i_].y));             \
            *(uint2*)(d_ + i_ * 4 + 2) =                                    \
                make_uint2(f2tf32(ar[i_].z), f2tf32(ar[i_].w));             \
        }                                                                   \
    } while (0)

    LOADA(0); STOREA(0);
    {
        uint32_t* Wb0 = dyn + 8704;
#pragma unroll
        for (int i = 0; i < 4; ++i) {
            int cl = wcl + i * 16;
            float4 vv = *(const float4*)(w + cl * 64 + wco4);
            Wb0[(wsc4 + 0) * 68 + cl] = f2tf32(vv.x);
            Wb0[(wsc4 + 1) * 68 + cl] = f2tf32(vv.y);
            Wb0[(wsc4 + 2) * 68 + cl] = f2tf32(vv.z);
            Wb0[(wsc4 + 3) * 68 + cl] = f2tf32(vv.w);
        }
        float4 vv = *(const float4*)(pplw + qcl * 16 + qo4);
        Wb0[(qsc4 + 0) * 68 + qcl] = f2tf32(vv.x);
        Wb0[(qsc4 + 1) * 68 + qcl] = f2tf32(vv.y);
        Wb0[(qsc4 + 2) * 68 + qcl] = f2tf32(vv.z);
        Wb0[(qsc4 + 3) * 68 + qcl] = f2tf32(vv.w);
    }
#pragma unroll
    for (int i = 0; i < 4; ++i) {
        int id = tid + i * 256;
        int k = id >> 4, co4 = (id & 15) * 4;
        float4 vv = *(const float4*)(w + (256 + k) * 64 + co4);
        W2[(co4 + 0) * 68 + k] = f2tf32(vv.x);
        W2[(co4 + 1) * 68 + k] = f2tf32(vv.y);
        W2[(co4 + 2) * 68 + k] = f2tf32(vv.z);
        W2[(co4 + 3) * 68 + k] = f2tf32(vv.w);
    }
    if (tid < 64) {
        float sc = g2[tid] * rsqrtf(v[tid] + 1e-3f);
        scs2[tid] = sc;
        shs2[tid] = be[tid] - m[tid] * sc + pb[tid] * sc;
    } else if (tid < 80) {
        int o = tid - 64;
        float sc = ppg[o] * rsqrtf(ppv[o] + 1e-3f);
        psc[o] = sc;
        psh[o] = ppbe[o] - ppm[o] * sc + pplb[o] * sc;
    }
    LOADA(1);
    __syncthreads();

    float a1c[5][4];
#pragma unroll
    for (int nb = 0; nb < 5; ++nb) a1c[nb][0] = a1c[nb][1] = a1c[nb][2] = a1c[nb][3] = 0.f;
    int wn40 = wn * 40;
#pragma unroll 1
    for (int ck = 0; ck < 4; ++ck) {
        float4 wrp[4], wrq;
        if (ck + 1 < 4) {
            int cb = (ck + 1) * 64;
#pragma unroll
            for (int i = 0; i < 4; ++i)
                wrp[i] = *(const float4*)(w + (cb + wcl + i * 16) * 64 + wco4);
            wrq = *(const float4*)(pplw + (cb + qcl) * 16 + qo4);
        }
        const uint32_t* Ab = dyn + (ck & 1) * 4352;
        const uint32_t* Ar0 = Ab + (m0 + g) * 68 + t;
        const uint32_t* Ar1 = Ab + (m0 + g + 8) * 68 + t;
        const uint32_t* Wc = dyn + 8704 + (ck & 1) * 5440 + (wn40 + g) * 68 + t;
#pragma unroll
        for (int k0 = 0; k0 < 64; k0 += 8) {
            uint32_t a0 = Ar0[k0], a1 = Ar1[k0];
            uint32_t a2 = Ar0[k0 + 4], a3 = Ar1[k0 + 4];
#pragma unroll
            for (int nb = 0; nb < 5; ++nb)
                mma_tf32(a1c[nb], a0, a1, a2, a3,
                         Wc[nb * 544 + k0], Wc[nb * 544 + k0 + 4]);
        }
        if (ck + 1 < 4) {
            uint32_t* Wn = dyn + 8704 + ((ck + 1) & 1) * 5440;
#pragma unroll
            for (int i = 0; i < 4; ++i) {
                int cl = wcl + i * 16;
                Wn[(wsc4 + 0) * 68 + cl] = f2tf32(wrp[i].x);
                Wn[(wsc4 + 1) * 68 + cl] = f2tf32(wrp[i].y);
                Wn[(wsc4 + 2) * 68 + cl] = f2tf32(wrp[i].z);
                Wn[(wsc4 + 3) * 68 + cl] = f2tf32(wrp[i].w);
            }
            Wn[(qsc4 + 0) * 68 + qcl] = f2tf32(wrq.x);
            Wn[(qsc4 + 1) * 68 + qcl] = f2tf32(wrq.y);
            Wn[(qsc4 + 2) * 68 + qcl] = f2tf32(wrq.z);
            Wn[(qsc4 + 3) * 68 + qcl] = f2tf32(wrq.w);
            STOREA((ck + 1) & 1);
        }
        __syncthreads();
        if (ck + 2 < 4) LOADA(ck + 2);
    }
#undef LOADA
#undef STOREA

    uint32_t* X2 = dyn;
    {
        int o = wn * 8 + 2 * t;
        float s0 = psc[o], s1 = psc[o + 1], h0 = psh[o], h1 = psh[o + 1];
        *(uint2*)&X2[(m0 + g) * 68 + o] =
            make_uint2(f2tf32(a1c[4][0] * s0 + h0), f2tf32(a1c[4][1] * s1 + h1));
        *(uint2*)&X2[(m0 + g + 8) * 68 + o] =
            make_uint2(f2tf32(a1c[4][2] * s0 + h0), f2tf32(a1c[4][3] * s1 + h1));
    }
    {
        const int HP[3] = {32, 22, 11};
#pragma unroll
        for (int lvl = 0; lvl < 3; ++lvl) {
            int hp = HP[lvl];
            float scale = hp * (1.f / 64.f);
            const float* P0 = g_pool + (size_t)(((lvl + 1) * 2 + b2) * HW) * 16;
            float fy = (yy + 0.5f) * scale - 0.5f;
            float y0f = floorf(fy);
            float ty = fy - y0f;
            int yA = min(max((int)y0f, 0), hp - 1);
            int yB = min(max((int)y0f + 1, 0), hp - 1);
#pragma unroll
            for (int i = 0; i < 4; ++i) {
                int id = tid + i * 256;
                int px = id >> 4, c = id & 15;
                float fx = (px + 0.5f) * scale - 0.5f;
                float x0f = floorf(fx);
                float tx = fx - x0f;
                int xA = min(max((int)x0f, 0), hp - 1);
                int xB = min(max((int)x0f + 1, 0), hp - 1);
                const float* P = P0 + c;
                float v00 = P[(yA * hp + xA) * 16], v01 = P[(yA * hp + xB) * 16];
                float v10 = P[(yB * hp + xA) * 16], v11 = P[(yB * hp + xB) * 16];
                float val = (1.f - ty) * ((1.f - tx) * v00 + tx * v01)
                          + ty * ((1.f - tx) * v10 + tx * v11);
                X2[px * 68 + 16 + lvl * 16 + c] = f2tf32(val);
            }
        }
    }
    __syncthreads();

    float a2c[4][4];
#pragma unroll
    for (int nb = 0; nb < 4; ++nb) a2c[nb][0] = a2c[nb][1] = a2c[nb][2] = a2c[nb][3] = 0.f;
    {
        const uint32_t* Ar0 = X2 + (m0 + g) * 68 + t;
        const uint32_t* Ar1 = X2 + (m0 + g + 8) * 68 + t;
        const uint32_t* Wc = W2 + (wn * 32 + g) * 68 + t;
#pragma unroll
        for (int k0 = 0; k0 < 64; k0 += 8) {
            uint32_t a0 = Ar0[k0], a1 = Ar1[k0];
            uint32_t a2 = Ar0[k0 + 4], a3 = Ar1[k0 + 4];
#pragma unroll
            for (int nb = 0; nb < 4; ++nb)
                mma_tf32(a2c[nb], a0, a1, a2, a3,
                         Wc[nb * 544 + k0], Wc[nb * 544 + k0 + 4]);
        }
    }
    float* o0 = out + (size_t)(tok0 + m0 + g) * 64;
    float* o1 = o0 + 8 * 64;
#pragma unroll
    for (int nb = 0; nb < 4; ++nb) {
        int col = wn * 32 + nb * 8 + 2 * t;
        float s0 = scs2[col], s1 = scs2[col + 1];
        float h0 = shs2[col], h1 = shs2[col + 1];
        float2 r0, r1;
        r0.x = fmaxf((a1c[nb][0] + a2c[nb][0]) * s0 + h0, 0.f);
        r0.y = fmaxf((a1c[nb][1] + a2c[nb][1]) * s1 + h1, 0.f);
        r1.x = fmaxf((a1c[nb][2] + a2c[nb][2]) * s0 + h0, 0.f);
        r1.y = fmaxf((a1c[nb][3] + a2c[nb][3]) * s1 + h1, 0.f);
        *(float2*)(o0 + col) = r0;
        *(float2*)(o1 + col) = r1;
    }
}

// ---------------- launch ---------------------------------------------------
extern "C" void kernel_launch(void* const* d_in, const int* in_sizes, int n_in,
                              void* d_out, int out_size) {
    const float* x       = (const float*)d_in[0];
    const float* conv_w  = (const float*)d_in[1];
    const float* conv_b  = (const float*)d_in[2];
    const float* bn_g    = (const float*)d_in[3];
    const float* bn_b    = (const float*)d_in[4];
    const float* bn_m    = (const float*)d_in[5];
    const float* bn_v    = (const float*)d_in[6];
    const float* q_w     = (const float*)d_in[7];
    const float* q_b     = (const float*)d_in[8];
    const float* k_w     = (const float*)d_in[9];
    const float* k_b     = (const float*)d_in[10];
    const float* v_w     = (const float*)d_in[11];
    const float* v_b     = (const float*)d_in[12];
    const float* attn_g  = (const float*)d_in[13];
    const float* ppl_w   = (const float*)d_in[14];
    const float* ppl_b   = (const float*)d_in[15];
    const float* ppl_bng = (const float*)d_in[16];
    const float* ppl_bnb = (const float*)d_in[17];
    const float* ppl_bnm = (const float*)d_in[18];
    const float* ppl_bnv = (const float*)d_in[19];
    const float* proj_w  = (const float*)d_in[20];
    const float* proj_b  = (const float*)d_in[21];
    const float* pbn_g   = (const float*)d_in[22];
    const float* pbn_b   = (const float*)d_in[23];
    const float* pbn_m   = (const float*)d_in[24];
    const float* pbn_v   = (const float*)d_in[25];
    float* out = (float*)d_out;

    const int CONV_SMEM = 26240 * 4;   // 104,960 B
    const int ATTN_SMEM = 16384 * 4;   // 65,536 B
    const int PROJ_SMEM = 24096 * 4;   // 96,384 B
    cudaFuncSetAttribute(k_conv, cudaFuncAttributeMaxDynamicSharedMemorySize, CONV_SMEM);
    cudaFuncSetAttribute(k_attn, cudaFuncAttributeMaxDynamicSharedMemorySize, ATTN_SMEM);
    cudaFuncSetAttribute(k_proj, cudaFuncAttributeMaxDynamicSharedMemorySize, PROJ_SMEM);

    k_conv<<<dim3(32, 8), 256, CONV_SMEM>>>(x, conv_w, conv_b, bn_g, bn_b, bn_m, bn_v,
                                            q_w, q_b, k_w, k_b, v_w, v_b);
    k_attn<<<dim3(32, 4, 2), 256, ATTN_SMEM>>>(attn_g);
    k_pool<<<dim3(408, 2), 256>>>(ppl_w, ppl_b, ppl_bng, ppl_bnb, ppl_bnm, ppl_bnv);
    k_proj<<<128, 256, PROJ_SMEM>>>(proj_w, proj_b, pbn_g, pbn_b, pbn_m, pbn_v,
                                    ppl_w, ppl_b, ppl_bng, ppl_bnb, ppl_bnm, ppl_bnv, out);
}

// round 14
// speedup vs baseline: 1.2448x; 1.0211x over previous
#include <cuda_runtime.h>
#include <cuda_bf16.h>
#include <math.h>
#include <stdint.h>

#define NB 4
#define BATCH 2
#define HW 4096
#define F 64
#define LOG2E 1.4426950408889634f

// ---------------- scratch (device globals; no allocation allowed) ----------
__device__ float    g_fused[BATCH * HW * 256];
__device__ uint32_t g_q[BATCH * NB * HW * 4];       // f16x2 pairs [pos][4]
__device__ uint32_t g_k[BATCH * NB * HW * 4];       // f16x2 pairs
__device__ uint32_t g_vp[BATCH * NB * 32 * 4096];   // f16x2 pairs, ldmatrix order
__device__ float    g_pool[NB * BATCH * HW * 16];

// ---------------- helpers ---------------------------------------------------
__device__ __forceinline__ uint32_t f2tf32(float f) {
    uint32_t r; asm("cvt.rna.tf32.f32 %0, %1;" : "=r"(r) : "f"(f)); return r;
}
__device__ __forceinline__ uint32_t packh(float hi, float lo) {
    uint32_t r; asm("cvt.rn.f16x2.f32 %0, %1, %2;" : "=r"(r) : "f"(hi), "f"(lo)); return r;
}
__device__ __forceinline__ uint32_t ex2h2(uint32_t x) {
    uint32_t y; asm("ex2.approx.f16x2 %0, %1;" : "=r"(y) : "r"(x)); return y;
}
__device__ __forceinline__ void mma_tf32(float c[4], uint32_t a0, uint32_t a1,
                                         uint32_t a2, uint32_t a3,
                                         uint32_t b0, uint32_t b1) {
    asm volatile(
        "mma.sync.aligned.m16n8k8.row.col.f32.tf32.tf32.f32 "
        "{%0,%1,%2,%3},{%4,%5,%6,%7},{%8,%9},{%0,%1,%2,%3};"
        : "+f"(c[0]), "+f"(c[1]), "+f"(c[2]), "+f"(c[3])
        : "r"(a0), "r"(a1), "r"(a2), "r"(a3), "r"(b0), "r"(b1));
}
__device__ __forceinline__ void mma_f16(float c[4], uint32_t a0, uint32_t a1,
                                        uint32_t a2, uint32_t a3,
                                        uint32_t b0, uint32_t b1) {
    asm volatile(
        "mma.sync.aligned.m16n8k16.row.col.f32.f16.f16.f32 "
        "{%0,%1,%2,%3},{%4,%5,%6,%7},{%8,%9},{%0,%1,%2,%3};"
        : "+f"(c[0]), "+f"(c[1]), "+f"(c[2]), "+f"(c[3])
        : "r"(a0), "r"(a1), "r"(a2), "r"(a3), "r"(b0), "r"(b1));
}
__device__ __forceinline__ void mma_f16k8(float c[4], uint32_t a0, uint32_t a1,
                                          uint32_t b0) {
    asm volatile(
        "mma.sync.aligned.m16n8k8.row.col.f32.f16.f16.f32 "
        "{%0,%1,%2,%3},{%4,%5},{%6},{%0,%1,%2,%3};"
        : "+f"(c[0]), "+f"(c[1]), "+f"(c[2]), "+f"(c[3])
        : "r"(a0), "r"(a1), "r"(b0));
}
__device__ __forceinline__ void ldsm_x4(uint32_t& r0, uint32_t& r1,
                                        uint32_t& r2, uint32_t& r3, uint32_t addr) {
    asm volatile("ldmatrix.sync.aligned.m8n8.x4.shared.b16 {%0,%1,%2,%3}, [%4];"
        : "=r"(r0), "=r"(r1), "=r"(r2), "=r"(r3) : "r"(addr));
}
__device__ __forceinline__ void cpa16(uint32_t s, const void* g) {
    asm volatile("cp.async.cg.shared.global [%0], [%1], 16;" :: "r"(s), "l"(g));
}
__device__ __forceinline__ void cpa16z(uint32_t s, const void* g, int sz) {
    asm volatile("cp.async.cg.shared.global [%0], [%1], 16, %2;" :: "r"(s), "l"(g), "r"(sz));
}

// ---------------- K1: dilated conv + fused QKV --------------------------
__global__ void __launch_bounds__(256, 2) k_conv(
        const float* __restrict__ x, const float* __restrict__ wg,
        const float* __restrict__ cb, const float* __restrict__ bg,
        const float* __restrict__ bbe, const float* __restrict__ bm,
        const float* __restrict__ bv,
        const float* __restrict__ qw, const float* __restrict__ qb,
        const float* __restrict__ kw, const float* __restrict__ kb_,
        const float* __restrict__ vw, const float* __restrict__ vb) {
    extern __shared__ uint32_t dyn[];
    uint32_t* Vt = dyn + 8704;
    uint32_t* QW = dyn + 12928;
    uint32_t* KW = dyn + 13472;
    float* vbs = (float*)(dyn + 14016);
    float* qkb = (float*)(dyn + 14080);
    float* scs = (float*)(dyn + 26112);
    float* shs = (float*)(dyn + 26176);

    int tid = threadIdx.x;
    int bb = blockIdx.y, b = bb >> 2, br = bb & 3;
    int d = 1 << br;
    int pix0 = blockIdx.x * 128;
    int y0 = blockIdx.x * 2;

    if (tid < 64) {
        int idx = br * 64 + tid;
        float sc = bg[idx] * rsqrtf(bv[idx] + 1e-3f);
        scs[tid] = sc;
        shs[tid] = bbe[idx] - bm[idx] * sc + cb[idx] * sc;
    }

    int w = tid >> 5, lane = tid & 31;
    int g = lane >> 2, t = lane & 3;
    int m0 = w * 16;

    float c[8][4];
#pragma unroll
    for (int nb = 0; nb < 8; ++nb) c[nb][0] = c[nb][1] = c[nb][2] = c[nb][3] = 0.f;

    int p = tid >> 1, ch = (tid & 1) * 32;
    int prow = p >> 6, pcol = p & 63;
    int wci0 = tid >> 4, wco4 = (tid & 15) * 4;

    uint32_t sh0 = (uint32_t)__cvta_generic_to_shared(dyn);
    uint32_t a_dst0 = sh0 + (uint32_t)((p * 68 + ch) * 4);
    const float* xb = x + (size_t)b * 64 * 64 * 64;
    const float* wbase = wg + (size_t)br * 9 * 4096;

#define PREFETCH_A(tap, bi) do {                                             \
        int ky_ = (tap) / 3, kx_ = (tap) - ky_ * 3;                          \
        int iy_ = y0 + prow + d * (ky_ - 1);                                 \
        int ix_ = pcol + d * (kx_ - 1);                                      \
        int val_ = (((unsigned)iy_ < 64u) & ((unsigned)ix_ < 64u)) ? 16 : 0; \
        int iyc_ = min(max(iy_, 0), 63), ixc_ = min(max(ix_, 0), 63);        \
        const float* asrc_ = xb + (((size_t)iyc_ * 64 + ixc_) * 64 + ch);    \
        uint32_t ad_ = a_dst0 + (uint32_t)(bi) * 34816u;                     \
        _Pragma("unroll")                                                    \
        for (int i_ = 0; i_ < 8; ++i_) cpa16z(ad_ + i_ * 16, asrc_ + i_ * 4, val_); \
        asm volatile("cp.async.commit_group;");                              \
    } while (0)

    PREFETCH_A(0, 0);
    PREFETCH_A(1, 1);
    {
        uint32_t* W0 = dyn + 17408;
#pragma unroll
        for (int i = 0; i < 4; ++i) {
            int ci = wci0 + i * 16;
            float4 v = *(const float4*)(wbase + ci * 64 + wco4);
            W0[(wco4 + 0) * 68 + ci] = f2tf32(v.x);
            W0[(wco4 + 1) * 68 + ci] = f2tf32(v.y);
            W0[(wco4 + 2) * 68 + ci] = f2tf32(v.z);
            W0[(wco4 + 3) * 68 + ci] = f2tf32(v.w);
        }
    }
    asm volatile("cp.async.wait_group 1;");
    __syncthreads();

#pragma unroll 1
    for (int tap = 0; tap < 9; ++tap) {
        float4 wr[4];
        if (tap + 1 < 9) {
            const float* wt1 = wbase + (size_t)(tap + 1) * 4096;
#pragma unroll
            for (int i = 0; i < 4; ++i)
                wr[i] = *(const float4*)(wt1 + (wci0 + i * 16) * 64 + wco4);
        }
        const uint32_t* Ab = dyn + (tap & 1) * 8704;
        const uint32_t* Wb = dyn + 17408 + (tap & 1) * 4352;
        const uint32_t* Ar0 = Ab + (m0 + g) * 68 + t;
        const uint32_t* Ar1 = Ab + (m0 + g + 8) * 68 + t;
        const uint32_t* Wg_ = Wb + g * 68 + t;
#pragma unroll
        for (int k0 = 0; k0 < 64; k0 += 8) {
            uint32_t a0 = Ar0[k0], a1 = Ar1[k0];
            uint32_t a2 = Ar0[k0 + 4], a3 = Ar1[k0 + 4];
#pragma unroll
            for (int nb = 0; nb < 8; ++nb)
                mma_tf32(c[nb], a0, a1, a2, a3,
                         Wg_[nb * 8 * 68 + k0], Wg_[nb * 8 * 68 + k0 + 4]);
        }
        if (tap + 1 < 9) {
            uint32_t* Wn = dyn + 17408 + ((tap + 1) & 1) * 4352;
#pragma unroll
            for (int i = 0; i < 4; ++i) {
                int ci = wci0 + i * 16;
                Wn[(wco4 + 0) * 68 + ci] = f2tf32(wr[i].x);
                Wn[(wco4 + 1) * 68 + ci] = f2tf32(wr[i].y);
                Wn[(wco4 + 2) * 68 + ci] = f2tf32(wr[i].z);
                Wn[(wco4 + 3) * 68 + ci] = f2tf32(wr[i].w);
            }
        }
        __syncthreads();
        if (tap + 2 < 9) {
            PREFETCH_A(tap + 2, (tap & 1));
            asm volatile("cp.async.wait_group 1;");
            __syncthreads();
        } else if (tap + 1 < 9) {
            asm volatile("cp.async.wait_group 0;");
            __syncthreads();
        }
    }
#undef PREFETCH_A

    float rv[8][4];
    float* f0 = g_fused + ((size_t)b * HW + pix0 + m0 + g) * 256 + br * 64;
    float* f1 = f0 + 8 * 256;
#pragma unroll
    for (int nb = 0; nb < 8; ++nb) {
        int col = nb * 8 + 2 * t;
        rv[nb][0] = fmaxf(c[nb][0] * scs[col] + shs[col], 0.f);
        rv[nb][1] = fmaxf(c[nb][1] * scs[col + 1] + shs[col + 1], 0.f);
        rv[nb][2] = fmaxf(c[nb][2] * scs[col] + shs[col], 0.f);
        rv[nb][3] = fmaxf(c[nb][3] * scs[col + 1] + shs[col + 1], 0.f);
        *(float2*)(f0 + col) = make_float2(rv[nb][0], rv[nb][1]);
        *(float2*)(f1 + col) = make_float2(rv[nb][2], rv[nb][3]);
    }
    __syncthreads();
    uint32_t* As = dyn;
#pragma unroll
    for (int nb = 0; nb < 8; ++nb) {
        int col = nb * 8 + 2 * t;
        *(uint2*)&As[(m0 + g) * 68 + col] =
            make_uint2(f2tf32(rv[nb][0]), f2tf32(rv[nb][1]));
        *(uint2*)&As[(m0 + g + 8) * 68 + col] =
            make_uint2(f2tf32(rv[nb][2]), f2tf32(rv[nb][3]));
    }
    uint32_t* Wv = dyn + 17408;
#pragma unroll
    for (int i = 0; i < 4; ++i) {
        int ci = wci0 + i * 16;
        float4 v = *(const float4*)(vw + br * 4096 + ci * 64 + wco4);
        Wv[(wco4 + 0) * 68 + ci] = f2tf32(v.x);
        Wv[(wco4 + 1) * 68 + ci] = f2tf32(v.y);
        Wv[(wco4 + 2) * 68 + ci] = f2tf32(v.z);
        Wv[(wco4 + 3) * 68 + ci] = f2tf32(v.w);
    }
    if (tid < 128) {
        int ci = tid >> 1, d4 = (tid & 1) * 4;
        float4 v = *(const float4*)(qw + br * 512 + ci * 8 + d4);
        QW[(d4 + 0) * 68 + ci] = f2tf32(v.x * LOG2E);
        QW[(d4 + 1) * 68 + ci] = f2tf32(v.y * LOG2E);
        QW[(d4 + 2) * 68 + ci] = f2tf32(v.z * LOG2E);
        QW[(d4 + 3) * 68 + ci] = f2tf32(v.w * LOG2E);
    } else {
        int id = tid - 128;
        int ci = id >> 1, d4 = (id & 1) * 4;
        float4 v = *(const float4*)(kw + br * 512 + ci * 8 + d4);
        KW[(d4 + 0) * 68 + ci] = f2tf32(v.x);
        KW[(d4 + 1) * 68 + ci] = f2tf32(v.y);
        KW[(d4 + 2) * 68 + ci] = f2tf32(v.z);
        KW[(d4 + 3) * 68 + ci] = f2tf32(v.w);
    }
    if (tid < 64) vbs[tid] = vb[br * 64 + tid];
    if (tid >= 64 && tid < 72) qkb[tid - 64] = qb[br * 8 + tid - 64] * LOG2E;
    if (tid >= 72 && tid < 80) qkb[8 + tid - 72] = kb_[br * 8 + tid - 72];
    __syncthreads();
    const uint32_t* Ar0 = As + (m0 + g) * 68 + t;
    const uint32_t* Ar1 = As + (m0 + g + 8) * 68 + t;
    const uint32_t* Wg_ = Wv + g * 68 + t;
    float vac[8][4];
#pragma unroll
    for (int nb = 0; nb < 8; ++nb) vac[nb][0] = vac[nb][1] = vac[nb][2] = vac[nb][3] = 0.f;
#pragma unroll
    for (int k0 = 0; k0 < 64; k0 += 8) {
        uint32_t a0 = Ar0[k0], a1 = Ar1[k0];
        uint32_t a2 = Ar0[k0 + 4], a3 = Ar1[k0 + 4];
#pragma unroll
        for (int nb = 0; nb < 8; ++nb)
            mma_tf32(vac[nb], a0, a1, a2, a3, Wg_[nb * 8 * 68 + k0], Wg_[nb * 8 * 68 + k0 + 4]);
    }
    float qa_[4] = {0.f, 0.f, 0.f, 0.f}, ka_[4] = {0.f, 0.f, 0.f, 0.f};
    const uint32_t* Qg_ = QW + g * 68 + t;
    const uint32_t* Kg_ = KW + g * 68 + t;
#pragma unroll
    for (int k0 = 0; k0 < 64; k0 += 8) {
        uint32_t a0 = Ar0[k0], a1 = Ar1[k0];
        uint32_t a2 = Ar0[k0 + 4], a3 = Ar1[k0 + 4];
        mma_tf32(qa_, a0, a1, a2, a3, Qg_[k0], Qg_[k0 + 4]);
        mma_tf32(ka_, a0, a1, a2, a3, Kg_[k0], Kg_[k0 + 4]);
    }
    {
        float b0f = qkb[2 * t], b1f = qkb[2 * t + 1];
        uint32_t* qd = g_q + ((size_t)bb * HW + pix0 + m0 + g) * 4 + t;
        qd[0]  = packh(qa_[1] + b1f, qa_[0] + b0f);
        qd[32] = packh(qa_[3] + b1f, qa_[2] + b0f);
        float c0f = qkb[8 + 2 * t], c1f = qkb[8 + 2 * t + 1];
        uint32_t* kd = g_k + ((size_t)bb * HW + pix0 + m0 + g) * 4 + t;
        kd[0]  = packh(ka_[1] + c1f, ka_[0] + c0f);
        kd[32] = packh(ka_[3] + c1f, ka_[2] + c0f);
    }
    // ---- V pack (f16 pairs) into Vt[px][33] ----
#pragma unroll
    for (int nb = 0; nb < 8; ++nb) {
        int col = nb * 8 + 2 * t;
        Vt[(m0 + g) * 33 + nb * 4 + t] =
            packh(vac[nb][1] + vbs[col + 1], vac[nb][0] + vbs[col]);
        Vt[(m0 + g + 8) * 33 + nb * 4 + t] =
            packh(vac[nb][3] + vbs[col + 1], vac[nb][2] + vbs[col]);
    }
    __syncthreads();
    uint32_t* vout = g_vp + ((size_t)bb * 32 + blockIdx.x) * 4096;
#pragma unroll
    for (int i = 0; i < 16; ++i) {
        int o = tid + i * 256;
        int col = o & 3, row = (o >> 2) & 7, mat = o >> 5;
        int kpt = ((mat >> 3) << 2) | col;
        int cch = ((mat & 7) << 3) | row;
        uint32_t lo = Vt[(2 * kpt) * 33 + (cch >> 1)];
        uint32_t hi = Vt[(2 * kpt + 1) * 33 + (cch >> 1)];
        vout[o] = (cch & 1) ? ((lo >> 16) | (hi & 0xFFFF0000u))
                            : ((lo & 0xFFFFu) | (hi << 16));
    }
}

// ---------------- K3: flash attention, all-fp16 operands -------------------
// dyn smem (words): Qs @0 (512), Ks @512 (3x512), Vs @2048 (3x4096) = 14336
__global__ void __launch_bounds__(256, 2) k_attn(const float* __restrict__ gamma) {
    extern __shared__ uint32_t dsh[];
    uint32_t* Qs = dsh;
    int tid = threadIdx.x;
    int br = blockIdx.y, b = blockIdx.z;
    int bb = b * NB + br;
    int n0 = blockIdx.x * 128;
    int w = tid >> 5, lane = tid & 31;
    int g = lane >> 2, t = lane & 3;

    const uint32_t* kgm = g_k + (size_t)bb * HW * 4;
    const uint32_t* vgm = g_vp + (size_t)bb * 32 * 4096;

    uint32_t shb = (uint32_t)__cvta_generic_to_shared(dsh);
    uint32_t ksa[3], vsa[3];
#pragma unroll
    for (int i = 0; i < 3; ++i) {
        ksa[i] = shb + (512u + i * 512u) * 4u;
        vsa[i] = shb + (2048u + i * 4096u) * 4u;
    }

    if (tid < 128) cpa16(ksa[0] + tid * 16, kgm + tid * 4);
#pragma unroll
    for (int j = 0; j < 4; ++j)
        cpa16(vsa[0] + (tid + j * 256) * 16, vgm + (tid + j * 256) * 4);
    asm volatile("cp.async.commit_group;");
    if (tid < 128)
        ((uint4*)Qs)[tid] = ((const uint4*)(g_q + ((size_t)bb * HW + n0) * 4))[tid];
    if (tid < 128) cpa16(ksa[1] + tid * 16, kgm + 512 + tid * 4);
#pragma unroll
    for (int j = 0; j < 4; ++j)
        cpa16(vsa[1] + (tid + j * 256) * 16, vgm + 4096 + (tid + j * 256) * 4);
    asm volatile("cp.async.commit_group;");
    __syncthreads();

    int r0i = w * 16 + g;
    uint32_t qa0 = Qs[r0i * 4 + t];
    uint32_t qa1 = Qs[(r0i + 8) * 4 + t];

    int midx = lane >> 3;
    int lane_const = (midx & 1) * 8 + (midx >> 1);
    uint32_t lboff = (uint32_t)((lane_const * 32 + (lane & 7) * 4) * 4);

    float o[8][4];
#pragma unroll
    for (int nb = 0; nb < 8; ++nb) { o[nb][0] = o[nb][1] = o[nb][2] = o[nb][3] = 0.f; }
    float zc[4] = {0.f, 0.f, 0.f, 0.f};
    const uint32_t ONES = 0x3C003C00u;

    int cur = 0, pf = 2;
#pragma unroll 1
    for (int it = 0; it < 32; ++it) {
        if (it < 31) asm volatile("cp.async.wait_group 1;");
        else         asm volatile("cp.async.wait_group 0;");
        __syncthreads();
        const uint32_t* Kc = dsh + 512 + cur * 512;
        uint32_t lb = vsa[cur] + lboff;

        uint32_t pa[16][2];
#pragma unroll
        for (int half = 0; half < 2; ++half) {
            float s[8][4];
#pragma unroll
            for (int n2 = 0; n2 < 8; ++n2) {
                int nb = half * 8 + n2;
                uint32_t b0 = Kc[(nb * 8 + g) * 4 + t];
                s[n2][0] = s[n2][1] = s[n2][2] = s[n2][3] = 0.f;
                mma_f16k8(s[n2], qa0, qa1, b0);
            }
#pragma unroll
            for (int n2 = 0; n2 < 8; ++n2) {
                int j = half * 8 + n2;
                pa[j][0] = ex2h2(packh(s[n2][1], s[n2][0]));
                pa[j][1] = ex2h2(packh(s[n2][3], s[n2][2]));
            }
        }
#pragma unroll
        for (int ks = 0; ks < 8; ++ks) {
#pragma unroll
            for (int nbp = 0; nbp < 4; ++nbp) {
                uint32_t b00, b10, b01, b11;
                ldsm_x4(b00, b10, b01, b11, lb + (uint32_t)((16 * ks + 2 * nbp) * 128));
                mma_f16(o[2 * nbp], pa[2 * ks][0], pa[2 * ks][1],
                        pa[2 * ks + 1][0], pa[2 * ks + 1][1], b00, b10);
                mma_f16(o[2 * nbp + 1], pa[2 * ks][0], pa[2 * ks][1],
                        pa[2 * ks + 1][0], pa[2 * ks + 1][1], b01, b11);
            }
            mma_f16(zc, pa[2 * ks][0], pa[2 * ks][1],
                    pa[2 * ks + 1][0], pa[2 * ks + 1][1], ONES, ONES);
        }
        if (it + 2 < 32) {
            int t2 = it + 2;
            if (tid < 128) cpa16(ksa[pf] + tid * 16, kgm + (size_t)t2 * 512 + tid * 4);
#pragma unroll
            for (int j = 0; j < 4; ++j)
                cpa16(vsa[pf] + (tid + j * 256) * 16,
                      vgm + (size_t)t2 * 4096 + (tid + j * 256) * 4);
            asm volatile("cp.async.commit_group;");
        }
        cur = (cur == 2) ? 0 : cur + 1;
        pf = (pf == 2) ? 0 : pf + 1;
    }
    float ga = gamma[br];
    float i0 = ga / zc[0], i1 = ga / zc[2];
    float* base0 = g_fused + ((size_t)b * HW + n0 + w * 16 + g) * 256 + br * 64 + 2 * t;
    float* base1 = base0 + 8 * 256;
#pragma unroll
    for (int nb = 0; nb < 8; ++nb) {
        float2 v0 = *(float2*)(base0 + nb * 8);
        v0.x += o[nb][0] * i0; v0.y += o[nb][1] * i0;
        *(float2*)(base0 + nb * 8) = v0;
        float2 v1 = *(float2*)(base1 + nb * 8);
        v1.x += o[nb][2] * i1; v1.y += o[nb][3] * i1;
        *(float2*)(base1 + nb * 8) = v1;
    }
}

// ---------------- K4: pool, float4 channels, 4 outputs/block ---------------
template<int PS, int PLO>
__device__ __forceinline__ float4 pool_win4(int b, int oy, int ox, int c4) {
    int ys0 = oy * PS - PLO, xs0 = ox * PS - PLO;
    float4 s = make_float4(0.f, 0.f, 0.f, 0.f);
    int cnt = 0;
#pragma unroll
    for (int dy = 0; dy < PS; ++dy) {
        int yy = ys0 + dy;
        bool vy = (unsigned)yy < 64u;
        int yyc = min(max(yy, 0), 63);
#pragma unroll
        for (int dx = 0; dx < PS; ++dx) {
            int xx = xs0 + dx;
            bool v = vy && ((unsigned)xx < 64u);
            int xxc = min(max(xx, 0), 63);
            float4 val = *(const float4*)(g_fused + ((size_t)(b * HW) + yyc * 64 + xxc) * 256 + c4);
            if (v) { s.x += val.x; s.y += val.y; s.z += val.z; s.w += val.w; ++cnt; }
        }
    }
    float inv = 1.f / (float)cnt;
    s.x *= inv; s.y *= inv; s.z *= inv; s.w *= inv;
    return s;
}

__global__ void k_pool(const float* __restrict__ pw, const float* __restrict__ pb,
                       const float* __restrict__ pg, const float* __restrict__ pbe,
                       const float* __restrict__ pm, const float* __restrict__ pv) {
    __shared__ float avg[4][256];
    __shared__ float part[4][64];
    int b = blockIdx.y;
    int slot = threadIdx.x >> 6;
    int l64 = threadIdx.x & 63;
    int lin = blockIdx.x * 4 + slot;
    bool valid = lin < 1629;
    int linc = valid ? lin : 1628;
    int j, r;
    if (linc < 1024)      { j = 1; r = linc; }
    else if (linc < 1508) { j = 2; r = linc - 1024; }
    else                  { j = 3; r = linc - 1508; }
    const int HPs[4] = {64, 32, 22, 11};
    int hp = HPs[j];
    int oy = r / hp, ox = r % hp;
    int c4 = l64 * 4;
    float4 s;
    if (j == 1)      s = pool_win4<2, 0>(b, oy, ox, c4);
    else if (j == 2) s = pool_win4<3, 1>(b, oy, ox, c4);
    else             s = pool_win4<6, 1>(b, oy, ox, c4);
    *(float4*)&avg[slot][c4] = s;
    __syncthreads();
    int o = l64 & 15, q = l64 >> 4;
    const float* wp = pw + j * 4096 + o;
    float a = 0.f;
#pragma unroll 16
    for (int i = 0; i < 64; ++i) {
        int ci = q * 64 + i;
        a += avg[slot][ci] * wp[ci * 16];
    }
    part[slot][q * 16 + o] = a;
    __syncthreads();
    if (l64 < 16 && valid) {
        float acc = pb[j * 16 + l64] + part[slot][l64] + part[slot][16 + l64]
                  + part[slot][32 + l64] + part[slot][48 + l64];
        int idx = j * 16 + l64;
        float sc = pg[idx] * rsqrtf(pv[idx] + 1e-3f);
        float sh = pbe[idx] - pm[idx] * sc;
        g_pool[((size_t)((j * 2 + b) * HW) + oy * hp + ox) * 16 + l64] = acc * sc + sh;
    }
}

// ---------------- K5: proj GEMM (unchanged) --------------------------------
__global__ void __launch_bounds__(256) k_proj(
        const float* __restrict__ w, const float* __restrict__ pb,
        const float* __restrict__ g2, const float* __restrict__ be,
        const float* __restrict__ m, const float* __restrict__ v,
        const float* __restrict__ pplw, const float* __restrict__ pplb,
        const float* __restrict__ ppg, const float* __restrict__ ppbe,
        const float* __restrict__ ppm, const float* __restrict__ ppv,
        float* __restrict__ out) {
    extern __shared__ uint32_t dyn[];
    uint32_t* W2 = dyn + 19584;
    float* scs2 = (float*)(dyn + 23936);
    float* shs2 = (float*)(dyn + 24000);
    float* psc = (float*)(dyn + 24064);
    float* psh = (float*)(dyn + 24080);

    int tid = threadIdx.x;
    int tok0 = blockIdx.x * 64;
    int b2 = tok0 >> 12;
    int yy = (tok0 & 4095) >> 6;
    int w_ = tid >> 5, lane = tid & 31;
    int wm = w_ & 3, wn = w_ >> 2;
    int g = lane >> 2, t = lane & 3;
    int m0 = wm * 16;

    int p4 = tid >> 2, cs = (tid & 3) * 16;
    const float* asrc = g_fused + (size_t)(tok0 + p4) * 256 + cs;
    float4 ar[4];
    int wcl = tid >> 4, wco4 = (tid & 15) * 4;
    int wsc4 = wco4 + (wco4 >= 32 ? 8 : 0);
    int qcl = tid >> 2, qo4 = (tid & 3) * 4;
    int qsc4 = (qo4 < 8) ? (32 + qo4) : (64 + qo4);

#define LOADA(ck) do {                                                      \
        const float* s_ = asrc + (ck) * 64;                                 \
        ar[0] = *(const float4*)(s_);      ar[1] = *(const float4*)(s_ + 4); \
        ar[2] = *(const float4*)(s_ + 8);  ar[3] = *(const float4*)(s_ + 12); \
    } while (0)
#define STOREA(bi) do {                                                     \
        uint32_t* d_ = dyn + (bi) * 4352 + p4 * 68 + cs;                    \
        _Pragma("unroll")                                                   \
        for (int i_ = 0; i_ < 4; ++i_) {                                    \
            *(uint2*)(d_ + i_ * 4) =                                        \
                make_uint2(f2tf32(ar[i_].x), f2tf32(ar[i_].y));             \
            *(uint2*)(d_ + i_ * 4 + 2) =                                    \
                make_uint2(f2tf32(ar[i_].z), f2tf32(ar[i_].w));             \
        }                                                                   \
    } while (0)

    LOADA(0); STOREA(0);
    {
        uint32_t* Wb0 = dyn + 8704;
#pragma unroll
        for (int i = 0; i < 4; ++i) {
            int cl = wcl + i * 16;
            float4 vv = *(const float4*)(w + cl * 64 + wco4);
            Wb0[(wsc4 + 0) * 68 + cl] = f2tf32(vv.x);
            Wb0[(wsc4 + 1) * 68 + cl] = f2tf32(vv.y);
            Wb0[(wsc4 + 2) * 68 + cl] = f2tf32(vv.z);
            Wb0[(wsc4 + 3) * 68 + cl] = f2tf32(vv.w);
        }
        float4 vv = *(const float4*)(pplw + qcl * 16 + qo4);
        Wb0[(qsc4 + 0) * 68 + qcl] = f2tf32(vv.x);
        Wb0[(qsc4 + 1) * 68 + qcl] = f2tf32(vv.y);
        Wb0[(qsc4 + 2) * 68 + qcl] = f2tf32(vv.z);
        Wb0[(qsc4 + 3) * 68 + qcl] = f2tf32(vv.w);
    }
#pragma unroll
    for (int i = 0; i < 4; ++i) {
        int id = tid + i * 256;
        int k = id >> 4, co4 = (id & 15) * 4;
        float4 vv = *(const float4*)(w + (256 + k) * 64 + co4);
        W2[(co4 + 0) * 68 + k] = f2tf32(vv.x);
        W2[(co4 + 1) * 68 + k] = f2tf32(vv.y);
        W2[(co4 + 2) * 68 + k] = f2tf32(vv.z);
        W2[(co4 + 3) * 68 + k] = f2tf32(vv.w);
    }
    if (tid < 64) {
        float sc = g2[tid] * rsqrtf(v[tid] + 1e-3f);
        scs2[tid] = sc;
        shs2[tid] = be[tid] - m[tid] * sc + pb[tid] * sc;
    } else if (tid < 80) {
        int o = tid - 64;
        float sc = ppg[o] * rsqrtf(ppv[o] + 1e-3f);
        psc[o] = sc;
        psh[o] = ppbe[o] - ppm[o] * sc + pplb[o] * sc;
    }
    LOADA(1);
    __syncthreads();

    float a1c[5][4];
#pragma unroll
    for (int nb = 0; nb < 5; ++nb) a1c[nb][0] = a1c[nb][1] = a1c[nb][2] = a1c[nb][3] = 0.f;
    int wn40 = wn * 40;
#pragma unroll 1
    for (int ck = 0; ck < 4; ++ck) {
        float4 wrp[4], wrq;
        if (ck + 1 < 4) {
            int cb = (ck + 1) * 64;
#pragma unroll
            for (int i = 0; i < 4; ++i)
                wrp[i] = *(const float4*)(w + (cb + wcl + i * 16) * 64 + wco4);
            wrq = *(const float4*)(pplw + (cb + qcl) * 16 + qo4);
        }
        const uint32_t* Ab = dyn + (ck & 1) * 4352;
        const uint32_t* Ar0 = Ab + (m0 + g) * 68 + t;
        const uint32_t* Ar1 = Ab + (m0 + g + 8) * 68 + t;
        const uint32_t* Wc = dyn + 8704 + (ck & 1) * 5440 + (wn40 + g) * 68 + t;
#pragma unroll
        for (int k0 = 0; k0 < 64; k0 += 8) {
            uint32_t a0 = Ar0[k0], a1 = Ar1[k0];
            uint32_t a2 = Ar0[k0 + 4], a3 = Ar1[k0 + 4];
#pragma unroll
            for (int nb = 0; nb < 5; ++nb)
                mma_tf32(a1c[nb], a0, a1, a2, a3,
                         Wc[nb * 544 + k0], Wc[nb * 544 + k0 + 4]);
        }
        if (ck + 1 < 4) {
            uint32_t* Wn = dyn + 8704 + ((ck + 1) & 1) * 5440;
#pragma unroll
            for (int i = 0; i < 4; ++i) {
                int cl = wcl + i * 16;
                Wn[(wsc4 + 0) * 68 + cl] = f2tf32(wrp[i].x);
                Wn[(wsc4 + 1) * 68 + cl] = f2tf32(wrp[i].y);
                Wn[(wsc4 + 2) * 68 + cl] = f2tf32(wrp[i].z);
                Wn[(wsc4 + 3) * 68 + cl] = f2tf32(wrp[i].w);
            }
            Wn[(qsc4 + 0) * 68 + qcl] = f2tf32(wrq.x);
            Wn[(qsc4 + 1) * 68 + qcl] = f2tf32(wrq.y);
            Wn[(qsc4 + 2) * 68 + qcl] = f2tf32(wrq.z);
            Wn[(qsc4 + 3) * 68 + qcl] = f2tf32(wrq.w);
            STOREA((ck + 1) & 1);
        }
        __syncthreads();
        if (ck + 2 < 4) LOADA(ck + 2);
    }
#undef LOADA
#undef STOREA

    uint32_t* X2 = dyn;
    {
        int o = wn * 8 + 2 * t;
        float s0 = psc[o], s1 = psc[o + 1], h0 = psh[o], h1 = psh[o + 1];
        *(uint2*)&X2[(m0 + g) * 68 + o] =
            make_uint2(f2tf32(a1c[4][0] * s0 + h0), f2tf32(a1c[4][1] * s1 + h1));
        *(uint2*)&X2[(m0 + g + 8) * 68 + o] =
            make_uint2(f2tf32(a1c[4][2] * s0 + h0), f2tf32(a1c[4][3] * s1 + h1));
    }
    {
        const int HP[3] = {32, 22, 11};
#pragma unroll
        for (int lvl = 0; lvl < 3; ++lvl) {
            int hp = HP[lvl];
            float scale = hp * (1.f / 64.f);
            const float* P0 = g_pool + (size_t)(((lvl + 1) * 2 + b2) * HW) * 16;
            float fy = (yy + 0.5f) * scale - 0.5f;
            float y0f = floorf(fy);
            float ty = fy - y0f;
            int yA = min(max((int)y0f, 0), hp - 1);
            int yB = min(max((int)y0f + 1, 0), hp - 1);
#pragma unroll
            for (int i = 0; i < 4; ++i) {
                int id = tid + i * 256;
                int px = id >> 4, c = id & 15;
                float fx = (px + 0.5f) * scale - 0.5f;
                float x0f = floorf(fx);
                float tx = fx - x0f;
                int xA = min(max((int)x0f, 0), hp - 1);
                int xB = min(max((int)x0f + 1, 0), hp - 1);
                const float* P = P0 + c;
                float v00 = P[(yA * hp + xA) * 16], v01 = P[(yA * hp + xB) * 16];
                float v10 = P[(yB * hp + xA) * 16], v11 = P[(yB * hp + xB) * 16];
                float val = (1.f - ty) * ((1.f - tx) * v00 + tx * v01)
                          + ty * ((1.f - tx) * v10 + tx * v11);
                X2[px * 68 + 16 + lvl * 16 + c] = f2tf32(val);
            }
        }
    }
    __syncthreads();

    float a2c[4][4];
#pragma unroll
    for (int nb = 0; nb < 4; ++nb) a2c[nb][0] = a2c[nb][1] = a2c[nb][2] = a2c[nb][3] = 0.f;
    {
        const uint32_t* Ar0 = X2 + (m0 + g) * 68 + t;
        const uint32_t* Ar1 = X2 + (m0 + g + 8) * 68 + t;
        const uint32_t* Wc = W2 + (wn * 32 + g) * 68 + t;
#pragma unroll
        for (int k0 = 0; k0 < 64; k0 += 8) {
            uint32_t a0 = Ar0[k0], a1 = Ar1[k0];
            uint32_t a2 = Ar0[k0 + 4], a3 = Ar1[k0 + 4];
#pragma unroll
            for (int nb = 0; nb < 4; ++nb)
                mma_tf32(a2c[nb], a0, a1, a2, a3,
                         Wc[nb * 544 + k0], Wc[nb * 544 + k0 + 4]);
        }
    }
    float* o0 = out + (size_t)(tok0 + m0 + g) * 64;
    float* o1 = o0 + 8 * 64;
#pragma unroll
    for (int nb = 0; nb < 4; ++nb) {
        int col = wn * 32 + nb * 8 + 2 * t;
        float s0 = scs2[col], s1 = scs2[col + 1];
        float h0 = shs2[col], h1 = shs2[col + 1];
        float2 r0, r1;
        r0.x = fmaxf((a1c[nb][0] + a2c[nb][0]) * s0 + h0, 0.f);
        r0.y = fmaxf((a1c[nb][1] + a2c[nb][1]) * s1 + h1, 0.f);
        r1.x = fmaxf((a1c[nb][2] + a2c[nb][2]) * s0 + h0, 0.f);
        r1.y = fmaxf((a1c[nb][3] + a2c[nb][3]) * s1 + h1, 0.f);
        *(float2*)(o0 + col) = r0;
        *(float2*)(o1 + col) = r1;
    }
}

// ---------------- launch ---------------------------------------------------
extern "C" void kernel_launch(void* const* d_in, const int* in_sizes, int n_in,
                              void* d_out, int out_size) {
    const float* x       = (const float*)d_in[0];
    const float* conv_w  = (const float*)d_in[1];
    const float* conv_b  = (const float*)d_in[2];
    const float* bn_g    = (const float*)d_in[3];
    const float* bn_b    = (const float*)d_in[4];
    const float* bn_m    = (const float*)d_in[5];
    const float* bn_v    = (const float*)d_in[6];
    const float* q_w     = (const float*)d_in[7];
    const float* q_b     = (const float*)d_in[8];
    const float* k_w     = (const float*)d_in[9];
    const float* k_b     = (const float*)d_in[10];
    const float* v_w     = (const float*)d_in[11];
    const float* v_b     = (const float*)d_in[12];
    const float* attn_g  = (const float*)d_in[13];
    const float* ppl_w   = (const float*)d_in[14];
    const float* ppl_b   = (const float*)d_in[15];
    const float* ppl_bng = (const float*)d_in[16];
    const float* ppl_bnb = (const float*)d_in[17];
    const float* ppl_bnm = (const float*)d_in[18];
    const float* ppl_bnv = (const float*)d_in[19];
    const float* proj_w  = (const float*)d_in[20];
    const float* proj_b  = (const float*)d_in[21];
    const float* pbn_g   = (const float*)d_in[22];
    const float* pbn_b   = (const float*)d_in[23];
    const float* pbn_m   = (const float*)d_in[24];
    const float* pbn_v   = (const float*)d_in[25];
    float* out = (float*)d_out;

    const int CONV_SMEM = 26240 * 4;   // 104,960 B
    const int ATTN_SMEM = 14336 * 4;   // 57,344 B
    const int PROJ_SMEM = 24096 * 4;   // 96,384 B
    cudaFuncSetAttribute(k_conv, cudaFuncAttributeMaxDynamicSharedMemorySize, CONV_SMEM);
    cudaFuncSetAttribute(k_attn, cudaFuncAttributeMaxDynamicSharedMemorySize, ATTN_SMEM);
    cudaFuncSetAttribute(k_proj, cudaFuncAttributeMaxDynamicSharedMemorySize, PROJ_SMEM);

    k_conv<<<dim3(32, 8), 256, CONV_SMEM>>>(x, conv_w, conv_b, bn_g, bn_b, bn_m, bn_v,
                                            q_w, q_b, k_w, k_b, v_w, v_b);
    k_attn<<<dim3(32, 4, 2), 256, ATTN_SMEM>>>(attn_g);
    k_pool<<<dim3(408, 2), 256>>>(ppl_w, ppl_b, ppl_bng, ppl_bnb, ppl_bnm, ppl_bnv);
    k_proj<<<128, 256, PROJ_SMEM>>>(proj_w, proj_b, pbn_g, pbn_b, pbn_m, pbn_v,
                                    ppl_w, ppl_b, ppl_bng, ppl_bnb, ppl_bnm, ppl_bnv, out);
}

// round 15
// speedup vs baseline: 1.2656x; 1.0167x over previous
#include <cuda_runtime.h>
#include <cuda_bf16.h>
#include <math.h>
#include <stdint.h>

#define NB 4
#define BATCH 2
#define HW 4096
#define F 64
#define LOG2E 1.4426950408889634f

// ---------------- scratch (device globals; no allocation allowed) ----------
__device__ float    g_fused[BATCH * HW * 256];
__device__ uint32_t g_q[BATCH * NB * HW * 4];       // f16x2 pairs [pos][4]
__device__ uint32_t g_k[BATCH * NB * HW * 4];       // f16x2 pairs
__device__ uint32_t g_vp[BATCH * NB * 32 * 4096];   // f16x2 pairs, ldmatrix order
__device__ float    g_pool[NB * BATCH * HW * 16];

// ---------------- helpers ---------------------------------------------------
__device__ __forceinline__ uint32_t f2tf32(float f) {
    uint32_t r; asm("cvt.rna.tf32.f32 %0, %1;" : "=r"(r) : "f"(f)); return r;
}
__device__ __forceinline__ uint32_t packh(float hi, float lo) {
    uint32_t r; asm("cvt.rn.f16x2.f32 %0, %1, %2;" : "=r"(r) : "f"(hi), "f"(lo)); return r;
}
__device__ __forceinline__ uint32_t ex2h2(uint32_t x) {
    uint32_t y; asm("ex2.approx.f16x2 %0, %1;" : "=r"(y) : "r"(x)); return y;
}
__device__ __forceinline__ void mma_tf32(float c[4], uint32_t a0, uint32_t a1,
                                         uint32_t a2, uint32_t a3,
                                         uint32_t b0, uint32_t b1) {
    asm volatile(
        "mma.sync.aligned.m16n8k8.row.col.f32.tf32.tf32.f32 "
        "{%0,%1,%2,%3},{%4,%5,%6,%7},{%8,%9},{%0,%1,%2,%3};"
        : "+f"(c[0]), "+f"(c[1]), "+f"(c[2]), "+f"(c[3])
        : "r"(a0), "r"(a1), "r"(a2), "r"(a3), "r"(b0), "r"(b1));
}
__device__ __forceinline__ void mma_f16(float c[4], uint32_t a0, uint32_t a1,
                                        uint32_t a2, uint32_t a3,
                                        uint32_t b0, uint32_t b1) {
    asm volatile(
        "mma.sync.aligned.m16n8k16.row.col.f32.f16.f16.f32 "
        "{%0,%1,%2,%3},{%4,%5,%6,%7},{%8,%9},{%0,%1,%2,%3};"
        : "+f"(c[0]), "+f"(c[1]), "+f"(c[2]), "+f"(c[3])
        : "r"(a0), "r"(a1), "r"(a2), "r"(a3), "r"(b0), "r"(b1));
}
// QK: f16 accumulator -> scores arrive pre-packed as f16x2
__device__ __forceinline__ void mma_f16k8h(uint32_t& d0, uint32_t& d1,
                                           uint32_t a0, uint32_t a1, uint32_t b0) {
    asm volatile(
        "mma.sync.aligned.m16n8k8.row.col.f16.f16.f16.f16 "
        "{%0,%1},{%2,%3},{%4},{%5,%6};"
        : "=r"(d0), "=r"(d1)
        : "r"(a0), "r"(a1), "r"(b0), "r"(0u), "r"(0u));
}
__device__ __forceinline__ void ldsm_x4(uint32_t& r0, uint32_t& r1,
                                        uint32_t& r2, uint32_t& r3, uint32_t addr) {
    asm volatile("ldmatrix.sync.aligned.m8n8.x4.shared.b16 {%0,%1,%2,%3}, [%4];"
        : "=r"(r0), "=r"(r1), "=r"(r2), "=r"(r3) : "r"(addr));
}
__device__ __forceinline__ void cpa16(uint32_t s, const void* g) {
    asm volatile("cp.async.cg.shared.global [%0], [%1], 16;" :: "r"(s), "l"(g));
}
__device__ __forceinline__ void cpa16z(uint32_t s, const void* g, int sz) {
    asm volatile("cp.async.cg.shared.global [%0], [%1], 16, %2;" :: "r"(s), "l"(g), "r"(sz));
}

// ---------------- K1: dilated conv + fused QKV (unchanged) -----------------
__global__ void __launch_bounds__(256, 2) k_conv(
        const float* __restrict__ x, const float* __restrict__ wg,
        const float* __restrict__ cb, const float* __restrict__ bg,
        const float* __restrict__ bbe, const float* __restrict__ bm,
        const float* __restrict__ bv,
        const float* __restrict__ qw, const float* __restrict__ qb,
        const float* __restrict__ kw, const float* __restrict__ kb_,
        const float* __restrict__ vw, const float* __restrict__ vb) {
    extern __shared__ uint32_t dyn[];
    uint32_t* Vt = dyn + 8704;
    uint32_t* QW = dyn + 12928;
    uint32_t* KW = dyn + 13472;
    float* vbs = (float*)(dyn + 14016);
    float* qkb = (float*)(dyn + 14080);
    float* scs = (float*)(dyn + 26112);
    float* shs = (float*)(dyn + 26176);

    int tid = threadIdx.x;
    int bb = blockIdx.y, b = bb >> 2, br = bb & 3;
    int d = 1 << br;
    int pix0 = blockIdx.x * 128;
    int y0 = blockIdx.x * 2;

    if (tid < 64) {
        int idx = br * 64 + tid;
        float sc = bg[idx] * rsqrtf(bv[idx] + 1e-3f);
        scs[tid] = sc;
        shs[tid] = bbe[idx] - bm[idx] * sc + cb[idx] * sc;
    }

    int w = tid >> 5, lane = tid & 31;
    int g = lane >> 2, t = lane & 3;
    int m0 = w * 16;

    float c[8][4];
#pragma unroll
    for (int nb = 0; nb < 8; ++nb) c[nb][0] = c[nb][1] = c[nb][2] = c[nb][3] = 0.f;

    int p = tid >> 1, ch = (tid & 1) * 32;
    int prow = p >> 6, pcol = p & 63;
    int wci0 = tid >> 4, wco4 = (tid & 15) * 4;

    uint32_t sh0 = (uint32_t)__cvta_generic_to_shared(dyn);
    uint32_t a_dst0 = sh0 + (uint32_t)((p * 68 + ch) * 4);
    const float* xb = x + (size_t)b * 64 * 64 * 64;
    const float* wbase = wg + (size_t)br * 9 * 4096;

#define PREFETCH_A(tap, bi) do {                                             \
        int ky_ = (tap) / 3, kx_ = (tap) - ky_ * 3;                          \
        int iy_ = y0 + prow + d * (ky_ - 1);                                 \
        int ix_ = pcol + d * (kx_ - 1);                                      \
        int val_ = (((unsigned)iy_ < 64u) & ((unsigned)ix_ < 64u)) ? 16 : 0; \
        int iyc_ = min(max(iy_, 0), 63), ixc_ = min(max(ix_, 0), 63);        \
        const float* asrc_ = xb + (((size_t)iyc_ * 64 + ixc_) * 64 + ch);    \
        uint32_t ad_ = a_dst0 + (uint32_t)(bi) * 34816u;                     \
        _Pragma("unroll")                                                    \
        for (int i_ = 0; i_ < 8; ++i_) cpa16z(ad_ + i_ * 16, asrc_ + i_ * 4, val_); \
        asm volatile("cp.async.commit_group;");                              \
    } while (0)

    PREFETCH_A(0, 0);
    PREFETCH_A(1, 1);
    {
        uint32_t* W0 = dyn + 17408;
#pragma unroll
        for (int i = 0; i < 4; ++i) {
            int ci = wci0 + i * 16;
            float4 v = *(const float4*)(wbase + ci * 64 + wco4);
            W0[(wco4 + 0) * 68 + ci] = f2tf32(v.x);
            W0[(wco4 + 1) * 68 + ci] = f2tf32(v.y);
            W0[(wco4 + 2) * 68 + ci] = f2tf32(v.z);
            W0[(wco4 + 3) * 68 + ci] = f2tf32(v.w);
        }
    }
    asm volatile("cp.async.wait_group 1;");
    __syncthreads();

#pragma unroll 1
    for (int tap = 0; tap < 9; ++tap) {
        float4 wr[4];
        if (tap + 1 < 9) {
            const float* wt1 = wbase + (size_t)(tap + 1) * 4096;
#pragma unroll
            for (int i = 0; i < 4; ++i)
                wr[i] = *(const float4*)(wt1 + (wci0 + i * 16) * 64 + wco4);
        }
        const uint32_t* Ab = dyn + (tap & 1) * 8704;
        const uint32_t* Wb = dyn + 17408 + (tap & 1) * 4352;
        const uint32_t* Ar0 = Ab + (m0 + g) * 68 + t;
        const uint32_t* Ar1 = Ab + (m0 + g + 8) * 68 + t;
        const uint32_t* Wg_ = Wb + g * 68 + t;
#pragma unroll
        for (int k0 = 0; k0 < 64; k0 += 8) {
            uint32_t a0 = Ar0[k0], a1 = Ar1[k0];
            uint32_t a2 = Ar0[k0 + 4], a3 = Ar1[k0 + 4];
#pragma unroll
            for (int nb = 0; nb < 8; ++nb)
                mma_tf32(c[nb], a0, a1, a2, a3,
                         Wg_[nb * 8 * 68 + k0], Wg_[nb * 8 * 68 + k0 + 4]);
        }
        if (tap + 1 < 9) {
            uint32_t* Wn = dyn + 17408 + ((tap + 1) & 1) * 4352;
#pragma unroll
            for (int i = 0; i < 4; ++i) {
                int ci = wci0 + i * 16;
                Wn[(wco4 + 0) * 68 + ci] = f2tf32(wr[i].x);
                Wn[(wco4 + 1) * 68 + ci] = f2tf32(wr[i].y);
                Wn[(wco4 + 2) * 68 + ci] = f2tf32(wr[i].z);
                Wn[(wco4 + 3) * 68 + ci] = f2tf32(wr[i].w);
            }
        }
        __syncthreads();
        if (tap + 2 < 9) {
            PREFETCH_A(tap + 2, (tap & 1));
            asm volatile("cp.async.wait_group 1;");
            __syncthreads();
        } else if (tap + 1 < 9) {
            asm volatile("cp.async.wait_group 0;");
            __syncthreads();
        }
    }
#undef PREFETCH_A

    float rv[8][4];
    float* f0 = g_fused + ((size_t)b * HW + pix0 + m0 + g) * 256 + br * 64;
    float* f1 = f0 + 8 * 256;
#pragma unroll
    for (int nb = 0; nb < 8; ++nb) {
        int col = nb * 8 + 2 * t;
        rv[nb][0] = fmaxf(c[nb][0] * scs[col] + shs[col], 0.f);
        rv[nb][1] = fmaxf(c[nb][1] * scs[col + 1] + shs[col + 1], 0.f);
        rv[nb][2] = fmaxf(c[nb][2] * scs[col] + shs[col], 0.f);
        rv[nb][3] = fmaxf(c[nb][3] * scs[col + 1] + shs[col + 1], 0.f);
        *(float2*)(f0 + col) = make_float2(rv[nb][0], rv[nb][1]);
        *(float2*)(f1 + col) = make_float2(rv[nb][2], rv[nb][3]);
    }
    __syncthreads();
    uint32_t* As = dyn;
#pragma unroll
    for (int nb = 0; nb < 8; ++nb) {
        int col = nb * 8 + 2 * t;
        *(uint2*)&As[(m0 + g) * 68 + col] =
            make_uint2(f2tf32(rv[nb][0]), f2tf32(rv[nb][1]));
        *(uint2*)&As[(m0 + g + 8) * 68 + col] =
            make_uint2(f2tf32(rv[nb][2]), f2tf32(rv[nb][3]));
    }
    uint32_t* Wv = dyn + 17408;
#pragma unroll
    for (int i = 0; i < 4; ++i) {
        int ci = wci0 + i * 16;
        float4 v = *(const float4*)(vw + br * 4096 + ci * 64 + wco4);
        Wv[(wco4 + 0) * 68 + ci] = f2tf32(v.x);
        Wv[(wco4 + 1) * 68 + ci] = f2tf32(v.y);
        Wv[(wco4 + 2) * 68 + ci] = f2tf32(v.z);
        Wv[(wco4 + 3) * 68 + ci] = f2tf32(v.w);
    }
    if (tid < 128) {
        int ci = tid >> 1, d4 = (tid & 1) * 4;
        float4 v = *(const float4*)(qw + br * 512 + ci * 8 + d4);
        QW[(d4 + 0) * 68 + ci] = f2tf32(v.x * LOG2E);
        QW[(d4 + 1) * 68 + ci] = f2tf32(v.y * LOG2E);
        QW[(d4 + 2) * 68 + ci] = f2tf32(v.z * LOG2E);
        QW[(d4 + 3) * 68 + ci] = f2tf32(v.w * LOG2E);
    } else {
        int id = tid - 128;
        int ci = id >> 1, d4 = (id & 1) * 4;
        float4 v = *(const float4*)(kw + br * 512 + ci * 8 + d4);
        KW[(d4 + 0) * 68 + ci] = f2tf32(v.x);
        KW[(d4 + 1) * 68 + ci] = f2tf32(v.y);
        KW[(d4 + 2) * 68 + ci] = f2tf32(v.z);
        KW[(d4 + 3) * 68 + ci] = f2tf32(v.w);
    }
    if (tid < 64) vbs[tid] = vb[br * 64 + tid];
    if (tid >= 64 && tid < 72) qkb[tid - 64] = qb[br * 8 + tid - 64] * LOG2E;
    if (tid >= 72 && tid < 80) qkb[8 + tid - 72] = kb_[br * 8 + tid - 72];
    __syncthreads();
    const uint32_t* Ar0 = As + (m0 + g) * 68 + t;
    const uint32_t* Ar1 = As + (m0 + g + 8) * 68 + t;
    const uint32_t* Wg_ = Wv + g * 68 + t;
    float vac[8][4];
#pragma unroll
    for (int nb = 0; nb < 8; ++nb) vac[nb][0] = vac[nb][1] = vac[nb][2] = vac[nb][3] = 0.f;
#pragma unroll
    for (int k0 = 0; k0 < 64; k0 += 8) {
        uint32_t a0 = Ar0[k0], a1 = Ar1[k0];
        uint32_t a2 = Ar0[k0 + 4], a3 = Ar1[k0 + 4];
#pragma unroll
        for (int nb = 0; nb < 8; ++nb)
            mma_tf32(vac[nb], a0, a1, a2, a3, Wg_[nb * 8 * 68 + k0], Wg_[nb * 8 * 68 + k0 + 4]);
    }
    float qa_[4] = {0.f, 0.f, 0.f, 0.f}, ka_[4] = {0.f, 0.f, 0.f, 0.f};
    const uint32_t* Qg_ = QW + g * 68 + t;
    const uint32_t* Kg_ = KW + g * 68 + t;
#pragma unroll
    for (int k0 = 0; k0 < 64; k0 += 8) {
        uint32_t a0 = Ar0[k0], a1 = Ar1[k0];
        uint32_t a2 = Ar0[k0 + 4], a3 = Ar1[k0 + 4];
        mma_tf32(qa_, a0, a1, a2, a3, Qg_[k0], Qg_[k0 + 4]);
        mma_tf32(ka_, a0, a1, a2, a3, Kg_[k0], Kg_[k0 + 4]);
    }
    {
        float b0f = qkb[2 * t], b1f = qkb[2 * t + 1];
        uint32_t* qd = g_q + ((size_t)bb * HW + pix0 + m0 + g) * 4 + t;
        qd[0]  = packh(qa_[1] + b1f, qa_[0] + b0f);
        qd[32] = packh(qa_[3] + b1f, qa_[2] + b0f);
        float c0f = qkb[8 + 2 * t], c1f = qkb[8 + 2 * t + 1];
        uint32_t* kd = g_k + ((size_t)bb * HW + pix0 + m0 + g) * 4 + t;
        kd[0]  = packh(ka_[1] + c1f, ka_[0] + c0f);
        kd[32] = packh(ka_[3] + c1f, ka_[2] + c0f);
    }
#pragma unroll
    for (int nb = 0; nb < 8; ++nb) {
        int col = nb * 8 + 2 * t;
        Vt[(m0 + g) * 33 + nb * 4 + t] =
            packh(vac[nb][1] + vbs[col + 1], vac[nb][0] + vbs[col]);
        Vt[(m0 + g + 8) * 33 + nb * 4 + t] =
            packh(vac[nb][3] + vbs[col + 1], vac[nb][2] + vbs[col]);
    }
    __syncthreads();
    uint32_t* vout = g_vp + ((size_t)bb * 32 + blockIdx.x) * 4096;
#pragma unroll
    for (int i = 0; i < 16; ++i) {
        int o = tid + i * 256;
        int col = o & 3, row = (o >> 2) & 7, mat = o >> 5;
        int kpt = ((mat >> 3) << 2) | col;
        int cch = ((mat & 7) << 3) | row;
        uint32_t lo = Vt[(2 * kpt) * 33 + (cch >> 1)];
        uint32_t hi = Vt[(2 * kpt + 1) * 33 + (cch >> 1)];
        vout[o] = (cch & 1) ? ((lo >> 16) | (hi & 0xFFFF0000u))
                            : ((lo & 0xFFFFu) | (hi << 16));
    }
}

// ---------------- K3: flash attention, f16-acc QK (pre-packed scores) ------
__global__ void __launch_bounds__(256, 2) k_attn(const float* __restrict__ gamma) {
    extern __shared__ uint32_t dsh[];
    uint32_t* Qs = dsh;
    int tid = threadIdx.x;
    int br = blockIdx.y, b = blockIdx.z;
    int bb = b * NB + br;
    int n0 = blockIdx.x * 128;
    int w = tid >> 5, lane = tid & 31;
    int g = lane >> 2, t = lane & 3;

    const uint32_t* kgm = g_k + (size_t)bb * HW * 4;
    const uint32_t* vgm = g_vp + (size_t)bb * 32 * 4096;

    uint32_t shb = (uint32_t)__cvta_generic_to_shared(dsh);
    uint32_t ksa[3], vsa[3];
#pragma unroll
    for (int i = 0; i < 3; ++i) {
        ksa[i] = shb + (512u + i * 512u) * 4u;
        vsa[i] = shb + (2048u + i * 4096u) * 4u;
    }

    if (tid < 128) cpa16(ksa[0] + tid * 16, kgm + tid * 4);
#pragma unroll
    for (int j = 0; j < 4; ++j)
        cpa16(vsa[0] + (tid + j * 256) * 16, vgm + (tid + j * 256) * 4);
    asm volatile("cp.async.commit_group;");
    if (tid < 128)
        ((uint4*)Qs)[tid] = ((const uint4*)(g_q + ((size_t)bb * HW + n0) * 4))[tid];
    if (tid < 128) cpa16(ksa[1] + tid * 16, kgm + 512 + tid * 4);
#pragma unroll
    for (int j = 0; j < 4; ++j)
        cpa16(vsa[1] + (tid + j * 256) * 16, vgm + 4096 + (tid + j * 256) * 4);
    asm volatile("cp.async.commit_group;");
    __syncthreads();

    int r0i = w * 16 + g;
    uint32_t qa0 = Qs[r0i * 4 + t];
    uint32_t qa1 = Qs[(r0i + 8) * 4 + t];

    int midx = lane >> 3;
    int lane_const = (midx & 1) * 8 + (midx >> 1);
    uint32_t lboff = (uint32_t)((lane_const * 32 + (lane & 7) * 4) * 4);

    float o[8][4];
#pragma unroll
    for (int nb = 0; nb < 8; ++nb) { o[nb][0] = o[nb][1] = o[nb][2] = o[nb][3] = 0.f; }
    float zc[4] = {0.f, 0.f, 0.f, 0.f};
    const uint32_t ONES = 0x3C003C00u;

    int cur = 0, pf = 2;
#pragma unroll 1
    for (int it = 0; it < 32; ++it) {
        if (it < 31) asm volatile("cp.async.wait_group 1;");
        else         asm volatile("cp.async.wait_group 0;");
        __syncthreads();
        const uint32_t* Kc = dsh + 512 + cur * 512;
        uint32_t lb = vsa[cur] + lboff;

        uint32_t pa[16][2];
#pragma unroll
        for (int j = 0; j < 16; ++j) {
            uint32_t b0 = Kc[(j * 8 + g) * 4 + t];
            uint32_t d0, d1;
            mma_f16k8h(d0, d1, qa0, qa1, b0);
            pa[j][0] = ex2h2(d0);
            pa[j][1] = ex2h2(d1);
        }
#pragma unroll
        for (int ks = 0; ks < 8; ++ks) {
#pragma unroll
            for (int nbp = 0; nbp < 4; ++nbp) {
                uint32_t b00, b10, b01, b11;
                ldsm_x4(b00, b10, b01, b11, lb + (uint32_t)((16 * ks + 2 * nbp) * 128));
                mma_f16(o[2 * nbp], pa[2 * ks][0], pa[2 * ks][1],
                        pa[2 * ks + 1][0], pa[2 * ks + 1][1], b00, b10);
                mma_f16(o[2 * nbp + 1], pa[2 * ks][0], pa[2 * ks][1],
                        pa[2 * ks + 1][0], pa[2 * ks + 1][1], b01, b11);
            }
            mma_f16(zc, pa[2 * ks][0], pa[2 * ks][1],
                    pa[2 * ks + 1][0], pa[2 * ks + 1][1], ONES, ONES);
        }
        if (it + 2 < 32) {
            int t2 = it + 2;
            if (tid < 128) cpa16(ksa[pf] + tid * 16, kgm + (size_t)t2 * 512 + tid * 4);
#pragma unroll
            for (int j = 0; j < 4; ++j)
                cpa16(vsa[pf] + (tid + j * 256) * 16,
                      vgm + (size_t)t2 * 4096 + (tid + j * 256) * 4);
            asm volatile("cp.async.commit_group;");
        }
        cur = (cur == 2) ? 0 : cur + 1;
        pf = (pf == 2) ? 0 : pf + 1;
    }
    float ga = gamma[br];
    float i0 = ga / zc[0], i1 = ga / zc[2];
    float* base0 = g_fused + ((size_t)b * HW + n0 + w * 16 + g) * 256 + br * 64 + 2 * t;
    float* base1 = base0 + 8 * 256;
#pragma unroll
    for (int nb = 0; nb < 8; ++nb) {
        float2 v0 = *(float2*)(base0 + nb * 8);
        v0.x += o[nb][0] * i0; v0.y += o[nb][1] * i0;
        *(float2*)(base0 + nb * 8) = v0;
        float2 v1 = *(float2*)(base1 + nb * 8);
        v1.x += o[nb][2] * i1; v1.y += o[nb][3] * i1;
        *(float2*)(base1 + nb * 8) = v1;
    }
}

// ---------------- K4: pool (unchanged) -------------------------------------
template<int PS, int PLO>
__device__ __forceinline__ float4 pool_win4(int b, int oy, int ox, int c4) {
    int ys0 = oy * PS - PLO, xs0 = ox * PS - PLO;
    float4 s = make_float4(0.f, 0.f, 0.f, 0.f);
    int cnt = 0;
#pragma unroll
    for (int dy = 0; dy < PS; ++dy) {
        int yy = ys0 + dy;
        bool vy = (unsigned)yy < 64u;
        int yyc = min(max(yy, 0), 63);
#pragma unroll
        for (int dx = 0; dx < PS; ++dx) {
            int xx = xs0 + dx;
            bool v = vy && ((unsigned)xx < 64u);
            int xxc = min(max(xx, 0), 63);
            float4 val = *(const float4*)(g_fused + ((size_t)(b * HW) + yyc * 64 + xxc) * 256 + c4);
            if (v) { s.x += val.x; s.y += val.y; s.z += val.z; s.w += val.w; ++cnt; }
        }
    }
    float inv = 1.f / (float)cnt;
    s.x *= inv; s.y *= inv; s.z *= inv; s.w *= inv;
    return s;
}

__global__ void k_pool(const float* __restrict__ pw, const float* __restrict__ pb,
                       const float* __restrict__ pg, const float* __restrict__ pbe,
                       const float* __restrict__ pm, const float* __restrict__ pv) {
    __shared__ float avg[4][256];
    __shared__ float part[4][64];
    int b = blockIdx.y;
    int slot = threadIdx.x >> 6;
    int l64 = threadIdx.x & 63;
    int lin = blockIdx.x * 4 + slot;
    bool valid = lin < 1629;
    int linc = valid ? lin : 1628;
    int j, r;
    if (linc < 1024)      { j = 1; r = linc; }
    else if (linc < 1508) { j = 2; r = linc - 1024; }
    else                  { j = 3; r = linc - 1508; }
    const int HPs[4] = {64, 32, 22, 11};
    int hp = HPs[j];
    int oy = r / hp, ox = r % hp;
    int c4 = l64 * 4;
    float4 s;
    if (j == 1)      s = pool_win4<2, 0>(b, oy, ox, c4);
    else if (j == 2) s = pool_win4<3, 1>(b, oy, ox, c4);
    else             s = pool_win4<6, 1>(b, oy, ox, c4);
    *(float4*)&avg[slot][c4] = s;
    __syncthreads();
    int o = l64 & 15, q = l64 >> 4;
    const float* wp = pw + j * 4096 + o;
    float a = 0.f;
#pragma unroll 16
    for (int i = 0; i < 64; ++i) {
        int ci = q * 64 + i;
        a += avg[slot][ci] * wp[ci * 16];
    }
    part[slot][q * 16 + o] = a;
    __syncthreads();
    if (l64 < 16 && valid) {
        float acc = pb[j * 16 + l64] + part[slot][l64] + part[slot][16 + l64]
                  + part[slot][32 + l64] + part[slot][48 + l64];
        int idx = j * 16 + l64;
        float sc = pg[idx] * rsqrtf(pv[idx] + 1e-3f);
        float sh = pbe[idx] - pm[idx] * sc;
        g_pool[((size_t)((j * 2 + b) * HW) + oy * hp + ox) * 16 + l64] = acc * sc + sh;
    }
}

// ---------------- K5: proj GEMM (unchanged) --------------------------------
__global__ void __launch_bounds__(256) k_proj(
        const float* __restrict__ w, const float* __restrict__ pb,
        const float* __restrict__ g2, const float* __restrict__ be,
        const float* __restrict__ m, const float* __restrict__ v,
        const float* __restrict__ pplw, const float* __restrict__ pplb,
        const float* __restrict__ ppg, const float* __restrict__ ppbe,
        const float* __restrict__ ppm, const float* __restrict__ ppv,
        float* __restrict__ out) {
    extern __shared__ uint32_t dyn[];
    uint32_t* W2 = dyn + 19584;
    float* scs2 = (float*)(dyn + 23936);
    float* shs2 = (float*)(dyn + 24000);
    float* psc = (float*)(dyn + 24064);
    float* psh = (float*)(dyn + 24080);

    int tid = threadIdx.x;
    int tok0 = blockIdx.x * 64;
    int b2 = tok0 >> 12;
    int yy = (tok0 & 4095) >> 6;
    int w_ = tid >> 5, lane = tid & 31;
    int wm = w_ & 3, wn = w_ >> 2;
    int g = lane >> 2, t = lane & 3;
    int m0 = wm * 16;

    int p4 = tid >> 2, cs = (tid & 3) * 16;
    const float* asrc = g_fused + (size_t)(tok0 + p4) * 256 + cs;
    float4 ar[4];
    int wcl = tid >> 4, wco4 = (tid & 15) * 4;
    int wsc4 = wco4 + (wco4 >= 32 ? 8 : 0);
    int qcl = tid >> 2, qo4 = (tid & 3) * 4;
    int qsc4 = (qo4 < 8) ? (32 + qo4) : (64 + qo4);

#define LOADA(ck) do {                                                      \
        const float* s_ = asrc + (ck) * 64;                                 \
        ar[0] = *(const float4*)(s_);      ar[1] = *(const float4*)(s_ + 4); \
        ar[2] = *(const float4*)(s_ + 8);  ar[3] = *(const float4*)(s_ + 12); \
    } while (0)
#define STOREA(bi) do {                                                     \
        uint32_t* d_ = dyn + (bi) * 4352 + p4 * 68 + cs;                    \
        _Pragma("unroll")                                                   \
        for (int i_ = 0; i_ < 4; ++i_) {                                    \
            *(uint2*)(d_ + i_ * 4) =                                        \
                make_uint2(f2tf32(ar[i_].x), f2tf32(ar[i_].y));             \
            *(uint2*)(d_ + i_ * 4 + 2) =                                    \
                make_uint2(f2tf32(ar[i_].z), f2tf32(ar[i_].w));             \
        }                                                                   \
    } while (0)

    LOADA(0); STOREA(0);
    {
        uint32_t* Wb0 = dyn + 8704;
#pragma unroll
        for (int i = 0; i < 4; ++i) {
            int cl = wcl + i * 16;
            float4 vv = *(const float4*)(w + cl * 64 + wco4);
            Wb0[(wsc4 + 0) * 68 + cl] = f2tf32(vv.x);
            Wb0[(wsc4 + 1) * 68 + cl] = f2tf32(vv.y);
            Wb0[(wsc4 + 2) * 68 + cl] = f2tf32(vv.z);
            Wb0[(wsc4 + 3) * 68 + cl] = f2tf32(vv.w);
        }
        float4 vv = *(const float4*)(pplw + qcl * 16 + qo4);
        Wb0[(qsc4 + 0) * 68 + qcl] = f2tf32(vv.x);
        Wb0[(qsc4 + 1) * 68 + qcl] = f2tf32(vv.y);
        Wb0[(qsc4 + 2) * 68 + qcl] = f2tf32(vv.z);
        Wb0[(qsc4 + 3) * 68 + qcl] = f2tf32(vv.w);
    }
#pragma unroll
    for (int i = 0; i < 4; ++i) {
        int id = tid + i * 256;
        int k = id >> 4, co4 = (id & 15) * 4;
        float4 vv = *(const float4*)(w + (256 + k) * 64 + co4);
        W2[(co4 + 0) * 68 + k] = f2tf32(vv.x);
        W2[(co4 + 1) * 68 + k] = f2tf32(vv.y);
        W2[(co4 + 2) * 68 + k] = f2tf32(vv.z);
        W2[(co4 + 3) * 68 + k] = f2tf32(vv.w);
    }
    if (tid < 64) {
        float sc = g2[tid] * rsqrtf(v[tid] + 1e-3f);
        scs2[tid] = sc;
        shs2[tid] = be[tid] - m[tid] * sc + pb[tid] * sc;
    } else if (tid < 80) {
        int o = tid - 64;
        float sc = ppg[o] * rsqrtf(ppv[o] + 1e-3f);
        psc[o] = sc;
        psh[o] = ppbe[o] - ppm[o] * sc + pplb[o] * sc;
    }
    LOADA(1);
    __syncthreads();

    float a1c[5][4];
#pragma unroll
    for (int nb = 0; nb < 5; ++nb) a1c[nb][0] = a1c[nb][1] = a1c[nb][2] = a1c[nb][3] = 0.f;
    int wn40 = wn * 40;
#pragma unroll 1
    for (int ck = 0; ck < 4; ++ck) {
        float4 wrp[4], wrq;
        if (ck + 1 < 4) {
            int cb = (ck + 1) * 64;
#pragma unroll
            for (int i = 0; i < 4; ++i)
                wrp[i] = *(const float4*)(w + (cb + wcl + i * 16) * 64 + wco4);
            wrq = *(const float4*)(pplw + (cb + qcl) * 16 + qo4);
        }
        const uint32_t* Ab = dyn + (ck & 1) * 4352;
        const uint32_t* Ar0 = Ab + (m0 + g) * 68 + t;
        const uint32_t* Ar1 = Ab + (m0 + g + 8) * 68 + t;
        const uint32_t* Wc = dyn + 8704 + (ck & 1) * 5440 + (wn40 + g) * 68 + t;
#pragma unroll
        for (int k0 = 0; k0 < 64; k0 += 8) {
            uint32_t a0 = Ar0[k0], a1 = Ar1[k0];
            uint32_t a2 = Ar0[k0 + 4], a3 = Ar1[k0 + 4];
#pragma unroll
            for (int nb = 0; nb < 5; ++nb)
                mma_tf32(a1c[nb], a0, a1, a2, a3,
                         Wc[nb * 544 + k0], Wc[nb * 544 + k0 + 4]);
        }
        if (ck + 1 < 4) {
            uint32_t* Wn = dyn + 8704 + ((ck + 1) & 1) * 5440;
#pragma unroll
            for (int i = 0; i < 4; ++i) {
                int cl = wcl + i * 16;
                Wn[(wsc4 + 0) * 68 + cl] = f2tf32(wrp[i].x);
                Wn[(wsc4 + 1) * 68 + cl] = f2tf32(wrp[i].y);
                Wn[(wsc4 + 2) * 68 + cl] = f2tf32(wrp[i].z);
                Wn[(wsc4 + 3) * 68 + cl] = f2tf32(wrp[i].w);
            }
            Wn[(qsc4 + 0) * 68 + qcl] = f2tf32(wrq.x);
            Wn[(qsc4 + 1) * 68 + qcl] = f2tf32(wrq.y);
            Wn[(qsc4 + 2) * 68 + qcl] = f2tf32(wrq.z);
            Wn[(qsc4 + 3) * 68 + qcl] = f2tf32(wrq.w);
            STOREA((ck + 1) & 1);
        }
        __syncthreads();
        if (ck + 2 < 4) LOADA(ck + 2);
    }
#undef LOADA
#undef STOREA

    uint32_t* X2 = dyn;
    {
        int o = wn * 8 + 2 * t;
        float s0 = psc[o], s1 = psc[o + 1], h0 = psh[o], h1 = psh[o + 1];
        *(uint2*)&X2[(m0 + g) * 68 + o] =
            make_uint2(f2tf32(a1c[4][0] * s0 + h0), f2tf32(a1c[4][1] * s1 + h1));
        *(uint2*)&X2[(m0 + g + 8) * 68 + o] =
            make_uint2(f2tf32(a1c[4][2] * s0 + h0), f2tf32(a1c[4][3] * s1 + h1));
    }
    {
        const int HP[3] = {32, 22, 11};
#pragma unroll
        for (int lvl = 0; lvl < 3; ++lvl) {
            int hp = HP[lvl];
            float scale = hp * (1.f / 64.f);
            const float* P0 = g_pool + (size_t)(((lvl + 1) * 2 + b2) * HW) * 16;
            float fy = (yy + 0.5f) * scale - 0.5f;
            float y0f = floorf(fy);
            float ty = fy - y0f;
            int yA = min(max((int)y0f, 0), hp - 1);
            int yB = min(max((int)y0f + 1, 0), hp - 1);
#pragma unroll
            for (int i = 0; i < 4; ++i) {
                int id = tid + i * 256;
                int px = id >> 4, c = id & 15;
                float fx = (px + 0.5f) * scale - 0.5f;
                float x0f = floorf(fx);
                float tx = fx - x0f;
                int xA = min(max((int)x0f, 0), hp - 1);
                int xB = min(max((int)x0f + 1, 0), hp - 1);
                const float* P = P0 + c;
                float v00 = P[(yA * hp + xA) * 16], v01 = P[(yA * hp + xB) * 16];
                float v10 = P[(yB * hp + xA) * 16], v11 = P[(yB * hp + xB) * 16];
                float val = (1.f - ty) * ((1.f - tx) * v00 + tx * v01)
                          + ty * ((1.f - tx) * v10 + tx * v11);
                X2[px * 68 + 16 + lvl * 16 + c] = f2tf32(val);
            }
        }
    }
    __syncthreads();

    float a2c[4][4];
#pragma unroll
    for (int nb = 0; nb < 4; ++nb) a2c[nb][0] = a2c[nb][1] = a2c[nb][2] = a2c[nb][3] = 0.f;
    {
        const uint32_t* Ar0 = X2 + (m0 + g) * 68 + t;
        const uint32_t* Ar1 = X2 + (m0 + g + 8) * 68 + t;
        const uint32_t* Wc = W2 + (wn * 32 + g) * 68 + t;
#pragma unroll
        for (int k0 = 0; k0 < 64; k0 += 8) {
            uint32_t a0 = Ar0[k0], a1 = Ar1[k0];
            uint32_t a2 = Ar0[k0 + 4], a3 = Ar1[k0 + 4];
#pragma unroll
            for (int nb = 0; nb < 4; ++nb)
                mma_tf32(a2c[nb], a0, a1, a2, a3,
                         Wc[nb * 544 + k0], Wc[nb * 544 + k0 + 4]);
        }
    }
    float* o0 = out + (size_t)(tok0 + m0 + g) * 64;
    float* o1 = o0 + 8 * 64;
#pragma unroll
    for (int nb = 0; nb < 4; ++nb) {
        int col = wn * 32 + nb * 8 + 2 * t;
        float s0 = scs2[col], s1 = scs2[col + 1];
        float h0 = shs2[col], h1 = shs2[col + 1];
        float2 r0, r1;
        r0.x = fmaxf((a1c[nb][0] + a2c[nb][0]) * s0 + h0, 0.f);
        r0.y = fmaxf((a1c[nb][1] + a2c[nb][1]) * s1 + h1, 0.f);
        r1.x = fmaxf((a1c[nb][2] + a2c[nb][2]) * s0 + h0, 0.f);
        r1.y = fmaxf((a1c[nb][3] + a2c[nb][3]) * s1 + h1, 0.f);
        *(float2*)(o0 + col) = r0;
        *(float2*)(o1 + col) = r1;
    }
}

// ---------------- launch ---------------------------------------------------
extern "C" void kernel_launch(void* const* d_in, const int* in_sizes, int n_in,
                              void* d_out, int out_size) {
    const float* x       = (const float*)d_in[0];
    const float* conv_w  = (const float*)d_in[1];
    const float* conv_b  = (const float*)d_in[2];
    const float* bn_g    = (const float*)d_in[3];
    const float* bn_b    = (const float*)d_in[4];
    const float* bn_m    = (const float*)d_in[5];
    const float* bn_v    = (const float*)d_in[6];
    const float* q_w     = (const float*)d_in[7];
    const float* q_b     = (const float*)d_in[8];
    const float* k_w     = (const float*)d_in[9];
    const float* k_b     = (const float*)d_in[10];
    const float* v_w     = (const float*)d_in[11];
    const float* v_b     = (const float*)d_in[12];
    const float* attn_g  = (const float*)d_in[13];
    const float* ppl_w   = (const float*)d_in[14];
    const float* ppl_b   = (const float*)d_in[15];
    const float* ppl_bng = (const float*)d_in[16];
    const float* ppl_bnb = (const float*)d_in[17];
    const float* ppl_bnm = (const float*)d_in[18];
    const float* ppl_bnv = (const float*)d_in[19];
    const float* proj_w  = (const float*)d_in[20];
    const float* proj_b  = (const float*)d_in[21];
    const float* pbn_g   = (const float*)d_in[22];
    const float* pbn_b   = (const float*)d_in[23];
    const float* pbn_m   = (const float*)d_in[24];
    const float* pbn_v   = (const float*)d_in[25];
    float* out = (float*)d_out;

    const int CONV_SMEM = 26240 * 4;   // 104,960 B
    const int ATTN_SMEM = 14336 * 4;   // 57,344 B
    const int PROJ_SMEM = 24096 * 4;   // 96,384 B
    cudaFuncSetAttribute(k_conv, cudaFuncAttributeMaxDynamicSharedMemorySize, CONV_SMEM);
    cudaFuncSetAttribute(k_attn, cudaFuncAttributeMaxDynamicSharedMemorySize, ATTN_SMEM);
    cudaFuncSetAttribute(k_proj, cudaFuncAttributeMaxDynamicSharedMemorySize, PROJ_SMEM);

    k_conv<<<dim3(32, 8), 256, CONV_SMEM>>>(x, conv_w, conv_b, bn_g, bn_b, bn_m, bn_v,
                                            q_w, q_b, k_w, k_b, v_w, v_b);
    k_attn<<<dim3(32, 4, 2), 256, ATTN_SMEM>>>(attn_g);
    k_pool<<<dim3(408, 2), 256>>>(ppl_w, ppl_b, ppl_bng, ppl_bnb, ppl_bnm, ppl_bnv);
    k_proj<<<128, 256, PROJ_SMEM>>>(proj_w, proj_b, pbn_g, pbn_b, pbn_m, pbn_v,
                                    ppl_w, ppl_b, ppl_bng, ppl_bnb, ppl_bnm, ppl_bnv, out);
}

// round 16
// speedup vs baseline: 1.2683x; 1.0022x over previous
#include <cuda_runtime.h>
#include <cuda_bf16.h>
#include <math.h>
#include <stdint.h>

#define NB 4
#define BATCH 2
#define HW 4096
#define F 64
#define LOG2E 1.4426950408889634f

// ---------------- scratch (device globals; no allocation allowed) ----------
__device__ float    g_fused[BATCH * HW * 256];
__device__ uint32_t g_q[BATCH * NB * HW * 4];       // f16x2 pairs [pos][4]
__device__ uint32_t g_k[BATCH * NB * HW * 4];       // f16x2 pairs
__device__ uint32_t g_vp[BATCH * NB * 32 * 4096];   // f16x2 pairs, ldmatrix order
__device__ float    g_pool[NB * BATCH * HW * 16];

// ---------------- helpers ---------------------------------------------------
__device__ __forceinline__ uint32_t f2tf32(float f) {
    uint32_t r; asm("cvt.rna.tf32.f32 %0, %1;" : "=r"(r) : "f"(f)); return r;
}
__device__ __forceinline__ uint32_t packh(float hi, float lo) {
    uint32_t r; asm("cvt.rn.f16x2.f32 %0, %1, %2;" : "=r"(r) : "f"(hi), "f"(lo)); return r;
}
__device__ __forceinline__ uint32_t ex2h2(uint32_t x) {
    uint32_t y; asm("ex2.approx.f16x2 %0, %1;" : "=r"(y) : "r"(x)); return y;
}
__device__ __forceinline__ void mma_tf32(float c[4], uint32_t a0, uint32_t a1,
                                         uint32_t a2, uint32_t a3,
                                         uint32_t b0, uint32_t b1) {
    asm volatile(
        "mma.sync.aligned.m16n8k8.row.col.f32.tf32.tf32.f32 "
        "{%0,%1,%2,%3},{%4,%5,%6,%7},{%8,%9},{%0,%1,%2,%3};"
        : "+f"(c[0]), "+f"(c[1]), "+f"(c[2]), "+f"(c[3])
        : "r"(a0), "r"(a1), "r"(a2), "r"(a3), "r"(b0), "r"(b1));
}
__device__ __forceinline__ void mma_f16(float c[4], uint32_t a0, uint32_t a1,
                                        uint32_t a2, uint32_t a3,
                                        uint32_t b0, uint32_t b1) {
    asm volatile(
        "mma.sync.aligned.m16n8k16.row.col.f32.f16.f16.f32 "
        "{%0,%1,%2,%3},{%4,%5,%6,%7},{%8,%9},{%0,%1,%2,%3};"
        : "+f"(c[0]), "+f"(c[1]), "+f"(c[2]), "+f"(c[3])
        : "r"(a0), "r"(a1), "r"(a2), "r"(a3), "r"(b0), "r"(b1));
}
// QK: f16 accumulator -> scores arrive pre-packed as f16x2
__device__ __forceinline__ void mma_f16k8h(uint32_t& d0, uint32_t& d1,
                                           uint32_t a0, uint32_t a1, uint32_t b0) {
    asm volatile(
        "mma.sync.aligned.m16n8k8.row.col.f16.f16.f16.f16 "
        "{%0,%1},{%2,%3},{%4},{%5,%6};"
        : "=r"(d0), "=r"(d1)
        : "r"(a0), "r"(a1), "r"(b0), "r"(0u), "r"(0u));
}
__device__ __forceinline__ void ldsm_x4(uint32_t& r0, uint32_t& r1,
                                        uint32_t& r2, uint32_t& r3, uint32_t addr) {
    asm volatile("ldmatrix.sync.aligned.m8n8.x4.shared.b16 {%0,%1,%2,%3}, [%4];"
        : "=r"(r0), "=r"(r1), "=r"(r2), "=r"(r3) : "r"(addr));
}
__device__ __forceinline__ void cpa16(uint32_t s, const void* g) {
    asm volatile("cp.async.cg.shared.global [%0], [%1], 16;" :: "r"(s), "l"(g));
}
__device__ __forceinline__ void cpa16z(uint32_t s, const void* g, int sz) {
    asm volatile("cp.async.cg.shared.global [%0], [%1], 16, %2;" :: "r"(s), "l"(g), "r"(sz));
}

// ---------------- K1: dilated conv + fused QKV (unchanged) -----------------
__global__ void __launch_bounds__(256, 2) k_conv(
        const float* __restrict__ x, const float* __restrict__ wg,
        const float* __restrict__ cb, const float* __restrict__ bg,
        const float* __restrict__ bbe, const float* __restrict__ bm,
        const float* __restrict__ bv,
        const float* __restrict__ qw, const float* __restrict__ qb,
        const float* __restrict__ kw, const float* __restrict__ kb_,
        const float* __restrict__ vw, const float* __restrict__ vb) {
    extern __shared__ uint32_t dyn[];
    uint32_t* Vt = dyn + 8704;
    uint32_t* QW = dyn + 12928;
    uint32_t* KW = dyn + 13472;
    float* vbs = (float*)(dyn + 14016);
    float* qkb = (float*)(dyn + 14080);
    float* scs = (float*)(dyn + 26112);
    float* shs = (float*)(dyn + 26176);

    int tid = threadIdx.x;
    int bb = blockIdx.y, b = bb >> 2, br = bb & 3;
    int d = 1 << br;
    int pix0 = blockIdx.x * 128;
    int y0 = blockIdx.x * 2;

    if (tid < 64) {
        int idx = br * 64 + tid;
        float sc = bg[idx] * rsqrtf(bv[idx] + 1e-3f);
        scs[tid] = sc;
        shs[tid] = bbe[idx] - bm[idx] * sc + cb[idx] * sc;
    }

    int w = tid >> 5, lane = tid & 31;
    int g = lane >> 2, t = lane & 3;
    int m0 = w * 16;

    float c[8][4];
#pragma unroll
    for (int nb = 0; nb < 8; ++nb) c[nb][0] = c[nb][1] = c[nb][2] = c[nb][3] = 0.f;

    int p = tid >> 1, ch = (tid & 1) * 32;
    int prow = p >> 6, pcol = p & 63;
    int wci0 = tid >> 4, wco4 = (tid & 15) * 4;

    uint32_t sh0 = (uint32_t)__cvta_generic_to_shared(dyn);
    uint32_t a_dst0 = sh0 + (uint32_t)((p * 68 + ch) * 4);
    const float* xb = x + (size_t)b * 64 * 64 * 64;
    const float* wbase = wg + (size_t)br * 9 * 4096;

#define PREFETCH_A(tap, bi) do {                                             \
        int ky_ = (tap) / 3, kx_ = (tap) - ky_ * 3;                          \
        int iy_ = y0 + prow + d * (ky_ - 1);                                 \
        int ix_ = pcol + d * (kx_ - 1);                                      \
        int val_ = (((unsigned)iy_ < 64u) & ((unsigned)ix_ < 64u)) ? 16 : 0; \
        int iyc_ = min(max(iy_, 0), 63), ixc_ = min(max(ix_, 0), 63);        \
        const float* asrc_ = xb + (((size_t)iyc_ * 64 + ixc_) * 64 + ch);    \
        uint32_t ad_ = a_dst0 + (uint32_t)(bi) * 34816u;                     \
        _Pragma("unroll")                                                    \
        for (int i_ = 0; i_ < 8; ++i_) cpa16z(ad_ + i_ * 16, asrc_ + i_ * 4, val_); \
        asm volatile("cp.async.commit_group;");                              \
    } while (0)

    PREFETCH_A(0, 0);
    PREFETCH_A(1, 1);
    {
        uint32_t* W0 = dyn + 17408;
#pragma unroll
        for (int i = 0; i < 4; ++i) {
            int ci = wci0 + i * 16;
            float4 v = *(const float4*)(wbase + ci * 64 + wco4);
            W0[(wco4 + 0) * 68 + ci] = f2tf32(v.x);
            W0[(wco4 + 1) * 68 + ci] = f2tf32(v.y);
            W0[(wco4 + 2) * 68 + ci] = f2tf32(v.z);
            W0[(wco4 + 3) * 68 + ci] = f2tf32(v.w);
        }
    }
    asm volatile("cp.async.wait_group 1;");
    __syncthreads();

#pragma unroll 1
    for (int tap = 0; tap < 9; ++tap) {
        float4 wr[4];
        if (tap + 1 < 9) {
            const float* wt1 = wbase + (size_t)(tap + 1) * 4096;
#pragma unroll
            for (int i = 0; i < 4; ++i)
                wr[i] = *(const float4*)(wt1 + (wci0 + i * 16) * 64 + wco4);
        }
        const uint32_t* Ab = dyn + (tap & 1) * 8704;
        const uint32_t* Wb = dyn + 17408 + (tap & 1) * 4352;
        const uint32_t* Ar0 = Ab + (m0 + g) * 68 + t;
        const uint32_t* Ar1 = Ab + (m0 + g + 8) * 68 + t;
        const uint32_t* Wg_ = Wb + g * 68 + t;
#pragma unroll
        for (int k0 = 0; k0 < 64; k0 += 8) {
            uint32_t a0 = Ar0[k0], a1 = Ar1[k0];
            uint32_t a2 = Ar0[k0 + 4], a3 = Ar1[k0 + 4];
#pragma unroll
            for (int nb = 0; nb < 8; ++nb)
                mma_tf32(c[nb], a0, a1, a2, a3,
                         Wg_[nb * 8 * 68 + k0], Wg_[nb * 8 * 68 + k0 + 4]);
        }
        if (tap + 1 < 9) {
            uint32_t* Wn = dyn + 17408 + ((tap + 1) & 1) * 4352;
#pragma unroll
            for (int i = 0; i < 4; ++i) {
                int ci = wci0 + i * 16;
                Wn[(wco4 + 0) * 68 + ci] = f2tf32(wr[i].x);
                Wn[(wco4 + 1) * 68 + ci] = f2tf32(wr[i].y);
                Wn[(wco4 + 2) * 68 + ci] = f2tf32(wr[i].z);
                Wn[(wco4 + 3) * 68 + ci] = f2tf32(wr[i].w);
            }
        }
        __syncthreads();
        if (tap + 2 < 9) {
            PREFETCH_A(tap + 2, (tap & 1));
            asm volatile("cp.async.wait_group 1;");
            __syncthreads();
        } else if (tap + 1 < 9) {
            asm volatile("cp.async.wait_group 0;");
            __syncthreads();
        }
    }
#undef PREFETCH_A

    float rv[8][4];
    float* f0 = g_fused + ((size_t)b * HW + pix0 + m0 + g) * 256 + br * 64;
    float* f1 = f0 + 8 * 256;
#pragma unroll
    for (int nb = 0; nb < 8; ++nb) {
        int col = nb * 8 + 2 * t;
        rv[nb][0] = fmaxf(c[nb][0] * scs[col] + shs[col], 0.f);
        rv[nb][1] = fmaxf(c[nb][1] * scs[col + 1] + shs[col + 1], 0.f);
        rv[nb][2] = fmaxf(c[nb][2] * scs[col] + shs[col], 0.f);
        rv[nb][3] = fmaxf(c[nb][3] * scs[col + 1] + shs[col + 1], 0.f);
        *(float2*)(f0 + col) = make_float2(rv[nb][0], rv[nb][1]);
        *(float2*)(f1 + col) = make_float2(rv[nb][2], rv[nb][3]);
    }
    __syncthreads();
    uint32_t* As = dyn;
#pragma unroll
    for (int nb = 0; nb < 8; ++nb) {
        int col = nb * 8 + 2 * t;
        *(uint2*)&As[(m0 + g) * 68 + col] =
            make_uint2(f2tf32(rv[nb][0]), f2tf32(rv[nb][1]));
        *(uint2*)&As[(m0 + g + 8) * 68 + col] =
            make_uint2(f2tf32(rv[nb][2]), f2tf32(rv[nb][3]));
    }
    uint32_t* Wv = dyn + 17408;
#pragma unroll
    for (int i = 0; i < 4; ++i) {
        int ci = wci0 + i * 16;
        float4 v = *(const float4*)(vw + br * 4096 + ci * 64 + wco4);
        Wv[(wco4 + 0) * 68 + ci] = f2tf32(v.x);
        Wv[(wco4 + 1) * 68 + ci] = f2tf32(v.y);
        Wv[(wco4 + 2) * 68 + ci] = f2tf32(v.z);
        Wv[(wco4 + 3) * 68 + ci] = f2tf32(v.w);
    }
    if (tid < 128) {
        int ci = tid >> 1, d4 = (tid & 1) * 4;
        float4 v = *(const float4*)(qw + br * 512 + ci * 8 + d4);
        QW[(d4 + 0) * 68 + ci] = f2tf32(v.x * LOG2E);
        QW[(d4 + 1) * 68 + ci] = f2tf32(v.y * LOG2E);
        QW[(d4 + 2) * 68 + ci] = f2tf32(v.z * LOG2E);
        QW[(d4 + 3) * 68 + ci] = f2tf32(v.w * LOG2E);
    } else {
        int id = tid - 128;
        int ci = id >> 1, d4 = (id & 1) * 4;
        float4 v = *(const float4*)(kw + br * 512 + ci * 8 + d4);
        KW[(d4 + 0) * 68 + ci] = f2tf32(v.x);
        KW[(d4 + 1) * 68 + ci] = f2tf32(v.y);
        KW[(d4 + 2) * 68 + ci] = f2tf32(v.z);
        KW[(d4 + 3) * 68 + ci] = f2tf32(v.w);
    }
    if (tid < 64) vbs[tid] = vb[br * 64 + tid];
    if (tid >= 64 && tid < 72) qkb[tid - 64] = qb[br * 8 + tid - 64] * LOG2E;
    if (tid >= 72 && tid < 80) qkb[8 + tid - 72] = kb_[br * 8 + tid - 72];
    __syncthreads();
    const uint32_t* Ar0 = As + (m0 + g) * 68 + t;
    const uint32_t* Ar1 = As + (m0 + g + 8) * 68 + t;
    const uint32_t* Wg_ = Wv + g * 68 + t;
    float vac[8][4];
#pragma unroll
    for (int nb = 0; nb < 8; ++nb) vac[nb][0] = vac[nb][1] = vac[nb][2] = vac[nb][3] = 0.f;
#pragma unroll
    for (int k0 = 0; k0 < 64; k0 += 8) {
        uint32_t a0 = Ar0[k0], a1 = Ar1[k0];
        uint32_t a2 = Ar0[k0 + 4], a3 = Ar1[k0 + 4];
#pragma unroll
        for (int nb = 0; nb < 8; ++nb)
            mma_tf32(vac[nb], a0, a1, a2, a3, Wg_[nb * 8 * 68 + k0], Wg_[nb * 8 * 68 + k0 + 4]);
    }
    float qa_[4] = {0.f, 0.f, 0.f, 0.f}, ka_[4] = {0.f, 0.f, 0.f, 0.f};
    const uint32_t* Qg_ = QW + g * 68 + t;
    const uint32_t* Kg_ = KW + g * 68 + t;
#pragma unroll
    for (int k0 = 0; k0 < 64; k0 += 8) {
        uint32_t a0 = Ar0[k0], a1 = Ar1[k0];
        uint32_t a2 = Ar0[k0 + 4], a3 = Ar1[k0 + 4];
        mma_tf32(qa_, a0, a1, a2, a3, Qg_[k0], Qg_[k0 + 4]);
        mma_tf32(ka_, a0, a1, a2, a3, Kg_[k0], Kg_[k0 + 4]);
    }
    {
        float b0f = qkb[2 * t], b1f = qkb[2 * t + 1];
        uint32_t* qd = g_q + ((size_t)bb * HW + pix0 + m0 + g) * 4 + t;
        qd[0]  = packh(qa_[1] + b1f, qa_[0] + b0f);
        qd[32] = packh(qa_[3] + b1f, qa_[2] + b0f);
        float c0f = qkb[8 + 2 * t], c1f = qkb[8 + 2 * t + 1];
        uint32_t* kd = g_k + ((size_t)bb * HW + pix0 + m0 + g) * 4 + t;
        kd[0]  = packh(ka_[1] + c1f, ka_[0] + c0f);
        kd[32] = packh(ka_[3] + c1f, ka_[2] + c0f);
    }
#pragma unroll
    for (int nb = 0; nb < 8; ++nb) {
        int col = nb * 8 + 2 * t;
        Vt[(m0 + g) * 33 + nb * 4 + t] =
            packh(vac[nb][1] + vbs[col + 1], vac[nb][0] + vbs[col]);
        Vt[(m0 + g + 8) * 33 + nb * 4 + t] =
            packh(vac[nb][3] + vbs[col + 1], vac[nb][2] + vbs[col]);
    }
    __syncthreads();
    uint32_t* vout = g_vp + ((size_t)bb * 32 + blockIdx.x) * 4096;
#pragma unroll
    for (int i = 0; i < 16; ++i) {
        int o = tid + i * 256;
        int col = o & 3, row = (o >> 2) & 7, mat = o >> 5;
        int kpt = ((mat >> 3) << 2) | col;
        int cch = ((mat & 7) << 3) | row;
        uint32_t lo = Vt[(2 * kpt) * 33 + (cch >> 1)];
        uint32_t hi = Vt[(2 * kpt + 1) * 33 + (cch >> 1)];
        vout[o] = (cch & 1) ? ((lo >> 16) | (hi & 0xFFFF0000u))
                            : ((lo & 0xFFFFu) | (hi << 16));
    }
}

// ---------------- K3: flash attention, K fragments via ldmatrix ------------
__global__ void __launch_bounds__(256, 2) k_attn(const float* __restrict__ gamma) {
    extern __shared__ uint32_t dsh[];
    uint32_t* Qs = dsh;
    int tid = threadIdx.x;
    int br = blockIdx.y, b = blockIdx.z;
    int bb = b * NB + br;
    int n0 = blockIdx.x * 128;
    int w = tid >> 5, lane = tid & 31;
    int g = lane >> 2, t = lane & 3;

    const uint32_t* kgm = g_k + (size_t)bb * HW * 4;
    const uint32_t* vgm = g_vp + (size_t)bb * 32 * 4096;

    uint32_t shb = (uint32_t)__cvta_generic_to_shared(dsh);
    uint32_t ksa[3], vsa[3];
#pragma unroll
    for (int i = 0; i < 3; ++i) {
        ksa[i] = shb + (512u + i * 512u) * 4u;
        vsa[i] = shb + (2048u + i * 4096u) * 4u;
    }

    if (tid < 128) cpa16(ksa[0] + tid * 16, kgm + tid * 4);
#pragma unroll
    for (int j = 0; j < 4; ++j)
        cpa16(vsa[0] + (tid + j * 256) * 16, vgm + (tid + j * 256) * 4);
    asm volatile("cp.async.commit_group;");
    if (tid < 128)
        ((uint4*)Qs)[tid] = ((const uint4*)(g_q + ((size_t)bb * HW + n0) * 4))[tid];
    if (tid < 128) cpa16(ksa[1] + tid * 16, kgm + 512 + tid * 4);
#pragma unroll
    for (int j = 0; j < 4; ++j)
        cpa16(vsa[1] + (tid + j * 256) * 16, vgm + 4096 + (tid + j * 256) * 4);
    asm volatile("cp.async.commit_group;");
    __syncthreads();

    int r0i = w * 16 + g;
    uint32_t qa0 = Qs[r0i * 4 + t];
    uint32_t qa1 = Qs[(r0i + 8) * 4 + t];

    int midx = lane >> 3;
    int lane_const = (midx & 1) * 8 + (midx >> 1);
    uint32_t lboff = (uint32_t)((lane_const * 32 + (lane & 7) * 4) * 4);
    // K ldmatrix: lane l -> matrix (l>>3), row (l&7); key = mat*8 + row, 16 B/row
    uint32_t kfoff = (uint32_t)((((lane >> 3) * 8 + (lane & 7)) * 16));

    float o[8][4];
#pragma unroll
    for (int nb = 0; nb < 8; ++nb) { o[nb][0] = o[nb][1] = o[nb][2] = o[nb][3] = 0.f; }
    float zc[4] = {0.f, 0.f, 0.f, 0.f};
    const uint32_t ONES = 0x3C003C00u;

    int cur = 0, pf = 2;
#pragma unroll 1
    for (int it = 0; it < 32; ++it) {
        if (it < 31) asm volatile("cp.async.wait_group 1;");
        else         asm volatile("cp.async.wait_group 0;");
        __syncthreads();
        uint32_t kb_base = ksa[cur] + kfoff;
        uint32_t lb = vsa[cur] + lboff;

        uint32_t pa[16][2];
#pragma unroll
        for (int j4 = 0; j4 < 4; ++j4) {
            uint32_t kb0, kb1, kb2, kb3;
            ldsm_x4(kb0, kb1, kb2, kb3, kb_base + (uint32_t)(j4 * 512));
            uint32_t d0, d1;
            mma_f16k8h(d0, d1, qa0, qa1, kb0);
            pa[j4 * 4 + 0][0] = ex2h2(d0); pa[j4 * 4 + 0][1] = ex2h2(d1);
            mma_f16k8h(d0, d1, qa0, qa1, kb1);
            pa[j4 * 4 + 1][0] = ex2h2(d0); pa[j4 * 4 + 1][1] = ex2h2(d1);
            mma_f16k8h(d0, d1, qa0, qa1, kb2);
            pa[j4 * 4 + 2][0] = ex2h2(d0); pa[j4 * 4 + 2][1] = ex2h2(d1);
            mma_f16k8h(d0, d1, qa0, qa1, kb3);
            pa[j4 * 4 + 3][0] = ex2h2(d0); pa[j4 * 4 + 3][1] = ex2h2(d1);
        }
#pragma unroll
        for (int ks = 0; ks < 8; ++ks) {
#pragma unroll
            for (int nbp = 0; nbp < 4; ++nbp) {
                uint32_t b00, b10, b01, b11;
                ldsm_x4(b00, b10, b01, b11, lb + (uint32_t)((16 * ks + 2 * nbp) * 128));
                mma_f16(o[2 * nbp], pa[2 * ks][0], pa[2 * ks][1],
                        pa[2 * ks + 1][0], pa[2 * ks + 1][1], b00, b10);
                mma_f16(o[2 * nbp + 1], pa[2 * ks][0], pa[2 * ks][1],
                        pa[2 * ks + 1][0], pa[2 * ks + 1][1], b01, b11);
            }
            mma_f16(zc, pa[2 * ks][0], pa[2 * ks][1],
                    pa[2 * ks + 1][0], pa[2 * ks + 1][1], ONES, ONES);
        }
        if (it + 2 < 32) {
            int t2 = it + 2;
            if (tid < 128) cpa16(ksa[pf] + tid * 16, kgm + (size_t)t2 * 512 + tid * 4);
#pragma unroll
            for (int j = 0; j < 4; ++j)
                cpa16(vsa[pf] + (tid + j * 256) * 16,
                      vgm + (size_t)t2 * 4096 + (tid + j * 256) * 4);
            asm volatile("cp.async.commit_group;");
        }
        cur = (cur == 2) ? 0 : cur + 1;
        pf = (pf == 2) ? 0 : pf + 1;
    }
    float ga = gamma[br];
    float i0 = ga / zc[0], i1 = ga / zc[2];
    float* base0 = g_fused + ((size_t)b * HW + n0 + w * 16 + g) * 256 + br * 64 + 2 * t;
    float* base1 = base0 + 8 * 256;
#pragma unroll
    for (int nb = 0; nb < 8; ++nb) {
        float2 v0 = *(float2*)(base0 + nb * 8);
        v0.x += o[nb][0] * i0; v0.y += o[nb][1] * i0;
        *(float2*)(base0 + nb * 8) = v0;
        float2 v1 = *(float2*)(base1 + nb * 8);
        v1.x += o[nb][2] * i1; v1.y += o[nb][3] * i1;
        *(float2*)(base1 + nb * 8) = v1;
    }
}

// ---------------- K4: pool (unchanged) -------------------------------------
template<int PS, int PLO>
__device__ __forceinline__ float4 pool_win4(int b, int oy, int ox, int c4) {
    int ys0 = oy * PS - PLO, xs0 = ox * PS - PLO;
    float4 s = make_float4(0.f, 0.f, 0.f, 0.f);
    int cnt = 0;
#pragma unroll
    for (int dy = 0; dy < PS; ++dy) {
        int yy = ys0 + dy;
        bool vy = (unsigned)yy < 64u;
        int yyc = min(max(yy, 0), 63);
#pragma unroll
        for (int dx = 0; dx < PS; ++dx) {
            int xx = xs0 + dx;
            bool v = vy && ((unsigned)xx < 64u);
            int xxc = min(max(xx, 0), 63);
            float4 val = *(const float4*)(g_fused + ((size_t)(b * HW) + yyc * 64 + xxc) * 256 + c4);
            if (v) { s.x += val.x; s.y += val.y; s.z += val.z; s.w += val.w; ++cnt; }
        }
    }
    float inv = 1.f / (float)cnt;
    s.x *= inv; s.y *= inv; s.z *= inv; s.w *= inv;
    return s;
}

__global__ void k_pool(const float* __restrict__ pw, const float* __restrict__ pb,
                       const float* __restrict__ pg, const float* __restrict__ pbe,
                       const float* __restrict__ pm, const float* __restrict__ pv) {
    __shared__ float avg[4][256];
    __shared__ float part[4][64];
    int b = blockIdx.y;
    int slot = threadIdx.x >> 6;
    int l64 = threadIdx.x & 63;
    int lin = blockIdx.x * 4 + slot;
    bool valid = lin < 1629;
    int linc = valid ? lin : 1628;
    int j, r;
    if (linc < 1024)      { j = 1; r = linc; }
    else if (linc < 1508) { j = 2; r = linc - 1024; }
    else                  { j = 3; r = linc - 1508; }
    const int HPs[4] = {64, 32, 22, 11};
    int hp = HPs[j];
    int oy = r / hp, ox = r % hp;
    int c4 = l64 * 4;
    float4 s;
    if (j == 1)      s = pool_win4<2, 0>(b, oy, ox, c4);
    else if (j == 2) s = pool_win4<3, 1>(b, oy, ox, c4);
    else             s = pool_win4<6, 1>(b, oy, ox, c4);
    *(float4*)&avg[slot][c4] = s;
    __syncthreads();
    int o = l64 & 15, q = l64 >> 4;
    const float* wp = pw + j * 4096 + o;
    float a = 0.f;
#pragma unroll 16
    for (int i = 0; i < 64; ++i) {
        int ci = q * 64 + i;
        a += avg[slot][ci] * wp[ci * 16];
    }
    part[slot][q * 16 + o] = a;
    __syncthreads();
    if (l64 < 16 && valid) {
        float acc = pb[j * 16 + l64] + part[slot][l64] + part[slot][16 + l64]
                  + part[slot][32 + l64] + part[slot][48 + l64];
        int idx = j * 16 + l64;
        float sc = pg[idx] * rsqrtf(pv[idx] + 1e-3f);
        float sh = pbe[idx] - pm[idx] * sc;
        g_pool[((size_t)((j * 2 + b) * HW) + oy * hp + ox) * 16 + l64] = acc * sc + sh;
    }
}

// ---------------- K5: proj GEMM (unchanged) --------------------------------
__global__ void __launch_bounds__(256) k_proj(
        const float* __restrict__ w, const float* __restrict__ pb,
        const float* __restrict__ g2, const float* __restrict__ be,
        const float* __restrict__ m, const float* __restrict__ v,
        const float* __restrict__ pplw, const float* __restrict__ pplb,
        const float* __restrict__ ppg, const float* __restrict__ ppbe,
        const float* __restrict__ ppm, const float* __restrict__ ppv,
        float* __restrict__ out) {
    extern __shared__ uint32_t dyn[];
    uint32_t* W2 = dyn + 19584;
    float* scs2 = (float*)(dyn + 23936);
    float* shs2 = (float*)(dyn + 24000);
    float* psc = (float*)(dyn + 24064);
    float* psh = (float*)(dyn + 24080);

    int tid = threadIdx.x;
    int tok0 = blockIdx.x * 64;
    int b2 = tok0 >> 12;
    int yy = (tok0 & 4095) >> 6;
    int w_ = tid >> 5, lane = tid & 31;
    int wm = w_ & 3, wn = w_ >> 2;
    int g = lane >> 2, t = lane & 3;
    int m0 = wm * 16;

    int p4 = tid >> 2, cs = (tid & 3) * 16;
    const float* asrc = g_fused + (size_t)(tok0 + p4) * 256 + cs;
    float4 ar[4];
    int wcl = tid >> 4, wco4 = (tid & 15) * 4;
    int wsc4 = wco4 + (wco4 >= 32 ? 8 : 0);
    int qcl = tid >> 2, qo4 = (tid & 3) * 4;
    int qsc4 = (qo4 < 8) ? (32 + qo4) : (64 + qo4);

#define LOADA(ck) do {                                                      \
        const float* s_ = asrc + (ck) * 64;                                 \
        ar[0] = *(const float4*)(s_);      ar[1] = *(const float4*)(s_ + 4); \
        ar[2] = *(const float4*)(s_ + 8);  ar[3] = *(const float4*)(s_ + 12); \
    } while (0)
#define STOREA(bi) do {                                                     \
        uint32_t* d_ = dyn + (bi) * 4352 + p4 * 68 + cs;                    \
        _Pragma("unroll")                                                   \
        for (int i_ = 0; i_ < 4; ++i_) {                                    \
            *(uint2*)(d_ + i_ * 4) =                                        \
                make_uint2(f2tf32(ar[i_].x), f2tf32(ar[i_].y));             \
            *(uint2*)(d_ + i_ * 4 + 2) =                                    \
                make_uint2(f2tf32(ar[i_].z), f2tf32(ar[i_].w));             \
        }                                                                   \
    } while (0)

    LOADA(0); STOREA(0);
    {
        uint32_t* Wb0 = dyn + 8704;
#pragma unroll
        for (int i = 0; i < 4; ++i) {
            int cl = wcl + i * 16;
            float4 vv = *(const float4*)(w + cl * 64 + wco4);
            Wb0[(wsc4 + 0) * 68 + cl] = f2tf32(vv.x);
            Wb0[(wsc4 + 1) * 68 + cl] = f2tf32(vv.y);
            Wb0[(wsc4 + 2) * 68 + cl] = f2tf32(vv.z);
            Wb0[(wsc4 + 3) * 68 + cl] = f2tf32(vv.w);
        }
        float4 vv = *(const float4*)(pplw + qcl * 16 + qo4);
        Wb0[(qsc4 + 0) * 68 + qcl] = f2tf32(vv.x);
        Wb0[(qsc4 + 1) * 68 + qcl] = f2tf32(vv.y);
        Wb0[(qsc4 + 2) * 68 + qcl] = f2tf32(vv.z);
        Wb0[(qsc4 + 3) * 68 + qcl] = f2tf32(vv.w);
    }
#pragma unroll
    for (int i = 0; i < 4; ++i) {
        int id = tid + i * 256;
        int k = id >> 4, co4 = (id & 15) * 4;
        float4 vv = *(const float4*)(w + (256 + k) * 64 + co4);
        W2[(co4 + 0) * 68 + k] = f2tf32(vv.x);
        W2[(co4 + 1) * 68 + k] = f2tf32(vv.y);
        W2[(co4 + 2) * 68 + k] = f2tf32(vv.z);
        W2[(co4 + 3) * 68 + k] = f2tf32(vv.w);
    }
    if (tid < 64) {
        float sc = g2[tid] * rsqrtf(v[tid] + 1e-3f);
        scs2[tid] = sc;
        shs2[tid] = be[tid] - m[tid] * sc + pb[tid] * sc;
    } else if (tid < 80) {
        int o = tid - 64;
        float sc = ppg[o] * rsqrtf(ppv[o] + 1e-3f);
        psc[o] = sc;
        psh[o] = ppbe[o] - ppm[o] * sc + pplb[o] * sc;
    }
    LOADA(1);
    __syncthreads();

    float a1c[5][4];
#pragma unroll
    for (int nb = 0; nb < 5; ++nb) a1c[nb][0] = a1c[nb][1] = a1c[nb][2] = a1c[nb][3] = 0.f;
    int wn40 = wn * 40;
#pragma unroll 1
    for (int ck = 0; ck < 4; ++ck) {
        float4 wrp[4], wrq;
        if (ck + 1 < 4) {
            int cb = (ck + 1) * 64;
#pragma unroll
            for (int i = 0; i < 4; ++i)
                wrp[i] = *(const float4*)(w + (cb + wcl + i * 16) * 64 + wco4);
            wrq = *(const float4*)(pplw + (cb + qcl) * 16 + qo4);
        }
        const uint32_t* Ab = dyn + (ck & 1) * 4352;
        const uint32_t* Ar0 = Ab + (m0 + g) * 68 + t;
        const uint32_t* Ar1 = Ab + (m0 + g + 8) * 68 + t;
        const uint32_t* Wc = dyn + 8704 + (ck & 1) * 5440 + (wn40 + g) * 68 + t;
#pragma unroll
        for (int k0 = 0; k0 < 64; k0 += 8) {
            uint32_t a0 = Ar0[k0], a1 = Ar1[k0];
            uint32_t a2 = Ar0[k0 + 4], a3 = Ar1[k0 + 4];
#pragma unroll
            for (int nb = 0; nb < 5; ++nb)
                mma_tf32(a1c[nb], a0, a1, a2, a3,
                         Wc[nb * 544 + k0], Wc[nb * 544 + k0 + 4]);
        }
        if (ck + 1 < 4) {
            uint32_t* Wn = dyn + 8704 + ((ck + 1) & 1) * 5440;
#pragma unroll
            for (int i = 0; i < 4; ++i) {
                int cl = wcl + i * 16;
                Wn[(wsc4 + 0) * 68 + cl] = f2tf32(wrp[i].x);
                Wn[(wsc4 + 1) * 68 + cl] = f2tf32(wrp[i].y);
                Wn[(wsc4 + 2) * 68 + cl] = f2tf32(wrp[i].z);
                Wn[(wsc4 + 3) * 68 + cl] = f2tf32(wrp[i].w);
            }
            Wn[(qsc4 + 0) * 68 + qcl] = f2tf32(wrq.x);
            Wn[(qsc4 + 1) * 68 + qcl] = f2tf32(wrq.y);
            Wn[(qsc4 + 2) * 68 + qcl] = f2tf32(wrq.z);
            Wn[(qsc4 + 3) * 68 + qcl] = f2tf32(wrq.w);
            STOREA((ck + 1) & 1);
        }
        __syncthreads();
        if (ck + 2 < 4) LOADA(ck + 2);
    }
#undef LOADA
#undef STOREA

    uint32_t* X2 = dyn;
    {
        int o = wn * 8 + 2 * t;
        float s0 = psc[o], s1 = psc[o + 1], h0 = psh[o], h1 = psh[o + 1];
        *(uint2*)&X2[(m0 + g) * 68 + o] =
            make_uint2(f2tf32(a1c[4][0] * s0 + h0), f2tf32(a1c[4][1] * s1 + h1));
        *(uint2*)&X2[(m0 + g + 8) * 68 + o] =
            make_uint2(f2tf32(a1c[4][2] * s0 + h0), f2tf32(a1c[4][3] * s1 + h1));
    }
    {
        const int HP[3] = {32, 22, 11};
#pragma unroll
        for (int lvl = 0; lvl < 3; ++lvl) {
            int hp = HP[lvl];
            float scale = hp * (1.f / 64.f);
            const float* P0 = g_pool + (size_t)(((lvl + 1) * 2 + b2) * HW) * 16;
            float fy = (yy + 0.5f) * scale - 0.5f;
            float y0f = floorf(fy);
            float ty = fy - y0f;
            int yA = min(max((int)y0f, 0), hp - 1);
            int yB = min(max((int)y0f + 1, 0), hp - 1);
#pragma unroll
            for (int i = 0; i < 4; ++i) {
                int id = tid + i * 256;
                int px = id >> 4, c = id & 15;
                float fx = (px + 0.5f) * scale - 0.5f;
                float x0f = floorf(fx);
                float tx = fx - x0f;
                int xA = min(max((int)x0f, 0), hp - 1);
                int xB = min(max((int)x0f + 1, 0), hp - 1);
                const float* P = P0 + c;
                float v00 = P[(yA * hp + xA) * 16], v01 = P[(yA * hp + xB) * 16];
                float v10 = P[(yB * hp + xA) * 16], v11 = P[(yB * hp + xB) * 16];
                float val = (1.f - ty) * ((1.f - tx) * v00 + tx * v01)
                          + ty * ((1.f - tx) * v10 + tx * v11);
                X2[px * 68 + 16 + lvl * 16 + c] = f2tf32(val);
            }
        }
    }
    __syncthreads();

    float a2c[4][4];
#pragma unroll
    for (int nb = 0; nb < 4; ++nb) a2c[nb][0] = a2c[nb][1] = a2c[nb][2] = a2c[nb][3] = 0.f;
    {
        const uint32_t* Ar0 = X2 + (m0 + g) * 68 + t;
        const uint32_t* Ar1 = X2 + (m0 + g + 8) * 68 + t;
        const uint32_t* Wc = W2 + (wn * 32 + g) * 68 + t;
#pragma unroll
        for (int k0 = 0; k0 < 64; k0 += 8) {
            uint32_t a0 = Ar0[k0], a1 = Ar1[k0];
            uint32_t a2 = Ar0[k0 + 4], a3 = Ar1[k0 + 4];
#pragma unroll
            for (int nb = 0; nb < 4; ++nb)
                mma_tf32(a2c[nb], a0, a1, a2, a3,
                         Wc[nb * 544 + k0], Wc[nb * 544 + k0 + 4]);
        }
    }
    float* o0 = out + (size_t)(tok0 + m0 + g) * 64;
    float* o1 = o0 + 8 * 64;
#pragma unroll
    for (int nb = 0; nb < 4; ++nb) {
        int col = wn * 32 + nb * 8 + 2 * t;
        float s0 = scs2[col], s1 = scs2[col + 1];
        float h0 = shs2[col], h1 = shs2[col + 1];
        float2 r0, r1;
        r0.x = fmaxf((a1c[nb][0] + a2c[nb][0]) * s0 + h0, 0.f);
        r0.y = fmaxf((a1c[nb][1] + a2c[nb][1]) * s1 + h1, 0.f);
        r1.x = fmaxf((a1c[nb][2] + a2c[nb][2]) * s0 + h0, 0.f);
        r1.y = fmaxf((a1c[nb][3] + a2c[nb][3]) * s1 + h1, 0.f);
        *(float2*)(o0 + col) = r0;
        *(float2*)(o1 + col) = r1;
    }
}

// ---------------- launch ---------------------------------------------------
extern "C" void kernel_launch(void* const* d_in, const int* in_sizes, int n_in,
                              void* d_out, int out_size) {
    const float* x       = (const float*)d_in[0];
    const float* conv_w  = (const float*)d_in[1];
    const float* conv_b  = (const float*)d_in[2];
    const float* bn_g    = (const float*)d_in[3];
    const float* bn_b    = (const float*)d_in[4];
    const float* bn_m    = (const float*)d_in[5];
    const float* bn_v    = (const float*)d_in[6];
    const float* q_w     = (const float*)d_in[7];
    const float* q_b     = (const float*)d_in[8];
    const float* k_w     = (const float*)d_in[9];
    const float* k_b     = (const float*)d_in[10];
    const float* v_w     = (const float*)d_in[11];
    const float* v_b     = (const float*)d_in[12];
    const float* attn_g  = (const float*)d_in[13];
    const float* ppl_w   = (const float*)d_in[14];
    const float* ppl_b   = (const float*)d_in[15];
    const float* ppl_bng = (const float*)d_in[16];
    const float* ppl_bnb = (const float*)d_in[17];
    const float* ppl_bnm = (const float*)d_in[18];
    const float* ppl_bnv = (const float*)d_in[19];
    const float* proj_w  = (const float*)d_in[20];
    const float* proj_b  = (const float*)d_in[21];
    const float* pbn_g   = (const float*)d_in[22];
    const float* pbn_b   = (const float*)d_in[23];
    const float* pbn_m   = (const float*)d_in[24];
    const float* pbn_v   = (const float*)d_in[25];
    float* out = (float*)d_out;

    const int CONV_SMEM = 26240 * 4;   // 104,960 B
    const int ATTN_SMEM = 14336 * 4;   // 57,344 B
    const int PROJ_SMEM = 24096 * 4;   // 96,384 B
    cudaFuncSetAttribute(k_conv, cudaFuncAttributeMaxDynamicSharedMemorySize, CONV_SMEM);
    cudaFuncSetAttribute(k_attn, cudaFuncAttributeMaxDynamicSharedMemorySize, ATTN_SMEM);
    cudaFuncSetAttribute(k_proj, cudaFuncAttributeMaxDynamicSharedMemorySize, PROJ_SMEM);

    k_conv<<<dim3(32, 8), 256, CONV_SMEM>>>(x, conv_w, conv_b, bn_g, bn_b, bn_m, bn_v,
                                            q_w, q_b, k_w, k_b, v_w, v_b);
    k_attn<<<dim3(32, 4, 2), 256, ATTN_SMEM>>>(attn_g);
    k_pool<<<dim3(408, 2), 256>>>(ppl_w, ppl_b, ppl_bng, ppl_bnb, ppl_bnm, ppl_bnv);
    k_proj<<<128, 256, PROJ_SMEM>>>(proj_w, proj_b, pbn_g, pbn_b, pbn_m, pbn_v,
                                    ppl_w, ppl_b, ppl_bng, ppl_bnb, ppl_bnm, ppl_bnv, out);
}